// round 5
// baseline (speedup 1.0000x reference)
#include <cuda_runtime.h>
#include <math.h>

#define MAXN 100000
#define CAP  128
#define LN_EPS 1e-5

typedef unsigned long long u64;

// ---------------- scratch (static device globals; no allocation) ----------------
__device__ float  g_agg[(size_t)MAXN * 128];
__device__ float  g_h1 [(size_t)MAXN * 128];
__device__ float  g_tmp[(size_t)MAXN * 128];
__device__ int    g_cnt[MAXN];
__device__ double g_red[8];
__device__ int    g_csr[(size_t)MAXN * CAP];

// ---------------- f32x2 packed helpers ----------------
__device__ __forceinline__ u64 pack2(float x) {
    u64 r; asm("mov.b64 %0, {%1, %1};" : "=l"(r) : "f"(x)); return r;
}
__device__ __forceinline__ void fma2(u64& d, u64 a, u64 b) {
    asm("fma.rn.f32x2 %0, %1, %2, %3;" : "=l"(d) : "l"(a), "l"(b), "l"(d));
}
__device__ __forceinline__ float2 unpk(u64 v) {
    float2 f; asm("mov.b64 {%0, %1}, %2;" : "=f"(f.x), "=f"(f.y) : "l"(v)); return f;
}

// ---------------- setup kernels ----------------
__global__ void zero_all_kernel(int* __restrict__ cnt, double* __restrict__ red, int N) {
    int i = blockIdx.x * blockDim.x + threadIdx.x;
    if (i < N) cnt[i] = 0;
    if (i < 8) red[i] = 0.0;
}

// one pass: histogram + padded-CSR fill (slot = old count)
__global__ void fill_kernel(const int* __restrict__ src, const int* __restrict__ dst,
                            int E, int* __restrict__ cnt, int* __restrict__ csr) {
    int e = blockIdx.x * blockDim.x + threadIdx.x;
    if (e >= E) return;
    int d = dst[e];
    int slot = atomicAdd(&cnt[d], 1);
    if (slot < CAP) csr[(size_t)d * CAP + slot] = src[e];
}

// ---------------- CSR mean-aggregation (gather, no atomics) ----------------
// warp per node, lane covers one float4 of the 128-wide row; 8-deep MLP
__global__ void aggregate128_kernel(const float* __restrict__ feat,
                                    const int* __restrict__ csr,
                                    const int* __restrict__ cnt,
                                    float* __restrict__ mean, int N) {
    int warp = (blockIdx.x * blockDim.x + threadIdx.x) >> 5;
    int lane = threadIdx.x & 31;
    if (warp >= N) return;
    int deg = cnt[warp];
    int n = deg < CAP ? deg : CAP;
    const int* row = csr + (size_t)warp * CAP;

    float4 a[8];
    #pragma unroll
    for (int j = 0; j < 8; j++) a[j] = make_float4(0.f, 0.f, 0.f, 0.f);

    int e = 0;
    for (; e + 8 <= n; e += 8) {
        int s[8];
        #pragma unroll
        for (int j = 0; j < 8; j++) s[j] = __ldg(&row[e + j]);
        #pragma unroll
        for (int j = 0; j < 8; j++) {
            float4 v = *(const float4*)(feat + (size_t)s[j] * 128 + lane * 4);
            a[j].x += v.x; a[j].y += v.y; a[j].z += v.z; a[j].w += v.w;
        }
    }
    for (; e < n; e++) {
        int s = __ldg(&row[e]);
        float4 v = *(const float4*)(feat + (size_t)s * 128 + lane * 4);
        a[0].x += v.x; a[0].y += v.y; a[0].z += v.z; a[0].w += v.w;
    }
    #pragma unroll
    for (int j = 1; j < 8; j++) {
        a[0].x += a[j].x; a[0].y += a[j].y; a[0].z += a[j].z; a[0].w += a[j].w;
    }
    float s = 1.0f / (float)(deg > 1 ? deg : 1);
    a[0].x *= s; a[0].y *= s; a[0].z *= s; a[0].w *= s;
    *(float4*)(mean + (size_t)warp * 128 + lane * 4) = a[0];
}

// D=50 variant: lanes 0..24 each cover a float2; 8-deep MLP
__global__ void aggregate50_kernel(const float* __restrict__ feat,
                                   const int* __restrict__ csr,
                                   const int* __restrict__ cnt,
                                   float* __restrict__ mean, int N) {
    int warp = (blockIdx.x * blockDim.x + threadIdx.x) >> 5;
    int lane = threadIdx.x & 31;
    if (warp >= N || lane >= 25) return;
    int deg = cnt[warp];
    int n = deg < CAP ? deg : CAP;
    const int* row = csr + (size_t)warp * CAP;

    float2 a[8];
    #pragma unroll
    for (int j = 0; j < 8; j++) a[j] = make_float2(0.f, 0.f);

    int e = 0;
    for (; e + 8 <= n; e += 8) {
        int s[8];
        #pragma unroll
        for (int j = 0; j < 8; j++) s[j] = __ldg(&row[e + j]);
        #pragma unroll
        for (int j = 0; j < 8; j++) {
            float2 v = *(const float2*)(feat + (size_t)s[j] * 50 + lane * 2);
            a[j].x += v.x; a[j].y += v.y;
        }
    }
    for (; e < n; e++) {
        int s = __ldg(&row[e]);
        float2 v = *(const float2*)(feat + (size_t)s * 50 + lane * 2);
        a[0].x += v.x; a[0].y += v.y;
    }
    #pragma unroll
    for (int j = 1; j < 8; j++) { a[0].x += a[j].x; a[0].y += a[j].y; }
    float s = 1.0f / (float)(deg > 1 ? deg : 1);
    a[0].x *= s; a[0].y *= s;
    *(float2*)(mean + (size_t)warp * 50 + lane * 2) = a[0];
}

// ---------------- 128x128-tile GEMM, packed f32x2 FMA, pipelined staging ----------------
template<int Kdim>
__device__ __forceinline__ void stage_load(const float* __restrict__ A,
                                           const float* __restrict__ W,
                                           int k0, int tid, int blockRow, int N,
                                           float (&ar)[8], float4& b0, float4& b1) {
    #pragma unroll
    for (int t = 0; t < 8; t++) {
        int lin = tid + t * 256;
        int m = lin >> 4, k = lin & 15;
        int row = blockRow + m, kk = k0 + k;
        float v = 0.0f;
        if (row < N && kk < Kdim) v = __ldg(&A[(size_t)row * Kdim + kk]);
        ar[t] = v;
    }
    {
        int kk = tid >> 5, c4 = tid & 31;
        int k = k0 + kk;
        b0 = make_float4(0.f, 0.f, 0.f, 0.f);
        if (k < Kdim) b0 = *(const float4*)(W + (size_t)k * 128 + c4 * 4);
    }
    {
        int lin = tid + 256;
        int kk = lin >> 5, c4 = lin & 31;
        int k = k0 + kk;
        b1 = make_float4(0.f, 0.f, 0.f, 0.f);
        if (k < Kdim) b1 = *(const float4*)(W + (size_t)k * 128 + c4 * 4);
    }
}

__device__ __forceinline__ void stage_store(int tid, const float (&ar)[8],
                                            float4 b0, float4 b1,
                                            float (*sA)[17], float (*sB)[128]) {
    #pragma unroll
    for (int t = 0; t < 8; t++) {
        int lin = tid + t * 256;
        sA[lin >> 4][lin & 15] = ar[t];
    }
    *(float4*)&sB[tid >> 5][(tid & 31) * 4] = b0;
    int lin = tid + 256;
    *(float4*)&sB[lin >> 5][(lin & 31) * 4] = b1;
}

template<int Kdim>
__device__ __forceinline__ void gphase(const float* __restrict__ A,
                                       const float* __restrict__ W,
                                       u64 (&acc)[8][4],
                                       float (*sA)[17], float (*sB)[128],
                                       int tid, int tx, int ty, int blockRow, int N) {
    float ar[8]; float4 b0, b1;
    stage_load<Kdim>(A, W, 0, tid, blockRow, N, ar, b0, b1);
    for (int k0 = 0; k0 < Kdim; k0 += 16) {
        stage_store(tid, ar, b0, b1, sA, sB);
        __syncthreads();
        // prefetch next tile while computing this one (zeros past the end; regs only)
        stage_load<Kdim>(A, W, k0 + 16, tid, blockRow, N, ar, b0, b1);
        #pragma unroll
        for (int kk = 0; kk < 16; kk++) {
            ulonglong2 tb0 = *(const ulonglong2*)&sB[kk][tx * 4];
            ulonglong2 tb1 = *(const ulonglong2*)&sB[kk][tx * 4 + 64];
            #pragma unroll
            for (int i = 0; i < 8; i++) {
                u64 a2 = pack2(sA[ty * 8 + i][kk]);
                fma2(acc[i][0], a2, tb0.x);
                fma2(acc[i][1], a2, tb0.y);
                fma2(acc[i][2], a2, tb1.x);
                fma2(acc[i][3], a2, tb1.y);
            }
        }
        __syncthreads();
    }
}

// out[N,128] = (optional) A1 @ W1 + A2 @ W2  [+ epilogue]
// EPI 0: + bias, store raw, accumulate (sum, sumsq) into redOut[0..1]
// EPI 1: v = prelu(ln(rawbuf)); out2 = v; out = v + acc        (skip-1 fused)
// EPI 2: v = prelu(ln(rawbuf)); out  = v + addend + acc        (skip-2 fused)
template<int KA, int KB, int EPI>
__global__ __launch_bounds__(256, 2)
void gemm_sage(const float* __restrict__ A1, const float* __restrict__ A2,
               const float* __restrict__ W1, const float* __restrict__ W2,
               const float* __restrict__ bias,
               float* __restrict__ out, float* __restrict__ out2,
               const float* __restrict__ rawbuf, const float* __restrict__ addend,
               const float* __restrict__ lnw, const float* __restrict__ lnb,
               const float* __restrict__ alpha,
               const double* __restrict__ redIn, double* __restrict__ redOut,
               int N) {
    __shared__ __align__(16) float sA[128][17];
    __shared__ __align__(16) float sB[16][128];
    __shared__ double sRed[8][2];

    int tid = threadIdx.x;
    int tx = tid & 15;   // column group: cols [tx*4, tx*4+4) and [tx*4+64, tx*4+68)
    int ty = tid >> 4;   // row group of 8
    int blockRow = blockIdx.x * 128;

    u64 acc[8][4];
    u64 z = pack2(0.0f);
    #pragma unroll
    for (int i = 0; i < 8; i++)
        #pragma unroll
        for (int j = 0; j < 4; j++) acc[i][j] = z;

    if constexpr (KA > 0)
        gphase<KA>(A1, W1, acc, sA, sB, tid, tx, ty, blockRow, N);
    gphase<KB>(A2, W2, acc, sA, sB, tid, tx, ty, blockRow, N);

    int cb0 = tx * 4;
    int cb1 = tx * 4 + 64;
    if constexpr (EPI == 0) {
        float bs[8];
        #pragma unroll
        for (int j = 0; j < 4; j++) { bs[j] = bias[cb0 + j]; bs[4 + j] = bias[cb1 + j]; }
        double ls = 0.0, lq = 0.0;
        #pragma unroll
        for (int i = 0; i < 8; i++) {
            int row = blockRow + ty * 8 + i;
            if (row < N) {
                float c[8];
                #pragma unroll
                for (int p = 0; p < 4; p++) {
                    float2 f = unpk(acc[i][p]);
                    c[2 * p] = f.x; c[2 * p + 1] = f.y;
                }
                #pragma unroll
                for (int j = 0; j < 8; j++) c[j] += bs[j];
                size_t off0 = (size_t)row * 128 + cb0;
                size_t off1 = (size_t)row * 128 + cb1;
                *(float4*)&out[off0] = make_float4(c[0], c[1], c[2], c[3]);
                *(float4*)&out[off1] = make_float4(c[4], c[5], c[6], c[7]);
                #pragma unroll
                for (int j = 0; j < 8; j++) {
                    ls += (double)c[j];
                    lq += (double)c[j] * (double)c[j];
                }
            }
        }
        #pragma unroll
        for (int off = 16; off > 0; off >>= 1) {
            ls += __shfl_down_sync(0xffffffffu, ls, off);
            lq += __shfl_down_sync(0xffffffffu, lq, off);
        }
        int wid = tid >> 5;
        if ((tid & 31) == 0) { sRed[wid][0] = ls; sRed[wid][1] = lq; }
        __syncthreads();
        if (tid == 0) {
            double S = 0.0, Q = 0.0;
            #pragma unroll
            for (int w = 0; w < 8; w++) { S += sRed[w][0]; Q += sRed[w][1]; }
            atomicAdd(&redOut[0], S);
            atomicAdd(&redOut[1], Q);
        }
    } else {
        double M = (double)N * 128.0;
        double mean = redIn[0] / M;
        double var = redIn[1] / M - mean * mean;
        if (var < 0.0) var = 0.0;
        float sc = (float)(1.0 / (sqrt(var) + LN_EPS));
        float mu = (float)mean;
        float a = alpha[0];
        float w[8], lb[8];
        #pragma unroll
        for (int j = 0; j < 4; j++) {
            w[j] = lnw[cb0 + j]; w[4 + j] = lnw[cb1 + j];
            lb[j] = lnb[cb0 + j]; lb[4 + j] = lnb[cb1 + j];
        }
        #pragma unroll
        for (int i = 0; i < 8; i++) {
            int row = blockRow + ty * 8 + i;
            if (row < N) {
                size_t off0 = (size_t)row * 128 + cb0;
                size_t off1 = (size_t)row * 128 + cb1;
                float4 r0 = *(const float4*)&rawbuf[off0];
                float4 r1 = *(const float4*)&rawbuf[off1];
                float rv[8] = {r0.x, r0.y, r0.z, r0.w, r1.x, r1.y, r1.z, r1.w};
                float v[8];
                #pragma unroll
                for (int j = 0; j < 8; j++) {
                    float t = (rv[j] - mu) * sc * w[j] + lb[j];
                    v[j] = t >= 0.f ? t : a * t;
                }
                float af[8];
                #pragma unroll
                for (int p = 0; p < 4; p++) {
                    float2 f = unpk(acc[i][p]);
                    af[2 * p] = f.x; af[2 * p + 1] = f.y;
                }
                if constexpr (EPI == 1) {
                    *(float4*)&out2[off0] = make_float4(v[0], v[1], v[2], v[3]);
                    *(float4*)&out2[off1] = make_float4(v[4], v[5], v[6], v[7]);
                    *(float4*)&out[off0] = make_float4(v[0] + af[0], v[1] + af[1],
                                                       v[2] + af[2], v[3] + af[3]);
                    *(float4*)&out[off1] = make_float4(v[4] + af[4], v[5] + af[5],
                                                       v[6] + af[6], v[7] + af[7]);
                } else {
                    float4 d0 = *(const float4*)&addend[off0];
                    float4 d1 = *(const float4*)&addend[off1];
                    *(float4*)&out[off0] = make_float4(v[0] + d0.x + af[0], v[1] + d0.y + af[1],
                                                       v[2] + d0.z + af[2], v[3] + d0.w + af[3]);
                    *(float4*)&out[off1] = make_float4(v[4] + d1.x + af[4], v[5] + d1.y + af[5],
                                                       v[6] + d1.z + af[6], v[7] + d1.w + af[7]);
                }
            }
        }
    }
}

// final LN + PReLU on the output buffer
__global__ void ln_prelu_kernel(float* __restrict__ buf, const double* __restrict__ red,
                                const float* __restrict__ lnw, const float* __restrict__ lnb,
                                const float* __restrict__ alpha, int N) {
    long idx = (long)blockIdx.x * blockDim.x + threadIdx.x;
    long total = (long)N * 32;
    if (idx >= total) return;
    double M = (double)N * 128.0;
    double mean = red[0] / M;
    double var = red[1] / M - mean * mean;
    if (var < 0.0) var = 0.0;
    float sc = (float)(1.0 / (sqrt(var) + LN_EPS));
    float mu = (float)mean;
    float a = alpha[0];
    int c4 = ((int)(idx & 31)) * 4;
    float4 v = ((float4*)buf)[idx];
    float w0 = lnw[c4], w1 = lnw[c4 + 1], w2 = lnw[c4 + 2], w3 = lnw[c4 + 3];
    float b0 = lnb[c4], b1 = lnb[c4 + 1], b2 = lnb[c4 + 2], b3 = lnb[c4 + 3];
    float o0 = (v.x - mu) * sc * w0 + b0; o0 = o0 >= 0.f ? o0 : a * o0;
    float o1 = (v.y - mu) * sc * w1 + b1; o1 = o1 >= 0.f ? o1 : a * o1;
    float o2 = (v.z - mu) * sc * w2 + b2; o2 = o2 >= 0.f ? o2 : a * o2;
    float o3 = (v.w - mu) * sc * w3 + b3; o3 = o3 >= 0.f ? o3 : a * o3;
    ((float4*)buf)[idx] = make_float4(o0, o1, o2, o3);
}

// ---------------- launch ----------------
extern "C" void kernel_launch(void* const* d_in, const int* in_sizes, int n_in,
                              void* d_out, int out_size) {
    const float* x    = (const float*)d_in[0];
    const int*   srcp = (const int*)d_in[1];
    const int*   dstp = (const int*)d_in[2];
    const float* Wl1  = (const float*)d_in[3];
    const float* Wr1  = (const float*)d_in[4];
    const float* b1   = (const float*)d_in[5];
    const float* Wl2  = (const float*)d_in[6];
    const float* Wr2  = (const float*)d_in[7];
    const float* b2   = (const float*)d_in[8];
    const float* Wl3  = (const float*)d_in[9];
    const float* Wr3  = (const float*)d_in[10];
    const float* b3   = (const float*)d_in[11];
    const float* Ws1  = (const float*)d_in[12];
    const float* Ws2  = (const float*)d_in[13];
    const float* lnw1 = (const float*)d_in[14];
    const float* lnb1 = (const float*)d_in[15];
    const float* lnw2 = (const float*)d_in[16];
    const float* lnb2 = (const float*)d_in[17];
    const float* lnw3 = (const float*)d_in[18];
    const float* lnb3 = (const float*)d_in[19];
    const float* a1   = (const float*)d_in[20];
    const float* a2   = (const float*)d_in[21];
    const float* a3   = (const float*)d_in[22];

    int E = in_sizes[1];
    int N = in_sizes[0] / 50;

    float *agg, *h1, *tmp;
    double* red;
    int *cnt, *csr;
    cudaGetSymbolAddress((void**)&agg, g_agg);
    cudaGetSymbolAddress((void**)&h1,  g_h1);
    cudaGetSymbolAddress((void**)&tmp, g_tmp);
    cudaGetSymbolAddress((void**)&red, g_red);
    cudaGetSymbolAddress((void**)&cnt, g_cnt);
    cudaGetSymbolAddress((void**)&csr, g_csr);

    float* out = (float*)d_out;

    int gemmGrid = (N + 127) / 128;
    int aggGrid = (N + 7) / 8;   // 8 warps (256 thr) per block

    // ---- padded-CSR build (2 kernels, no scan) ----
    zero_all_kernel<<<(N + 255) / 256, 256>>>(cnt, red, N);          // launch 0
    fill_kernel<<<(E + 255) / 256, 256>>>(srcp, dstp, E, cnt, csr);  // launch 1

    // ---- layer 1 ----
    aggregate50_kernel<<<aggGrid, 256>>>(x, csr, cnt, agg, N);       // launch 2
    gemm_sage<50, 50, 0><<<gemmGrid, 256>>>(agg, x, Wl1, Wr1, b1,    // launch 3
                                            h1, nullptr, nullptr, nullptr,
                                            nullptr, nullptr, nullptr,
                                            nullptr, red + 0, N);
    // h1 := prelu(ln(h1)); tmp := h1n + x@Ws1
    gemm_sage<0, 50, 1><<<gemmGrid, 256>>>(nullptr, x, nullptr, Ws1, nullptr,  // launch 4
                                           tmp, h1, h1, nullptr,
                                           lnw1, lnb1, a1,
                                           red + 0, nullptr, N);

    // ---- layer 2 ----
    aggregate128_kernel<<<aggGrid, 256>>>(tmp, csr, cnt, agg, N);    // launch 5 (ncu target)
    gemm_sage<128, 128, 0><<<gemmGrid, 256>>>(agg, tmp, Wl2, Wr2, b2,
                                              tmp, nullptr, nullptr, nullptr,
                                              nullptr, nullptr, nullptr,
                                              nullptr, red + 2, N);
    // tmp := prelu(ln(tmp)) + h1n + x@Ws2
    gemm_sage<0, 50, 2><<<gemmGrid, 256>>>(nullptr, x, nullptr, Ws2, nullptr,
                                           tmp, nullptr, tmp, h1,
                                           lnw2, lnb2, a2,
                                           red + 2, nullptr, N);

    // ---- layer 3 ----
    aggregate128_kernel<<<aggGrid, 256>>>(tmp, csr, cnt, agg, N);
    gemm_sage<128, 128, 0><<<gemmGrid, 256>>>(agg, tmp, Wl3, Wr3, b3,
                                              out, nullptr, nullptr, nullptr,
                                              nullptr, nullptr, nullptr,
                                              nullptr, red + 4, N);
    ln_prelu_kernel<<<(int)(((long)N * 32 + 255) / 256), 256>>>(out, red + 4,
                                                                lnw3, lnb3, a3, N);
}

// round 8
// speedup vs baseline: 1.3302x; 1.3302x over previous
#include <cuda_runtime.h>
#include <cuda_bf16.h>
#include <math.h>
#include <stdint.h>

#define MAXN 100000
#define CAP  128
#define LN_EPS 1e-5

typedef unsigned long long u64;

// ---------------- scratch (static device globals; no allocation) ----------------
__device__ float  g_agg[(size_t)MAXN * 128];
__device__ float  g_h1 [(size_t)MAXN * 128];
__device__ float  g_tmp[(size_t)MAXN * 128];
__device__ int    g_cnt[MAXN];
__device__ double g_red[8];
__device__ int    g_csr[(size_t)MAXN * CAP];
__device__ __align__(16) __nv_bfloat16 g_wimgh[8 * 16384];
__device__ __align__(16) __nv_bfloat16 g_wimgl[8 * 16384];

// ---------------- mma/ldmatrix helpers (sm_80+ ISA, valid on plain sm_103) ----
__device__ __forceinline__ uint32_t smem_to_u32(const void* p) {
    uint32_t a;
    asm("{ .reg .u64 t; cvta.to.shared.u64 t, %1; cvt.u32.u64 %0, t; }" : "=r"(a) : "l"(p));
    return a;
}
__device__ __forceinline__ void ldsm_x4(uint32_t (&r)[4], uint32_t addr) {
    asm volatile("ldmatrix.sync.aligned.m8n8.x4.shared.b16 {%0,%1,%2,%3}, [%4];"
                 : "=r"(r[0]), "=r"(r[1]), "=r"(r[2]), "=r"(r[3]) : "r"(addr));
}
__device__ __forceinline__ void ldsm_x2(uint32_t (&r)[2], uint32_t addr) {
    asm volatile("ldmatrix.sync.aligned.m8n8.x2.shared.b16 {%0,%1}, [%2];"
                 : "=r"(r[0]), "=r"(r[1]) : "r"(addr));
}
__device__ __forceinline__ void mma_bf16(float (&c)[4], const uint32_t (&a)[4],
                                         const uint32_t (&b)[2]) {
    asm volatile(
        "mma.sync.aligned.m16n8k16.row.col.f32.bf16.bf16.f32 "
        "{%0,%1,%2,%3}, {%4,%5,%6,%7}, {%8,%9}, {%0,%1,%2,%3};"
        : "+f"(c[0]), "+f"(c[1]), "+f"(c[2]), "+f"(c[3])
        : "r"(a[0]), "r"(a[1]), "r"(a[2]), "r"(a[3]), "r"(b[0]), "r"(b[1]));
}
// split two fp32 into packed bf16 hi-pair and lo-pair (low 16 bits = first elem)
__device__ __forceinline__ void split2(float v0, float v1, uint32_t& h, uint32_t& l) {
    __nv_bfloat16 h0 = __float2bfloat16(v0);
    __nv_bfloat16 h1 = __float2bfloat16(v1);
    __nv_bfloat16 l0 = __float2bfloat16(v0 - __bfloat162float(h0));
    __nv_bfloat16 l1 = __float2bfloat16(v1 - __bfloat162float(h1));
    h = (uint32_t)__bfloat16_as_ushort(h0) | ((uint32_t)__bfloat16_as_ushort(h1) << 16);
    l = (uint32_t)__bfloat16_as_ushort(l0) | ((uint32_t)__bfloat16_as_ushort(l1) << 16);
}

// ---------------- setup kernels ----------------
__global__ void zero_all_kernel(int* __restrict__ cnt, double* __restrict__ red, int N) {
    int i = blockIdx.x * blockDim.x + threadIdx.x;
    if (i < N) cnt[i] = 0;
    if (i < 8) red[i] = 0.0;
}

__global__ void fill_kernel(const int* __restrict__ src, const int* __restrict__ dst,
                            int E, int* __restrict__ cnt, int* __restrict__ csr) {
    int e = blockIdx.x * blockDim.x + threadIdx.x;
    if (e >= E) return;
    int d = dst[e];
    int slot = atomicAdd(&cnt[d], 1);
    if (slot < CAP) csr[(size_t)d * CAP + slot] = src[e];
}

// transpose + bf16-split each weight into [n=128][k=128] row-major images (zero-padded K)
__global__ void prep_weights_kernel(const float* Wl1, const float* Wr1, const float* Ws1,
                                    const float* Wl2, const float* Wr2, const float* Ws2,
                                    const float* Wl3, const float* Wr3,
                                    __nv_bfloat16* __restrict__ imgh,
                                    __nv_bfloat16* __restrict__ imgl) {
    int slot = blockIdx.x;
    const float* W; int K;
    switch (slot) {
        case 0: W = Wl1; K = 50;  break;
        case 1: W = Wr1; K = 50;  break;
        case 2: W = Ws1; K = 50;  break;
        case 3: W = Wl2; K = 128; break;
        case 4: W = Wr2; K = 128; break;
        case 5: W = Ws2; K = 50;  break;
        case 6: W = Wl3; K = 128; break;
        default: W = Wr3; K = 128; break;
    }
    for (int idx = threadIdx.x; idx < 16384; idx += blockDim.x) {
        int n = idx >> 7;
        int k = idx & 127;
        float v = (k < K) ? W[(size_t)k * 128 + n] : 0.0f;
        __nv_bfloat16 hb = __float2bfloat16(v);
        __nv_bfloat16 lb = __float2bfloat16(v - __bfloat162float(hb));
        imgh[slot * 16384 + idx] = hb;
        imgl[slot * 16384 + idx] = lb;
    }
}

// ---------------- CSR mean-aggregation ----------------
__global__ void aggregate128_kernel(const float* __restrict__ feat,
                                    const int* __restrict__ csr,
                                    const int* __restrict__ cnt,
                                    float* __restrict__ mean, int N) {
    int warp = (blockIdx.x * blockDim.x + threadIdx.x) >> 5;
    int lane = threadIdx.x & 31;
    if (warp >= N) return;
    int deg = cnt[warp];
    int n = deg < CAP ? deg : CAP;
    const int* row = csr + (size_t)warp * CAP;
    float4 a[8];
    #pragma unroll
    for (int j = 0; j < 8; j++) a[j] = make_float4(0.f, 0.f, 0.f, 0.f);
    int e = 0;
    for (; e + 8 <= n; e += 8) {
        int s[8];
        #pragma unroll
        for (int j = 0; j < 8; j++) s[j] = __ldg(&row[e + j]);
        #pragma unroll
        for (int j = 0; j < 8; j++) {
            float4 v = *(const float4*)(feat + (size_t)s[j] * 128 + lane * 4);
            a[j].x += v.x; a[j].y += v.y; a[j].z += v.z; a[j].w += v.w;
        }
    }
    for (; e < n; e++) {
        int s = __ldg(&row[e]);
        float4 v = *(const float4*)(feat + (size_t)s * 128 + lane * 4);
        a[0].x += v.x; a[0].y += v.y; a[0].z += v.z; a[0].w += v.w;
    }
    #pragma unroll
    for (int j = 1; j < 8; j++) {
        a[0].x += a[j].x; a[0].y += a[j].y; a[0].z += a[j].z; a[0].w += a[j].w;
    }
    float s = 1.0f / (float)(deg > 1 ? deg : 1);
    a[0].x *= s; a[0].y *= s; a[0].z *= s; a[0].w *= s;
    *(float4*)(mean + (size_t)warp * 128 + lane * 4) = a[0];
}

__global__ void aggregate50_kernel(const float* __restrict__ feat,
                                   const int* __restrict__ csr,
                                   const int* __restrict__ cnt,
                                   float* __restrict__ mean, int N) {
    int warp = (blockIdx.x * blockDim.x + threadIdx.x) >> 5;
    int lane = threadIdx.x & 31;
    if (warp >= N || lane >= 25) return;
    int deg = cnt[warp];
    int n = deg < CAP ? deg : CAP;
    const int* row = csr + (size_t)warp * CAP;
    float2 a[8];
    #pragma unroll
    for (int j = 0; j < 8; j++) a[j] = make_float2(0.f, 0.f);
    int e = 0;
    for (; e + 8 <= n; e += 8) {
        int s[8];
        #pragma unroll
        for (int j = 0; j < 8; j++) s[j] = __ldg(&row[e + j]);
        #pragma unroll
        for (int j = 0; j < 8; j++) {
            float2 v = *(const float2*)(feat + (size_t)s[j] * 50 + lane * 2);
            a[j].x += v.x; a[j].y += v.y;
        }
    }
    for (; e < n; e++) {
        int s = __ldg(&row[e]);
        float2 v = *(const float2*)(feat + (size_t)s * 50 + lane * 2);
        a[0].x += v.x; a[0].y += v.y;
    }
    #pragma unroll
    for (int j = 1; j < 8; j++) { a[0].x += a[j].x; a[0].y += a[j].y; }
    float s = 1.0f / (float)(deg > 1 ? deg : 1);
    a[0].x *= s; a[0].y *= s;
    *(float2*)(mean + (size_t)warp * 50 + lane * 2) = a[0];
}

// ---------------- mma.sync GEMM with fused epilogues ----------------
// smem: padded tiles [128 rows][32 cols bf16], row stride 80 B (conflict-free ldmatrix)
#define SOFF_AH 0
#define SOFF_AL 10240
#define SOFF_BH 20480
#define SOFF_BL 30720
#define SOFF_RED 40960
#define SM_BYTES (40960 + 256)

template<int KACT>
__device__ __forceinline__ void mma_phase(const float* __restrict__ A,
                                          const __nv_bfloat16* __restrict__ imgh,
                                          const __nv_bfloat16* __restrict__ imgl,
                                          unsigned char* sm, uint32_t sb,
                                          float (&acc)[2][4][4],
                                          int tid, int lane, int wm, int wn,
                                          int blockRow, int N) {
    const int row = tid >> 2;         // 0..127
    const int cg  = tid & 3;          // 8-col group
    const int grow = blockRow + row;
    constexpr int CHUNKS = (KACT <= 50) ? 2 : 4;
    for (int c = 0; c < CHUNKS; c++) {
        // ---- stage A (fp32 -> bf16 hi/lo) ----
        float v[8];
        if (KACT == 128) {
            if (grow < N) {
                const float* p = A + (size_t)grow * 128 + c * 32 + cg * 8;
                float4 t0 = *(const float4*)p;
                float4 t1 = *(const float4*)(p + 4);
                v[0] = t0.x; v[1] = t0.y; v[2] = t0.z; v[3] = t0.w;
                v[4] = t1.x; v[5] = t1.y; v[6] = t1.z; v[7] = t1.w;
            } else {
                #pragma unroll
                for (int j = 0; j < 8; j++) v[j] = 0.0f;
            }
        } else {
            #pragma unroll
            for (int j = 0; j < 8; j++) {
                int k = c * 32 + cg * 8 + j;
                v[j] = (grow < N && k < KACT) ? __ldg(&A[(size_t)grow * KACT + k]) : 0.0f;
            }
        }
        uint32_t h[4], l[4];
        #pragma unroll
        for (int p = 0; p < 4; p++) split2(v[2 * p], v[2 * p + 1], h[p], l[p]);
        *(uint4*)(sm + SOFF_AH + row * 80 + cg * 16) = make_uint4(h[0], h[1], h[2], h[3]);
        *(uint4*)(sm + SOFF_AL + row * 80 + cg * 16) = make_uint4(l[0], l[1], l[2], l[3]);
        // ---- stage B (straight copies of prepped bf16 images) ----
        {
            size_t so = ((size_t)row * 128 + c * 32 + cg * 8) * 2;  // byte offset
            uint4 bh4 = *(const uint4*)((const unsigned char*)imgh + so);
            uint4 bl4 = *(const uint4*)((const unsigned char*)imgl + so);
            *(uint4*)(sm + SOFF_BH + row * 80 + cg * 16) = bh4;
            *(uint4*)(sm + SOFF_BL + row * 80 + cg * 16) = bl4;
        }
        __syncthreads();
        // ---- compute: two k16 steps ----
        #pragma unroll
        for (int ks = 0; ks < 32; ks += 16) {
            uint32_t bh[4][2], bl[4][2];
            #pragma unroll
            for (int ni = 0; ni < 4; ni++) {
                int nrow = wn * 32 + ni * 8 + (lane & 7);
                int koff = ks + ((lane >> 3) & 1) * 8;
                ldsm_x2(bh[ni], sb + SOFF_BH + nrow * 80 + koff * 2);
                ldsm_x2(bl[ni], sb + SOFF_BL + nrow * 80 + koff * 2);
            }
            #pragma unroll
            for (int mi = 0; mi < 2; mi++) {
                int arow = wm * 32 + mi * 16 + (lane & 15);
                int koff = ks + (lane >> 4) * 8;
                uint32_t ah[4], al[4];
                ldsm_x4(ah, sb + SOFF_AH + arow * 80 + koff * 2);
                ldsm_x4(al, sb + SOFF_AL + arow * 80 + koff * 2);
                #pragma unroll
                for (int ni = 0; ni < 4; ni++) {
                    mma_bf16(acc[mi][ni], ah, bh[ni]);
                    mma_bf16(acc[mi][ni], ah, bl[ni]);
                    mma_bf16(acc[mi][ni], al, bh[ni]);
                }
            }
        }
        __syncthreads();
    }
}

// EPI 0: + bias, store raw to out, accumulate (sum,sumsq) into redOut
// EPI 1: v = prelu(ln(rawbuf)); out2 = v; out = v + acc
// EPI 2: v = prelu(ln(rawbuf)); out  = v + addend + acc
template<int KACT1, int KACT2, int EPI>
__global__ __launch_bounds__(512, 1)
void gemm_mma(const float* __restrict__ A1, const float* __restrict__ A2,
              const __nv_bfloat16* __restrict__ img1h, const __nv_bfloat16* __restrict__ img1l,
              const __nv_bfloat16* __restrict__ img2h, const __nv_bfloat16* __restrict__ img2l,
              const float* __restrict__ bias,
              float* __restrict__ out, float* __restrict__ out2,
              const float* __restrict__ rawbuf, const float* __restrict__ addend,
              const float* __restrict__ lnw, const float* __restrict__ lnb,
              const float* __restrict__ alpha,
              const double* __restrict__ redIn, double* __restrict__ redOut,
              int N) {
    __shared__ __align__(16) unsigned char sm[SM_BYTES];
    uint32_t sb = smem_to_u32(sm);
    int tid = threadIdx.x;
    int lane = tid & 31;
    int warp = tid >> 5;        // 0..15
    int wm = warp >> 2;         // 0..3 -> rows wm*32
    int wn = warp & 3;          // 0..3 -> cols wn*32
    int blockRow = blockIdx.x * 128;

    float acc[2][4][4];
    #pragma unroll
    for (int i = 0; i < 2; i++)
        #pragma unroll
        for (int j = 0; j < 4; j++)
            #pragma unroll
            for (int r = 0; r < 4; r++) acc[i][j][r] = 0.0f;

    if constexpr (KACT1 > 0)
        mma_phase<KACT1>(A1, img1h, img1l, sm, sb, acc, tid, lane, wm, wn, blockRow, N);
    mma_phase<KACT2>(A2, img2h, img2l, sm, sb, acc, tid, lane, wm, wn, blockRow, N);

    // ---- epilogue ----
    double ls = 0.0, lq = 0.0;
    float mu = 0.f, scale = 0.f, aslope = 0.f;
    if constexpr (EPI != 0) {
        double M = (double)N * 128.0;
        double mean = redIn[0] / M;
        double var = redIn[1] / M - mean * mean;
        if (var < 0.0) var = 0.0;
        scale = (float)(1.0 / (sqrt(var) + LN_EPS));
        mu = (float)mean;
        aslope = alpha[0];
    }
    #pragma unroll
    for (int mi = 0; mi < 2; mi++) {
        int rbase = blockRow + wm * 32 + mi * 16 + (lane >> 2);
        #pragma unroll
        for (int ni = 0; ni < 4; ni++) {
            int col = wn * 32 + ni * 8 + (lane & 3) * 2;
            #pragma unroll
            for (int half = 0; half < 2; half++) {
                int r = rbase + half * 8;
                if (r >= N) continue;
                float d0 = acc[mi][ni][half * 2];
                float d1 = acc[mi][ni][half * 2 + 1];
                size_t off = (size_t)r * 128 + col;
                if constexpr (EPI == 0) {
                    float o0 = d0 + bias[col];
                    float o1 = d1 + bias[col + 1];
                    *(float2*)&out[off] = make_float2(o0, o1);
                    ls += (double)o0 + (double)o1;
                    lq += (double)o0 * o0 + (double)o1 * o1;
                } else {
                    float2 rv = *(const float2*)&rawbuf[off];
                    float v0 = (rv.x - mu) * scale * lnw[col] + lnb[col];
                    float v1 = (rv.y - mu) * scale * lnw[col + 1] + lnb[col + 1];
                    v0 = v0 >= 0.f ? v0 : aslope * v0;
                    v1 = v1 >= 0.f ? v1 : aslope * v1;
                    if constexpr (EPI == 1) {
                        *(float2*)&out2[off] = make_float2(v0, v1);
                        *(float2*)&out[off] = make_float2(v0 + d0, v1 + d1);
                    } else {
                        float2 ad = *(const float2*)&addend[off];
                        *(float2*)&out[off] = make_float2(v0 + ad.x + d0, v1 + ad.y + d1);
                    }
                }
            }
        }
    }

    if constexpr (EPI == 0) {
        #pragma unroll
        for (int off = 16; off > 0; off >>= 1) {
            ls += __shfl_down_sync(0xffffffffu, ls, off);
            lq += __shfl_down_sync(0xffffffffu, lq, off);
        }
        double* sRed = (double*)(sm + SOFF_RED);
        if (lane == 0) { sRed[warp * 2] = ls; sRed[warp * 2 + 1] = lq; }
        __syncthreads();
        if (tid == 0) {
            double S = 0.0, Q = 0.0;
            #pragma unroll
            for (int w = 0; w < 16; w++) { S += sRed[w * 2]; Q += sRed[w * 2 + 1]; }
            atomicAdd(&redOut[0], S);
            atomicAdd(&redOut[1], Q);
        }
    }
}

// final LN + PReLU on the output buffer
__global__ void ln_prelu_kernel(float* __restrict__ buf, const double* __restrict__ red,
                                const float* __restrict__ lnw, const float* __restrict__ lnb,
                                const float* __restrict__ alpha, int N) {
    long idx = (long)blockIdx.x * blockDim.x + threadIdx.x;
    long total = (long)N * 32;
    if (idx >= total) return;
    double M = (double)N * 128.0;
    double mean = red[0] / M;
    double var = red[1] / M - mean * mean;
    if (var < 0.0) var = 0.0;
    float sc = (float)(1.0 / (sqrt(var) + LN_EPS));
    float mu = (float)mean;
    float a = alpha[0];
    int c4 = ((int)(idx & 31)) * 4;
    float4 v = ((float4*)buf)[idx];
    float w0 = lnw[c4], w1 = lnw[c4 + 1], w2 = lnw[c4 + 2], w3 = lnw[c4 + 3];
    float b0 = lnb[c4], b1 = lnb[c4 + 1], b2 = lnb[c4 + 2], b3 = lnb[c4 + 3];
    float o0 = (v.x - mu) * sc * w0 + b0; o0 = o0 >= 0.f ? o0 : a * o0;
    float o1 = (v.y - mu) * sc * w1 + b1; o1 = o1 >= 0.f ? o1 : a * o1;
    float o2 = (v.z - mu) * sc * w2 + b2; o2 = o2 >= 0.f ? o2 : a * o2;
    float o3 = (v.w - mu) * sc * w3 + b3; o3 = o3 >= 0.f ? o3 : a * o3;
    ((float4*)buf)[idx] = make_float4(o0, o1, o2, o3);
}

// ---------------- launch ----------------
extern "C" void kernel_launch(void* const* d_in, const int* in_sizes, int n_in,
                              void* d_out, int out_size) {
    const float* x    = (const float*)d_in[0];
    const int*   srcp = (const int*)d_in[1];
    const int*   dstp = (const int*)d_in[2];
    const float* Wl1  = (const float*)d_in[3];
    const float* Wr1  = (const float*)d_in[4];
    const float* b1   = (const float*)d_in[5];
    const float* Wl2  = (const float*)d_in[6];
    const float* Wr2  = (const float*)d_in[7];
    const float* b2   = (const float*)d_in[8];
    const float* Wl3  = (const float*)d_in[9];
    const float* Wr3  = (const float*)d_in[10];
    const float* b3   = (const float*)d_in[11];
    const float* Ws1  = (const float*)d_in[12];
    const float* Ws2  = (const float*)d_in[13];
    const float* lnw1 = (const float*)d_in[14];
    const float* lnb1 = (const float*)d_in[15];
    const float* lnw2 = (const float*)d_in[16];
    const float* lnb2 = (const float*)d_in[17];
    const float* lnw3 = (const float*)d_in[18];
    const float* lnb3 = (const float*)d_in[19];
    const float* a1   = (const float*)d_in[20];
    const float* a2   = (const float*)d_in[21];
    const float* a3   = (const float*)d_in[22];

    int E = in_sizes[1];
    int N = in_sizes[0] / 50;

    float *agg, *h1, *tmp;
    double* red;
    int *cnt, *csr;
    __nv_bfloat16 *imgh, *imgl;
    cudaGetSymbolAddress((void**)&agg,  g_agg);
    cudaGetSymbolAddress((void**)&h1,   g_h1);
    cudaGetSymbolAddress((void**)&tmp,  g_tmp);
    cudaGetSymbolAddress((void**)&red,  g_red);
    cudaGetSymbolAddress((void**)&cnt,  g_cnt);
    cudaGetSymbolAddress((void**)&csr,  g_csr);
    cudaGetSymbolAddress((void**)&imgh, g_wimgh);
    cudaGetSymbolAddress((void**)&imgl, g_wimgl);

    float* out = (float*)d_out;

    int gemmGrid = (N + 127) / 128;
    int aggGrid = (N + 7) / 8;

    // ---- setup ----
    prep_weights_kernel<<<8, 256>>>(Wl1, Wr1, Ws1, Wl2, Wr2, Ws2, Wl3, Wr3, imgh, imgl);
    zero_all_kernel<<<(N + 255) / 256, 256>>>(cnt, red, N);
    fill_kernel<<<(E + 255) / 256, 256>>>(srcp, dstp, E, cnt, csr);

    // ---- layer 1 ----
    aggregate50_kernel<<<aggGrid, 256>>>(x, csr, cnt, agg, N);
    gemm_mma<50, 50, 0><<<gemmGrid, 512>>>(
        agg, x, imgh + 0 * 16384, imgl + 0 * 16384, imgh + 1 * 16384, imgl + 1 * 16384,
        b1, h1, nullptr, nullptr, nullptr, nullptr, nullptr, nullptr,
        nullptr, red + 0, N);
    // h1 := prelu(ln(h1)); tmp := h1n + x@Ws1
    gemm_mma<0, 50, 1><<<gemmGrid, 512>>>(
        nullptr, x, nullptr, nullptr, imgh + 2 * 16384, imgl + 2 * 16384,
        nullptr, tmp, h1, h1, nullptr, lnw1, lnb1, a1,
        red + 0, nullptr, N);

    // ---- layer 2 ----
    aggregate128_kernel<<<aggGrid, 256>>>(tmp, csr, cnt, agg, N);
    gemm_mma<128, 128, 0><<<gemmGrid, 512>>>(
        agg, tmp, imgh + 3 * 16384, imgl + 3 * 16384, imgh + 4 * 16384, imgl + 4 * 16384,
        b2, tmp, nullptr, nullptr, nullptr, nullptr, nullptr, nullptr,
        nullptr, red + 2, N);
    // tmp := prelu(ln(tmp)) + h1n + x@Ws2
    gemm_mma<0, 50, 2><<<gemmGrid, 512>>>(
        nullptr, x, nullptr, nullptr, imgh + 5 * 16384, imgl + 5 * 16384,
        nullptr, tmp, nullptr, tmp, h1, lnw2, lnb2, a2,
        red + 2, nullptr, N);

    // ---- layer 3 ----
    aggregate128_kernel<<<aggGrid, 256>>>(tmp, csr, cnt, agg, N);
    gemm_mma<128, 128, 0><<<gemmGrid, 512>>>(
        agg, tmp, imgh + 6 * 16384, imgl + 6 * 16384, imgh + 7 * 16384, imgl + 7 * 16384,
        b3, out, nullptr, nullptr, nullptr, nullptr, nullptr, nullptr,
        nullptr, red + 4, N);
    ln_prelu_kernel<<<(int)(((long)N * 32 + 255) / 256), 256>>>(out, red + 4,
                                                                lnw3, lnb3, a3, N);
}

// round 9
// speedup vs baseline: 1.3699x; 1.0299x over previous
#include <cuda_runtime.h>
#include <cuda_bf16.h>
#include <math.h>
#include <stdint.h>

#define MAXN 100000
#define CAP  128
#define LN_EPS 1e-5

typedef unsigned long long u64;

// ---------------- scratch (static device globals; no allocation) ----------------
__device__ float  g_agg[(size_t)MAXN * 128];
__device__ float  g_h1 [(size_t)MAXN * 128];
__device__ float  g_tmp[(size_t)MAXN * 128];
__device__ float  g_x64[(size_t)MAXN * 64];
__device__ int    g_cnt[MAXN];
__device__ double g_red[8];
__device__ int    g_csr[(size_t)MAXN * CAP];
__device__ __align__(16) __nv_bfloat16 g_wimgh[8 * 16384];
__device__ __align__(16) __nv_bfloat16 g_wimgl[8 * 16384];

// ---------------- mma/ldmatrix/cp.async helpers (sm_80+ ISA) ----------------
__device__ __forceinline__ uint32_t smem_to_u32(const void* p) {
    uint32_t a;
    asm("{ .reg .u64 t; cvta.to.shared.u64 t, %1; cvt.u32.u64 %0, t; }" : "=r"(a) : "l"(p));
    return a;
}
__device__ __forceinline__ void ldsm_x4(uint32_t (&r)[4], uint32_t addr) {
    asm volatile("ldmatrix.sync.aligned.m8n8.x4.shared.b16 {%0,%1,%2,%3}, [%4];"
                 : "=r"(r[0]), "=r"(r[1]), "=r"(r[2]), "=r"(r[3]) : "r"(addr));
}
__device__ __forceinline__ void ldsm_x2(uint32_t (&r)[2], uint32_t addr) {
    asm volatile("ldmatrix.sync.aligned.m8n8.x2.shared.b16 {%0,%1}, [%2];"
                 : "=r"(r[0]), "=r"(r[1]) : "r"(addr));
}
__device__ __forceinline__ void mma_bf16(float (&c)[4], const uint32_t (&a)[4],
                                         const uint32_t (&b)[2]) {
    asm volatile(
        "mma.sync.aligned.m16n8k16.row.col.f32.bf16.bf16.f32 "
        "{%0,%1,%2,%3}, {%4,%5,%6,%7}, {%8,%9}, {%0,%1,%2,%3};"
        : "+f"(c[0]), "+f"(c[1]), "+f"(c[2]), "+f"(c[3])
        : "r"(a[0]), "r"(a[1]), "r"(a[2]), "r"(a[3]), "r"(b[0]), "r"(b[1]));
}
__device__ __forceinline__ void cpa16(uint32_t dst, const void* src, uint32_t srcsize) {
    asm volatile("cp.async.cg.shared.global [%0], [%1], 16, %2;"
                 :: "r"(dst), "l"(src), "r"(srcsize));
}
__device__ __forceinline__ void cp_commit() {
    asm volatile("cp.async.commit_group;" ::: "memory");
}
template<int NW>
__device__ __forceinline__ void cp_wait() {
    asm volatile("cp.async.wait_group %0;" :: "n"(NW) : "memory");
}
__device__ __forceinline__ void split2(float v0, float v1, uint32_t& h, uint32_t& l) {
    __nv_bfloat16 h0 = __float2bfloat16(v0);
    __nv_bfloat16 h1 = __float2bfloat16(v1);
    __nv_bfloat16 l0 = __float2bfloat16(v0 - __bfloat162float(h0));
    __nv_bfloat16 l1 = __float2bfloat16(v1 - __bfloat162float(h1));
    h = (uint32_t)__bfloat16_as_ushort(h0) | ((uint32_t)__bfloat16_as_ushort(h1) << 16);
    l = (uint32_t)__bfloat16_as_ushort(l0) | ((uint32_t)__bfloat16_as_ushort(l1) << 16);
}

// ---------------- setup kernels ----------------
__global__ void zero_all_kernel(int* __restrict__ cnt, double* __restrict__ red, int N) {
    int i = blockIdx.x * blockDim.x + threadIdx.x;
    if (i < N) cnt[i] = 0;
    if (i < 8) red[i] = 0.0;
}

__global__ void fill_kernel(const int* __restrict__ src, const int* __restrict__ dst,
                            int E, int* __restrict__ cnt, int* __restrict__ csr) {
    int e = blockIdx.x * blockDim.x + threadIdx.x;
    if (e >= E) return;
    int d = dst[e];
    int slot = atomicAdd(&cnt[d], 1);
    if (slot < CAP) csr[(size_t)d * CAP + slot] = src[e];
}

// pad x [N,50] -> x64 [N,64] (zeros in cols 50..63)
__global__ void padx_kernel(const float* __restrict__ x, float* __restrict__ x64, int N) {
    long t = (long)blockIdx.x * blockDim.x + threadIdx.x;
    long total = (long)N * 64;
    if (t >= total) return;
    int row = (int)(t >> 6);
    int col = (int)(t & 63);
    x64[t] = (col < 50) ? x[(size_t)row * 50 + col] : 0.0f;
}

// transpose + bf16-split each weight into [n=128][k=128] row-major images (zero-padded K)
__global__ void prep_weights_kernel(const float* Wl1, const float* Wr1, const float* Ws1,
                                    const float* Wl2, const float* Wr2, const float* Ws2,
                                    const float* Wl3, const float* Wr3,
                                    __nv_bfloat16* __restrict__ imgh,
                                    __nv_bfloat16* __restrict__ imgl) {
    int slot = blockIdx.x;
    const float* W; int K;
    switch (slot) {
        case 0: W = Wl1; K = 50;  break;
        case 1: W = Wr1; K = 50;  break;
        case 2: W = Ws1; K = 50;  break;
        case 3: W = Wl2; K = 128; break;
        case 4: W = Wr2; K = 128; break;
        case 5: W = Ws2; K = 50;  break;
        case 6: W = Wl3; K = 128; break;
        default: W = Wr3; K = 128; break;
    }
    for (int idx = threadIdx.x; idx < 16384; idx += blockDim.x) {
        int n = idx >> 7;
        int k = idx & 127;
        float v = (k < K) ? W[(size_t)k * 128 + n] : 0.0f;
        __nv_bfloat16 hb = __float2bfloat16(v);
        __nv_bfloat16 lb = __float2bfloat16(v - __bfloat162float(hb));
        imgh[slot * 16384 + idx] = hb;
        imgl[slot * 16384 + idx] = lb;
    }
}

// ---------------- CSR mean-aggregation ----------------
__global__ void aggregate128_kernel(const float* __restrict__ feat,
                                    const int* __restrict__ csr,
                                    const int* __restrict__ cnt,
                                    float* __restrict__ mean, int N) {
    int warp = (blockIdx.x * blockDim.x + threadIdx.x) >> 5;
    int lane = threadIdx.x & 31;
    if (warp >= N) return;
    int deg = cnt[warp];
    int n = deg < CAP ? deg : CAP;
    const int* row = csr + (size_t)warp * CAP;
    float4 a[8];
    #pragma unroll
    for (int j = 0; j < 8; j++) a[j] = make_float4(0.f, 0.f, 0.f, 0.f);
    int e = 0;
    for (; e + 8 <= n; e += 8) {
        int s[8];
        #pragma unroll
        for (int j = 0; j < 8; j++) s[j] = __ldg(&row[e + j]);
        #pragma unroll
        for (int j = 0; j < 8; j++) {
            float4 v = *(const float4*)(feat + (size_t)s[j] * 128 + lane * 4);
            a[j].x += v.x; a[j].y += v.y; a[j].z += v.z; a[j].w += v.w;
        }
    }
    for (; e < n; e++) {
        int s = __ldg(&row[e]);
        float4 v = *(const float4*)(feat + (size_t)s * 128 + lane * 4);
        a[0].x += v.x; a[0].y += v.y; a[0].z += v.z; a[0].w += v.w;
    }
    #pragma unroll
    for (int j = 1; j < 8; j++) {
        a[0].x += a[j].x; a[0].y += a[j].y; a[0].z += a[j].z; a[0].w += a[j].w;
    }
    float s = 1.0f / (float)(deg > 1 ? deg : 1);
    a[0].x *= s; a[0].y *= s; a[0].z *= s; a[0].w *= s;
    *(float4*)(mean + (size_t)warp * 128 + lane * 4) = a[0];
}

// D=50 variant: gathers 50-wide rows of x, writes padded [N][64] (zeros cols 50..63)
__global__ void aggregate50_kernel(const float* __restrict__ feat,
                                   const int* __restrict__ csr,
                                   const int* __restrict__ cnt,
                                   float* __restrict__ mean, int N) {
    int warp = (blockIdx.x * blockDim.x + threadIdx.x) >> 5;
    int lane = threadIdx.x & 31;
    if (warp >= N) return;
    int deg = cnt[warp];
    float2 r = make_float2(0.f, 0.f);
    if (lane < 25) {
        int n = deg < CAP ? deg : CAP;
        const int* row = csr + (size_t)warp * CAP;
        float2 a[8];
        #pragma unroll
        for (int j = 0; j < 8; j++) a[j] = make_float2(0.f, 0.f);
        int e = 0;
        for (; e + 8 <= n; e += 8) {
            int s[8];
            #pragma unroll
            for (int j = 0; j < 8; j++) s[j] = __ldg(&row[e + j]);
            #pragma unroll
            for (int j = 0; j < 8; j++) {
                float2 v = *(const float2*)(feat + (size_t)s[j] * 50 + lane * 2);
                a[j].x += v.x; a[j].y += v.y;
            }
        }
        for (; e < n; e++) {
            int s = __ldg(&row[e]);
            float2 v = *(const float2*)(feat + (size_t)s * 50 + lane * 2);
            a[0].x += v.x; a[0].y += v.y;
        }
        #pragma unroll
        for (int j = 1; j < 8; j++) { a[0].x += a[j].x; a[0].y += a[j].y; }
        float s = 1.0f / (float)(deg > 1 ? deg : 1);
        r.x = a[0].x * s; r.y = a[0].y * s;
    }
    *(float2*)(mean + (size_t)warp * 64 + lane * 2) = r;
}

// ---------------- cp.async-pipelined mma.sync GEMM with fused epilogues ----------------
// dynamic smem layout (byte offsets)
#define ARAW0 0
#define ARAW1 18432
#define ACH   36864
#define ACL   47104
#define BH0   57344
#define BH1   67584
#define BL0   77824
#define BL1   88064
#define SREDO 98304
#define SMBYTES (98304 + 256)

template<int KPHYS>
__device__ __forceinline__ void prefetch_chunk(const float* __restrict__ A,
                                               const __nv_bfloat16* __restrict__ bh,
                                               const __nv_bfloat16* __restrict__ bl,
                                               uint32_t sb, int buf, int c,
                                               int tid, int blockRow, int N) {
    // A raw fp32 tile: 128 rows x 32 cols = 1024 16B segments (2 per thread)
    #pragma unroll
    for (int t = 0; t < 2; t++) {
        int g = tid + t * 512;
        int row = g >> 3, s = g & 7;
        int grow = blockRow + row;
        const float* src = A + (size_t)grow * KPHYS + c * 32 + s * 4;
        uint32_t dst = sb + (buf ? ARAW1 : ARAW0) + row * 144 + s * 16;
        cpa16(dst, src, grow < N ? 16u : 0u);
    }
    // B hi/lo bf16 tiles: 128 rows x 32 cols bf16 = 512 16B segs each (1 per thread)
    {
        int n = tid >> 2, s = tid & 3;
        const unsigned char* srch = (const unsigned char*)bh + ((size_t)n * 128 + c * 32) * 2 + s * 16;
        const unsigned char* srcl = (const unsigned char*)bl + ((size_t)n * 128 + c * 32) * 2 + s * 16;
        cpa16(sb + (buf ? BH1 : BH0) + n * 80 + s * 16, srch, 16u);
        cpa16(sb + (buf ? BL1 : BL0) + n * 80 + s * 16, srcl, 16u);
    }
}

template<int KPHYS>
__device__ __forceinline__ void mma_phase_cp(const float* __restrict__ A,
                                             const __nv_bfloat16* __restrict__ imgh,
                                             const __nv_bfloat16* __restrict__ imgl,
                                             unsigned char* sm, uint32_t sb,
                                             float (&acc)[2][4][4],
                                             int tid, int lane, int wm, int wn,
                                             int blockRow, int N) {
    constexpr int CH = KPHYS / 32;
    prefetch_chunk<KPHYS>(A, imgh, imgl, sb, 0, 0, tid, blockRow, N);
    cp_commit();
    for (int c = 0; c < CH; c++) {
        int buf = c & 1;
        if (c + 1 < CH) {
            prefetch_chunk<KPHYS>(A, imgh, imgl, sb, buf ^ 1, c + 1, tid, blockRow, N);
            cp_commit();
            cp_wait<1>();
        } else {
            cp_wait<0>();
        }
        __syncthreads();
        // ---- convert raw A fp32 -> padded bf16 hi/lo tiles ----
        {
            int row = tid >> 2, cg = tid & 3;
            const unsigned char* rp = sm + (buf ? ARAW1 : ARAW0) + row * 144 + cg * 32;
            float4 f0 = *(const float4*)rp;
            float4 f1 = *(const float4*)(rp + 16);
            uint32_t h[4], l[4];
            split2(f0.x, f0.y, h[0], l[0]);
            split2(f0.z, f0.w, h[1], l[1]);
            split2(f1.x, f1.y, h[2], l[2]);
            split2(f1.z, f1.w, h[3], l[3]);
            *(uint4*)(sm + ACH + row * 80 + cg * 16) = make_uint4(h[0], h[1], h[2], h[3]);
            *(uint4*)(sm + ACL + row * 80 + cg * 16) = make_uint4(l[0], l[1], l[2], l[3]);
        }
        __syncthreads();
        // ---- compute: two k16 steps ----
        uint32_t bhb = sb + (buf ? BH1 : BH0);
        uint32_t blb = sb + (buf ? BL1 : BL0);
        #pragma unroll
        for (int ks = 0; ks < 32; ks += 16) {
            uint32_t bh[4][2], bl[4][2];
            #pragma unroll
            for (int ni = 0; ni < 4; ni++) {
                int nrow = wn * 32 + ni * 8 + (lane & 7);
                int koff = ks + ((lane >> 3) & 1) * 8;
                ldsm_x2(bh[ni], bhb + nrow * 80 + koff * 2);
                ldsm_x2(bl[ni], blb + nrow * 80 + koff * 2);
            }
            #pragma unroll
            for (int mi = 0; mi < 2; mi++) {
                int arow = wm * 32 + mi * 16 + (lane & 15);
                int koff = ks + (lane >> 4) * 8;
                uint32_t ah[4], al[4];
                ldsm_x4(ah, sb + ACH + arow * 80 + koff * 2);
                ldsm_x4(al, sb + ACL + arow * 80 + koff * 2);
                #pragma unroll
                for (int ni = 0; ni < 4; ni++) {
                    mma_bf16(acc[mi][ni], ah, bh[ni]);
                    mma_bf16(acc[mi][ni], ah, bl[ni]);
                    mma_bf16(acc[mi][ni], al, bh[ni]);
                }
            }
        }
        __syncthreads();
    }
}

// EPI 0: + bias, store raw to out, accumulate (sum,sumsq) into redOut
// EPI 1: v = prelu(ln(rawbuf)); out2 = v; out = v + acc
// EPI 2: v = prelu(ln(rawbuf)); out  = v + addend + acc
template<int KP1, int KP2, int EPI>
__global__ __launch_bounds__(512, 1)
void gemm_mma(const float* __restrict__ A1, const float* __restrict__ A2,
              const __nv_bfloat16* __restrict__ img1h, const __nv_bfloat16* __restrict__ img1l,
              const __nv_bfloat16* __restrict__ img2h, const __nv_bfloat16* __restrict__ img2l,
              const float* __restrict__ bias,
              float* __restrict__ out, float* __restrict__ out2,
              const float* __restrict__ rawbuf, const float* __restrict__ addend,
              const float* __restrict__ lnw, const float* __restrict__ lnb,
              const float* __restrict__ alpha,
              const double* __restrict__ redIn, double* __restrict__ redOut,
              int N) {
    extern __shared__ __align__(16) unsigned char sm[];
    uint32_t sb = smem_to_u32(sm);
    int tid = threadIdx.x;
    int lane = tid & 31;
    int warp = tid >> 5;
    int wm = warp >> 2;
    int wn = warp & 3;
    int blockRow = blockIdx.x * 128;

    float acc[2][4][4];
    #pragma unroll
    for (int i = 0; i < 2; i++)
        #pragma unroll
        for (int j = 0; j < 4; j++)
            #pragma unroll
            for (int r = 0; r < 4; r++) acc[i][j][r] = 0.0f;

    if constexpr (KP1 > 0)
        mma_phase_cp<KP1>(A1, img1h, img1l, sm, sb, acc, tid, lane, wm, wn, blockRow, N);
    mma_phase_cp<KP2>(A2, img2h, img2l, sm, sb, acc, tid, lane, wm, wn, blockRow, N);

    // ---- epilogue ----
    double ls = 0.0, lq = 0.0;
    float mu = 0.f, scale = 0.f, aslope = 0.f;
    if constexpr (EPI != 0) {
        double M = (double)N * 128.0;
        double mean = redIn[0] / M;
        double var = redIn[1] / M - mean * mean;
        if (var < 0.0) var = 0.0;
        scale = (float)(1.0 / (sqrt(var) + LN_EPS));
        mu = (float)mean;
        aslope = alpha[0];
    }
    #pragma unroll
    for (int mi = 0; mi < 2; mi++) {
        int rbase = blockRow + wm * 32 + mi * 16 + (lane >> 2);
        #pragma unroll
        for (int ni = 0; ni < 4; ni++) {
            int col = wn * 32 + ni * 8 + (lane & 3) * 2;
            #pragma unroll
            for (int half = 0; half < 2; half++) {
                int r = rbase + half * 8;
                if (r >= N) continue;
                float d0 = acc[mi][ni][half * 2];
                float d1 = acc[mi][ni][half * 2 + 1];
                size_t off = (size_t)r * 128 + col;
                if constexpr (EPI == 0) {
                    float o0 = d0 + bias[col];
                    float o1 = d1 + bias[col + 1];
                    *(float2*)&out[off] = make_float2(o0, o1);
                    ls += (double)o0 + (double)o1;
                    lq += (double)o0 * o0 + (double)o1 * o1;
                } else {
                    float2 rv = *(const float2*)&rawbuf[off];
                    float v0 = (rv.x - mu) * scale * lnw[col] + lnb[col];
                    float v1 = (rv.y - mu) * scale * lnw[col + 1] + lnb[col + 1];
                    v0 = v0 >= 0.f ? v0 : aslope * v0;
                    v1 = v1 >= 0.f ? v1 : aslope * v1;
                    if constexpr (EPI == 1) {
                        *(float2*)&out2[off] = make_float2(v0, v1);
                        *(float2*)&out[off] = make_float2(v0 + d0, v1 + d1);
                    } else {
                        float2 ad = *(const float2*)&addend[off];
                        *(float2*)&out[off] = make_float2(v0 + ad.x + d0, v1 + ad.y + d1);
                    }
                }
            }
        }
    }

    if constexpr (EPI == 0) {
        #pragma unroll
        for (int off = 16; off > 0; off >>= 1) {
            ls += __shfl_down_sync(0xffffffffu, ls, off);
            lq += __shfl_down_sync(0xffffffffu, lq, off);
        }
        double* sRed = (double*)(sm + SREDO);
        if (lane == 0) { sRed[warp * 2] = ls; sRed[warp * 2 + 1] = lq; }
        __syncthreads();
        if (tid == 0) {
            double S = 0.0, Q = 0.0;
            #pragma unroll
            for (int w = 0; w < 16; w++) { S += sRed[w * 2]; Q += sRed[w * 2 + 1]; }
            atomicAdd(&redOut[0], S);
            atomicAdd(&redOut[1], Q);
        }
    }
}

// final LN + PReLU on the output buffer
__global__ void ln_prelu_kernel(float* __restrict__ buf, const double* __restrict__ red,
                                const float* __restrict__ lnw, const float* __restrict__ lnb,
                                const float* __restrict__ alpha, int N) {
    long idx = (long)blockIdx.x * blockDim.x + threadIdx.x;
    long total = (long)N * 32;
    if (idx >= total) return;
    double M = (double)N * 128.0;
    double mean = red[0] / M;
    double var = red[1] / M - mean * mean;
    if (var < 0.0) var = 0.0;
    float sc = (float)(1.0 / (sqrt(var) + LN_EPS));
    float mu = (float)mean;
    float a = alpha[0];
    int c4 = ((int)(idx & 31)) * 4;
    float4 v = ((float4*)buf)[idx];
    float w0 = lnw[c4], w1 = lnw[c4 + 1], w2 = lnw[c4 + 2], w3 = lnw[c4 + 3];
    float b0 = lnb[c4], b1 = lnb[c4 + 1], b2 = lnb[c4 + 2], b3 = lnb[c4 + 3];
    float o0 = (v.x - mu) * sc * w0 + b0; o0 = o0 >= 0.f ? o0 : a * o0;
    float o1 = (v.y - mu) * sc * w1 + b1; o1 = o1 >= 0.f ? o1 : a * o1;
    float o2 = (v.z - mu) * sc * w2 + b2; o2 = o2 >= 0.f ? o2 : a * o2;
    float o3 = (v.w - mu) * sc * w3 + b3; o3 = o3 >= 0.f ? o3 : a * o3;
    ((float4*)buf)[idx] = make_float4(o0, o1, o2, o3);
}

// ---------------- launch ----------------
extern "C" void kernel_launch(void* const* d_in, const int* in_sizes, int n_in,
                              void* d_out, int out_size) {
    const float* x    = (const float*)d_in[0];
    const int*   srcp = (const int*)d_in[1];
    const int*   dstp = (const int*)d_in[2];
    const float* Wl1  = (const float*)d_in[3];
    const float* Wr1  = (const float*)d_in[4];
    const float* b1   = (const float*)d_in[5];
    const float* Wl2  = (const float*)d_in[6];
    const float* Wr2  = (const float*)d_in[7];
    const float* b2   = (const float*)d_in[8];
    const float* Wl3  = (const float*)d_in[9];
    const float* Wr3  = (const float*)d_in[10];
    const float* b3   = (const float*)d_in[11];
    const float* Ws1  = (const float*)d_in[12];
    const float* Ws2  = (const float*)d_in[13];
    const float* lnw1 = (const float*)d_in[14];
    const float* lnb1 = (const float*)d_in[15];
    const float* lnw2 = (const float*)d_in[16];
    const float* lnb2 = (const float*)d_in[17];
    const float* lnw3 = (const float*)d_in[18];
    const float* lnb3 = (const float*)d_in[19];
    const float* a1   = (const float*)d_in[20];
    const float* a2   = (const float*)d_in[21];
    const float* a3   = (const float*)d_in[22];

    int E = in_sizes[1];
    int N = in_sizes[0] / 50;

    float *agg, *h1, *tmp, *x64;
    double* red;
    int *cnt, *csr;
    __nv_bfloat16 *imgh, *imgl;
    cudaGetSymbolAddress((void**)&agg,  g_agg);
    cudaGetSymbolAddress((void**)&h1,   g_h1);
    cudaGetSymbolAddress((void**)&tmp,  g_tmp);
    cudaGetSymbolAddress((void**)&x64,  g_x64);
    cudaGetSymbolAddress((void**)&red,  g_red);
    cudaGetSymbolAddress((void**)&cnt,  g_cnt);
    cudaGetSymbolAddress((void**)&csr,  g_csr);
    cudaGetSymbolAddress((void**)&imgh, g_wimgh);
    cudaGetSymbolAddress((void**)&imgl, g_wimgl);

    float* out = (float*)d_out;

    int gemmGrid = (N + 127) / 128;
    int aggGrid = (N + 7) / 8;

    cudaFuncSetAttribute(gemm_mma<64, 64, 0>,   cudaFuncAttributeMaxDynamicSharedMemorySize, SMBYTES);
    cudaFuncSetAttribute(gemm_mma<0, 64, 1>,    cudaFuncAttributeMaxDynamicSharedMemorySize, SMBYTES);
    cudaFuncSetAttribute(gemm_mma<128, 128, 0>, cudaFuncAttributeMaxDynamicSharedMemorySize, SMBYTES);
    cudaFuncSetAttribute(gemm_mma<0, 64, 2>,    cudaFuncAttributeMaxDynamicSharedMemorySize, SMBYTES);

    // ---- setup ----
    prep_weights_kernel<<<8, 256>>>(Wl1, Wr1, Ws1, Wl2, Wr2, Ws2, Wl3, Wr3, imgh, imgl);
    zero_all_kernel<<<(N + 255) / 256, 256>>>(cnt, red, N);
    fill_kernel<<<(E + 255) / 256, 256>>>(srcp, dstp, E, cnt, csr);
    padx_kernel<<<(int)(((long)N * 64 + 255) / 256), 256>>>(x, x64, N);

    // ---- layer 1 ----
    aggregate50_kernel<<<aggGrid, 256>>>(x, csr, cnt, agg, N);
    gemm_mma<64, 64, 0><<<gemmGrid, 512, SMBYTES>>>(
        agg, x64, imgh + 0 * 16384, imgl + 0 * 16384, imgh + 1 * 16384, imgl + 1 * 16384,
        b1, h1, nullptr, nullptr, nullptr, nullptr, nullptr, nullptr,
        nullptr, red + 0, N);
    // h1 := prelu(ln(h1)); tmp := h1n + x@Ws1
    gemm_mma<0, 64, 1><<<gemmGrid, 512, SMBYTES>>>(
        nullptr, x64, nullptr, nullptr, imgh + 2 * 16384, imgl + 2 * 16384,
        nullptr, tmp, h1, h1, nullptr, lnw1, lnb1, a1,
        red + 0, nullptr, N);

    // ---- layer 2 ----
    aggregate128_kernel<<<aggGrid, 256>>>(tmp, csr, cnt, agg, N);
    gemm_mma<128, 128, 0><<<gemmGrid, 512, SMBYTES>>>(
        agg, tmp, imgh + 3 * 16384, imgl + 3 * 16384, imgh + 4 * 16384, imgl + 4 * 16384,
        b2, tmp, nullptr, nullptr, nullptr, nullptr, nullptr, nullptr,
        nullptr, red + 2, N);
    // tmp := prelu(ln(tmp)) + h1n + x@Ws2
    gemm_mma<0, 64, 2><<<gemmGrid, 512, SMBYTES>>>(
        nullptr, x64, nullptr, nullptr, imgh + 5 * 16384, imgl + 5 * 16384,
        nullptr, tmp, nullptr, tmp, h1, lnw2, lnb2, a2,
        red + 2, nullptr, N);

    // ---- layer 3 ----
    aggregate128_kernel<<<aggGrid, 256>>>(tmp, csr, cnt, agg, N);
    gemm_mma<128, 128, 0><<<gemmGrid, 512, SMBYTES>>>(
        agg, tmp, imgh + 6 * 16384, imgl + 6 * 16384, imgh + 7 * 16384, imgl + 7 * 16384,
        b3, out, nullptr, nullptr, nullptr, nullptr, nullptr, nullptr,
        nullptr, red + 4, N);
    ln_prelu_kernel<<<(int)(((long)N * 32 + 255) / 256), 256>>>(out, red + 4,
                                                                lnw3, lnb3, a3, N);
}

// round 11
// speedup vs baseline: 1.3774x; 1.0054x over previous
#include <cuda_runtime.h>
#include <cuda_bf16.h>
#include <math.h>
#include <stdint.h>

#define MAXN 100000
#define CAP  128
#define LN_EPS 1e-5

typedef unsigned long long u64;

// ---------------- scratch (static device globals; no allocation) ----------------
__device__ float  g_h1 [(size_t)MAXN * 128];
__device__ float  g_tmp[(size_t)MAXN * 128];
__device__ int    g_cnt[MAXN];
__device__ double g_red[8];
__device__ int    g_csr[(size_t)MAXN * CAP];
__device__ __align__(16) __nv_bfloat16 g_wimgh[8 * 16384];
__device__ __align__(16) __nv_bfloat16 g_wimgl[8 * 16384];
__device__ __align__(16) __nv_bfloat16 g_xh[(size_t)MAXN * 64];
__device__ __align__(16) __nv_bfloat16 g_xl[(size_t)MAXN * 64];
__device__ __align__(16) __nv_bfloat16 g_aggh[(size_t)MAXN * 128];
__device__ __align__(16) __nv_bfloat16 g_aggl[(size_t)MAXN * 128];
__device__ __align__(16) __nv_bfloat16 g_tmph[(size_t)MAXN * 128];
__device__ __align__(16) __nv_bfloat16 g_tmpl[(size_t)MAXN * 128];

// ---------------- mma/ldmatrix/cp.async helpers (sm_80+ ISA) ----------------
__device__ __forceinline__ uint32_t smem_to_u32(const void* p) {
    uint32_t a;
    asm("{ .reg .u64 t; cvta.to.shared.u64 t, %1; cvt.u32.u64 %0, t; }" : "=r"(a) : "l"(p));
    return a;
}
__device__ __forceinline__ void ldsm_x4(uint32_t (&r)[4], uint32_t addr) {
    asm volatile("ldmatrix.sync.aligned.m8n8.x4.shared.b16 {%0,%1,%2,%3}, [%4];"
                 : "=r"(r[0]), "=r"(r[1]), "=r"(r[2]), "=r"(r[3]) : "r"(addr));
}
__device__ __forceinline__ void ldsm_x2(uint32_t (&r)[2], uint32_t addr) {
    asm volatile("ldmatrix.sync.aligned.m8n8.x2.shared.b16 {%0,%1}, [%2];"
                 : "=r"(r[0]), "=r"(r[1]) : "r"(addr));
}
__device__ __forceinline__ void mma_bf16(float (&c)[4], const uint32_t (&a)[4],
                                         const uint32_t (&b)[2]) {
    asm volatile(
        "mma.sync.aligned.m16n8k16.row.col.f32.bf16.bf16.f32 "
        "{%0,%1,%2,%3}, {%4,%5,%6,%7}, {%8,%9}, {%0,%1,%2,%3};"
        : "+f"(c[0]), "+f"(c[1]), "+f"(c[2]), "+f"(c[3])
        : "r"(a[0]), "r"(a[1]), "r"(a[2]), "r"(a[3]), "r"(b[0]), "r"(b[1]));
}
__device__ __forceinline__ void cpa16(uint32_t dst, const void* src, uint32_t srcsize) {
    asm volatile("cp.async.cg.shared.global [%0], [%1], 16, %2;"
                 :: "r"(dst), "l"(src), "r"(srcsize));
}
__device__ __forceinline__ void cp_commit() {
    asm volatile("cp.async.commit_group;" ::: "memory");
}
template<int NW>
__device__ __forceinline__ void cp_wait() {
    asm volatile("cp.async.wait_group %0;" :: "n"(NW) : "memory");
}
// split two fp32 into packed bf16 hi-pair and lo-pair (low 16 bits = first elem)
__device__ __forceinline__ void split2(float v0, float v1, uint32_t& h, uint32_t& l) {
    __nv_bfloat16 h0 = __float2bfloat16(v0);
    __nv_bfloat16 h1 = __float2bfloat16(v1);
    __nv_bfloat16 l0 = __float2bfloat16(v0 - __bfloat162float(h0));
    __nv_bfloat16 l1 = __float2bfloat16(v1 - __bfloat162float(h1));
    h = (uint32_t)__bfloat16_as_ushort(h0) | ((uint32_t)__bfloat16_as_ushort(h1) << 16);
    l = (uint32_t)__bfloat16_as_ushort(l0) | ((uint32_t)__bfloat16_as_ushort(l1) << 16);
}

// ---------------- merged setup kernel ----------------
__global__ void setup_kernel(const float* __restrict__ x,
                             const float* Wl1, const float* Wr1, const float* Ws1,
                             const float* Wl2, const float* Wr2, const float* Ws2,
                             const float* Wl3, const float* Wr3,
                             int* __restrict__ cnt, double* __restrict__ red,
                             uint32_t* __restrict__ xh, uint32_t* __restrict__ xl,
                             __nv_bfloat16* __restrict__ imgh,
                             __nv_bfloat16* __restrict__ imgl, int N) {
    int zeroB = (N + 255) >> 8;
    int xB = (N * 32 + 255) >> 8;
    int bid = blockIdx.x;
    int tid = threadIdx.x;
    if (bid < zeroB) {
        int i = bid * 256 + tid;
        if (i < N) cnt[i] = 0;
        if (i < 8) red[i] = 0.0;
    } else if (bid < zeroB + xB) {
        int t = (bid - zeroB) * 256 + tid;
        int row = t >> 5;
        int c2 = t & 31;
        if (row < N) {
            int col = c2 * 2;
            float v0 = (col < 50) ? x[(size_t)row * 50 + col] : 0.0f;
            float v1 = (col + 1 < 50) ? x[(size_t)row * 50 + col + 1] : 0.0f;
            uint32_t h, l;
            split2(v0, v1, h, l);
            xh[(size_t)row * 32 + c2] = h;
            xl[(size_t)row * 32 + c2] = l;
        }
    } else {
        int b2 = bid - zeroB - xB;
        int slot = b2 >> 6;
        int idx = (b2 & 63) * 256 + tid;
        const float* W; int K;
        switch (slot) {
            case 0: W = Wl1; K = 50;  break;
            case 1: W = Wr1; K = 50;  break;
            case 2: W = Ws1; K = 50;  break;
            case 3: W = Wl2; K = 128; break;
            case 4: W = Wr2; K = 128; break;
            case 5: W = Ws2; K = 50;  break;
            case 6: W = Wl3; K = 128; break;
            default: W = Wr3; K = 128; break;
        }
        int n = idx >> 7;
        int k = idx & 127;
        float v = (k < K) ? W[(size_t)k * 128 + n] : 0.0f;
        __nv_bfloat16 hb = __float2bfloat16(v);
        __nv_bfloat16 lb = __float2bfloat16(v - __bfloat162float(hb));
        imgh[slot * 16384 + idx] = hb;
        imgl[slot * 16384 + idx] = lb;
    }
}

__global__ void fill_kernel(const int* __restrict__ src, const int* __restrict__ dst,
                            int E, int* __restrict__ cnt, int* __restrict__ csr) {
    int e = blockIdx.x * blockDim.x + threadIdx.x;
    if (e >= E) return;
    int d = dst[e];
    int slot = atomicAdd(&cnt[d], 1);
    if (slot < CAP) csr[(size_t)d * CAP + slot] = src[e];
}

// ---------------- CSR mean-aggregation -> bf16 hi/lo split images ----------------
__global__ void aggregate128_kernel(const float* __restrict__ feat,
                                    const int* __restrict__ csr,
                                    const int* __restrict__ cnt,
                                    uint32_t* __restrict__ mh,
                                    uint32_t* __restrict__ ml, int N) {
    int warp = (blockIdx.x * blockDim.x + threadIdx.x) >> 5;
    int lane = threadIdx.x & 31;
    if (warp >= N) return;
    int deg = cnt[warp];
    int n = deg < CAP ? deg : CAP;
    const int* row = csr + (size_t)warp * CAP;
    float4 a[8];
    #pragma unroll
    for (int j = 0; j < 8; j++) a[j] = make_float4(0.f, 0.f, 0.f, 0.f);
    int e = 0;
    for (; e + 8 <= n; e += 8) {
        int s[8];
        #pragma unroll
        for (int j = 0; j < 8; j++) s[j] = __ldg(&row[e + j]);
        #pragma unroll
        for (int j = 0; j < 8; j++) {
            float4 v = *(const float4*)(feat + (size_t)s[j] * 128 + lane * 4);
            a[j].x += v.x; a[j].y += v.y; a[j].z += v.z; a[j].w += v.w;
        }
    }
    for (; e < n; e++) {
        int s = __ldg(&row[e]);
        float4 v = *(const float4*)(feat + (size_t)s * 128 + lane * 4);
        a[0].x += v.x; a[0].y += v.y; a[0].z += v.z; a[0].w += v.w;
    }
    #pragma unroll
    for (int j = 1; j < 8; j++) {
        a[0].x += a[j].x; a[0].y += a[j].y; a[0].z += a[j].z; a[0].w += a[j].w;
    }
    float s = 1.0f / (float)(deg > 1 ? deg : 1);
    uint32_t h0, l0, h1, l1;
    split2(a[0].x * s, a[0].y * s, h0, l0);
    split2(a[0].z * s, a[0].w * s, h1, l1);
    *(uint2*)&mh[(size_t)warp * 64 + lane * 2] = make_uint2(h0, h1);
    *(uint2*)&ml[(size_t)warp * 64 + lane * 2] = make_uint2(l0, l1);
}

// D=50 variant: writes padded [N][64] split images (zeros cols 50..63)
__global__ void aggregate50_kernel(const float* __restrict__ feat,
                                   const int* __restrict__ csr,
                                   const int* __restrict__ cnt,
                                   uint32_t* __restrict__ mh,
                                   uint32_t* __restrict__ ml, int N) {
    int warp = (blockIdx.x * blockDim.x + threadIdx.x) >> 5;
    int lane = threadIdx.x & 31;
    if (warp >= N) return;
    int deg = cnt[warp];
    float2 r = make_float2(0.f, 0.f);
    if (lane < 25) {
        int n = deg < CAP ? deg : CAP;
        const int* row = csr + (size_t)warp * CAP;
        float2 a[8];
        #pragma unroll
        for (int j = 0; j < 8; j++) a[j] = make_float2(0.f, 0.f);
        int e = 0;
        for (; e + 8 <= n; e += 8) {
            int s[8];
            #pragma unroll
            for (int j = 0; j < 8; j++) s[j] = __ldg(&row[e + j]);
            #pragma unroll
            for (int j = 0; j < 8; j++) {
                float2 v = *(const float2*)(feat + (size_t)s[j] * 50 + lane * 2);
                a[j].x += v.x; a[j].y += v.y;
            }
        }
        for (; e < n; e++) {
            int s = __ldg(&row[e]);
            float2 v = *(const float2*)(feat + (size_t)s * 50 + lane * 2);
            a[0].x += v.x; a[0].y += v.y;
        }
        #pragma unroll
        for (int j = 1; j < 8; j++) { a[0].x += a[j].x; a[0].y += a[j].y; }
        float s = 1.0f / (float)(deg > 1 ? deg : 1);
        r.x = a[0].x * s; r.y = a[0].y * s;
    }
    uint32_t h, l;
    split2(r.x, r.y, h, l);
    mh[(size_t)warp * 32 + lane] = h;
    ml[(size_t)warp * 32 + lane] = l;
}

// ---------------- cp.async-pipelined mma.sync GEMM (pre-split operands) ----------
#define TILE_B 10240
#define SM_AH(b) ((b) * TILE_B)
#define SM_AL(b) (20480 + (b) * TILE_B)
#define SM_BH(b) (40960 + (b) * TILE_B)
#define SM_BL(b) (61440 + (b) * TILE_B)
#define SREDO 81920
#define SMBYTES (81920 + 256)

// EPI 0: + bias, store raw to out, accumulate (sum,sumsq) into redOut
// EPI 1: v = prelu(ln(rawbuf)); out2 = v; out = v + acc; split(out)->outsh/outsl
// EPI 2: v = prelu(ln(rawbuf)); out  = v + addend + acc; split(out)->outsh/outsl
template<int KP1, int KP2, int EPI>
__global__ __launch_bounds__(512, 1)
void gemm_mma(const __nv_bfloat16* __restrict__ A1h, const __nv_bfloat16* __restrict__ A1l,
              const __nv_bfloat16* __restrict__ A2h, const __nv_bfloat16* __restrict__ A2l,
              const __nv_bfloat16* __restrict__ B1h, const __nv_bfloat16* __restrict__ B1l,
              const __nv_bfloat16* __restrict__ B2h, const __nv_bfloat16* __restrict__ B2l,
              const float* __restrict__ bias,
              float* __restrict__ out, float* __restrict__ out2,
              uint32_t* __restrict__ outsh, uint32_t* __restrict__ outsl,
              const float* __restrict__ rawbuf, const float* __restrict__ addend,
              const float* __restrict__ lnw, const float* __restrict__ lnb,
              const float* __restrict__ alpha,
              const double* __restrict__ redIn, double* __restrict__ redOut,
              int N) {
    extern __shared__ __align__(16) unsigned char sm[];
    uint32_t sb = smem_to_u32(sm);
    int tid = threadIdx.x;
    int lane = tid & 31;
    int warp = tid >> 5;
    int wm = warp >> 2;
    int wn = warp & 3;
    int blockRow = blockIdx.x * 128;

    constexpr int CH1 = KP1 / 32;
    constexpr int CH2 = KP2 / 32;
    constexpr int CH = CH1 + CH2;

    const int prow = tid >> 2;        // 0..127
    const int pseg = tid & 3;         // 16B segment
    const int grow = blockRow + prow;
    const uint32_t asz = (grow < N) ? 16u : 0u;

    auto prefetch = [&](int cc, int buf) {
        const __nv_bfloat16 *ah, *al, *bh, *bl;
        int kp, c;
        if (cc < CH1) { ah = A1h; al = A1l; bh = B1h; bl = B1l; kp = KP1; c = cc; }
        else          { ah = A2h; al = A2l; bh = B2h; bl = B2l; kp = KP2; c = cc - CH1; }
        size_t aoff = ((size_t)grow * kp + c * 32) * 2 + pseg * 16;
        size_t boff = ((size_t)prow * 128 + c * 32) * 2 + pseg * 16;
        uint32_t d = prow * 80 + pseg * 16;
        cpa16(sb + SM_AH(buf) + d, (const unsigned char*)ah + aoff, asz);
        cpa16(sb + SM_AL(buf) + d, (const unsigned char*)al + aoff, asz);
        cpa16(sb + SM_BH(buf) + d, (const unsigned char*)bh + boff, 16u);
        cpa16(sb + SM_BL(buf) + d, (const unsigned char*)bl + boff, 16u);
    };

    float acc[2][4][4];
    #pragma unroll
    for (int i = 0; i < 2; i++)
        #pragma unroll
        for (int j = 0; j < 4; j++)
            #pragma unroll
            for (int r = 0; r < 4; r++) acc[i][j][r] = 0.0f;

    prefetch(0, 0);
    cp_commit();
    for (int cc = 0; cc < CH; cc++) {
        int buf = cc & 1;
        if (cc + 1 < CH) {
            prefetch(cc + 1, buf ^ 1);
            cp_commit();
            cp_wait<1>();
        } else {
            cp_wait<0>();
        }
        __syncthreads();
        uint32_t ahb = sb + SM_AH(buf), alb = sb + SM_AL(buf);
        uint32_t bhb = sb + SM_BH(buf), blb = sb + SM_BL(buf);
        #pragma unroll
        for (int ks = 0; ks < 32; ks += 16) {
            uint32_t bh[4][2], bl[4][2];
            #pragma unroll
            for (int ni = 0; ni < 4; ni++) {
                int nrow = wn * 32 + ni * 8 + (lane & 7);
                int koff = ks + ((lane >> 3) & 1) * 8;
                ldsm_x2(bh[ni], bhb + nrow * 80 + koff * 2);
                ldsm_x2(bl[ni], blb + nrow * 80 + koff * 2);
            }
            #pragma unroll
            for (int mi = 0; mi < 2; mi++) {
                int arow = wm * 32 + mi * 16 + (lane & 15);
                int koff = ks + (lane >> 4) * 8;
                uint32_t ah[4], al[4];
                ldsm_x4(ah, ahb + arow * 80 + koff * 2);
                ldsm_x4(al, alb + arow * 80 + koff * 2);
                #pragma unroll
                for (int ni = 0; ni < 4; ni++) {
                    mma_bf16(acc[mi][ni], ah, bh[ni]);
                    mma_bf16(acc[mi][ni], ah, bl[ni]);
                    mma_bf16(acc[mi][ni], al, bh[ni]);
                }
            }
        }
        __syncthreads();
    }

    // ---- epilogue ----
    double ls = 0.0, lq = 0.0;
    float mu = 0.f, scale = 0.f, aslope = 0.f;
    if constexpr (EPI != 0) {
        double M = (double)N * 128.0;
        double mean = redIn[0] / M;
        double var = redIn[1] / M - mean * mean;
        if (var < 0.0) var = 0.0;
        scale = (float)(1.0 / (sqrt(var) + LN_EPS));
        mu = (float)mean;
        aslope = alpha[0];
    }
    #pragma unroll
    for (int mi = 0; mi < 2; mi++) {
        int rbase = blockRow + wm * 32 + mi * 16 + (lane >> 2);
        #pragma unroll
        for (int ni = 0; ni < 4; ni++) {
            int col = wn * 32 + ni * 8 + (lane & 3) * 2;
            #pragma unroll
            for (int half = 0; half < 2; half++) {
                int r = rbase + half * 8;
                if (r >= N) continue;
                float d0 = acc[mi][ni][half * 2];
                float d1 = acc[mi][ni][half * 2 + 1];
                size_t off = (size_t)r * 128 + col;
                if constexpr (EPI == 0) {
                    float o0 = d0 + bias[col];
                    float o1 = d1 + bias[col + 1];
                    *(float2*)&out[off] = make_float2(o0, o1);
                    ls += (double)o0 + (double)o1;
                    lq += (double)o0 * o0 + (double)o1 * o1;
                } else {
                    float2 rv = *(const float2*)&rawbuf[off];
                    float v0 = (rv.x - mu) * scale * lnw[col] + lnb[col];
                    float v1 = (rv.y - mu) * scale * lnw[col + 1] + lnb[col + 1];
                    v0 = v0 >= 0.f ? v0 : aslope * v0;
                    v1 = v1 >= 0.f ? v1 : aslope * v1;
                    float o0, o1;
                    if constexpr (EPI == 1) {
                        *(float2*)&out2[off] = make_float2(v0, v1);
                        o0 = v0 + d0; o1 = v1 + d1;
                    } else {
                        float2 ad = *(const float2*)&addend[off];
                        o0 = v0 + ad.x + d0; o1 = v1 + ad.y + d1;
                    }
                    *(float2*)&out[off] = make_float2(o0, o1);
                    uint32_t h, l;
                    split2(o0, o1, h, l);
                    outsh[(size_t)r * 64 + (col >> 1)] = h;
                    outsl[(size_t)r * 64 + (col >> 1)] = l;
                }
            }
        }
    }

    if constexpr (EPI == 0) {
        #pragma unroll
        for (int off = 16; off > 0; off >>= 1) {
            ls += __shfl_down_sync(0xffffffffu, ls, off);
            lq += __shfl_down_sync(0xffffffffu, lq, off);
        }
        double* sRed = (double*)(sm + SREDO);
        if (lane == 0) { sRed[warp * 2] = ls; sRed[warp * 2 + 1] = lq; }
        __syncthreads();
        if (tid == 0) {
            double S = 0.0, Q = 0.0;
            #pragma unroll
            for (int w = 0; w < 16; w++) { S += sRed[w * 2]; Q += sRed[w * 2 + 1]; }
            atomicAdd(&redOut[0], S);
            atomicAdd(&redOut[1], Q);
        }
    }
}

// final LN + PReLU on the output buffer
__global__ void ln_prelu_kernel(float* __restrict__ buf, const double* __restrict__ red,
                                const float* __restrict__ lnw, const float* __restrict__ lnb,
                                const float* __restrict__ alpha, int N) {
    long idx = (long)blockIdx.x * blockDim.x + threadIdx.x;
    long total = (long)N * 32;
    if (idx >= total) return;
    double M = (double)N * 128.0;
    double mean = red[0] / M;
    double var = red[1] / M - mean * mean;
    if (var < 0.0) var = 0.0;
    float sc = (float)(1.0 / (sqrt(var) + LN_EPS));
    float mu = (float)mean;
    float a = alpha[0];
    int c4 = ((int)(idx & 31)) * 4;
    float4 v = ((float4*)buf)[idx];
    float w0 = lnw[c4], w1 = lnw[c4 + 1], w2 = lnw[c4 + 2], w3 = lnw[c4 + 3];
    float b0 = lnb[c4], b1 = lnb[c4 + 1], b2 = lnb[c4 + 2], b3 = lnb[c4 + 3];
    float o0 = (v.x - mu) * sc * w0 + b0; o0 = o0 >= 0.f ? o0 : a * o0;
    float o1 = (v.y - mu) * sc * w1 + b1; o1 = o1 >= 0.f ? o1 : a * o1;
    float o2 = (v.z - mu) * sc * w2 + b2; o2 = o2 >= 0.f ? o2 : a * o2;
    float o3 = (v.w - mu) * sc * w3 + b3; o3 = o3 >= 0.f ? o3 : a * o3;
    ((float4*)buf)[idx] = make_float4(o0, o1, o2, o3);
}

// ---------------- launch ----------------
extern "C" void kernel_launch(void* const* d_in, const int* in_sizes, int n_in,
                              void* d_out, int out_size) {
    const float* x    = (const float*)d_in[0];
    const int*   srcp = (const int*)d_in[1];
    const int*   dstp = (const int*)d_in[2];
    const float* Wl1  = (const float*)d_in[3];
    const float* Wr1  = (const float*)d_in[4];
    const float* b1   = (const float*)d_in[5];
    const float* Wl2  = (const float*)d_in[6];
    const float* Wr2  = (const float*)d_in[7];
    const float* b2   = (const float*)d_in[8];
    const float* Wl3  = (const float*)d_in[9];
    const float* Wr3  = (const float*)d_in[10];
    const float* b3   = (const float*)d_in[11];
    const float* Ws1  = (const float*)d_in[12];
    const float* Ws2  = (const float*)d_in[13];
    const float* lnw1 = (const float*)d_in[14];
    const float* lnb1 = (const float*)d_in[15];
    const float* lnw2 = (const float*)d_in[16];
    const float* lnb2 = (const float*)d_in[17];
    const float* lnw3 = (const float*)d_in[18];
    const float* lnb3 = (const float*)d_in[19];
    const float* a1   = (const float*)d_in[20];
    const float* a2   = (const float*)d_in[21];
    const float* a3   = (const float*)d_in[22];

    int E = in_sizes[1];
    int N = in_sizes[0] / 50;

    float *h1, *tmp;
    double* red;
    int *cnt, *csr;
    __nv_bfloat16 *imgh, *imgl, *xh, *xl, *aggh, *aggl, *tmph, *tmpl;
    cudaGetSymbolAddress((void**)&h1,   g_h1);
    cudaGetSymbolAddress((void**)&tmp,  g_tmp);
    cudaGetSymbolAddress((void**)&red,  g_red);
    cudaGetSymbolAddress((void**)&cnt,  g_cnt);
    cudaGetSymbolAddress((void**)&csr,  g_csr);
    cudaGetSymbolAddress((void**)&imgh, g_wimgh);
    cudaGetSymbolAddress((void**)&imgl, g_wimgl);
    cudaGetSymbolAddress((void**)&xh,   g_xh);
    cudaGetSymbolAddress((void**)&xl,   g_xl);
    cudaGetSymbolAddress((void**)&aggh, g_aggh);
    cudaGetSymbolAddress((void**)&aggl, g_aggl);
    cudaGetSymbolAddress((void**)&tmph, g_tmph);
    cudaGetSymbolAddress((void**)&tmpl, g_tmpl);

    float* out = (float*)d_out;

    int gemmGrid = (N + 127) / 128;
    int aggGrid = (N + 7) / 8;
    int zeroB = (N + 255) / 256;
    int xB = (N * 32 + 255) / 256;
    int setupGrid = zeroB + xB + 512;

    cudaFuncSetAttribute(gemm_mma<64, 64, 0>,   cudaFuncAttributeMaxDynamicSharedMemorySize, SMBYTES);
    cudaFuncSetAttribute(gemm_mma<0, 64, 1>,    cudaFuncAttributeMaxDynamicSharedMemorySize, SMBYTES);
    cudaFuncSetAttribute(gemm_mma<128, 128, 0>, cudaFuncAttributeMaxDynamicSharedMemorySize, SMBYTES);
    cudaFuncSetAttribute(gemm_mma<0, 64, 2>,    cudaFuncAttributeMaxDynamicSharedMemorySize, SMBYTES);

    // launch 0: merged setup
    setup_kernel<<<setupGrid, 256>>>(x, Wl1, Wr1, Ws1, Wl2, Wr2, Ws2, Wl3, Wr3,
                                     cnt, red, (uint32_t*)xh, (uint32_t*)xl,
                                     imgh, imgl, N);
    // launch 1: CSR fill
    fill_kernel<<<(E + 255) / 256, 256>>>(srcp, dstp, E, cnt, csr);
    // launch 2: layer-1 aggregation (splits to aggh/aggl)
    aggregate50_kernel<<<aggGrid, 256>>>(x, csr, cnt, (uint32_t*)aggh, (uint32_t*)aggl, N);
    // launch 3 (ncu target): layer-1 GEMM  h1raw = mean@Wl1 + x@Wr1 + b1
    gemm_mma<64, 64, 0><<<gemmGrid, 512, SMBYTES>>>(
        aggh, aggl, xh, xl,
        imgh + 0 * 16384, imgl + 0 * 16384, imgh + 1 * 16384, imgl + 1 * 16384,
        b1, h1,
        nullptr, nullptr, nullptr, nullptr, nullptr, nullptr, nullptr, nullptr, nullptr,
        red + 0, N);
    // launch 4: h1 := prelu(ln(h1raw)); tmp := h1n + x@Ws1 (+ split images)
    gemm_mma<0, 64, 1><<<gemmGrid, 512, SMBYTES>>>(
        nullptr, nullptr, xh, xl,
        nullptr, nullptr, imgh + 2 * 16384, imgl + 2 * 16384,
        nullptr, tmp, h1, (uint32_t*)tmph, (uint32_t*)tmpl, h1, nullptr,
        lnw1, lnb1, a1, red + 0, nullptr, N);
    // layer 2
    aggregate128_kernel<<<aggGrid, 256>>>(tmp, csr, cnt, (uint32_t*)aggh, (uint32_t*)aggl, N);
    gemm_mma<128, 128, 0><<<gemmGrid, 512, SMBYTES>>>(
        aggh, aggl, tmph, tmpl,
        imgh + 3 * 16384, imgl + 3 * 16384, imgh + 4 * 16384, imgl + 4 * 16384,
        b2, tmp,
        nullptr, nullptr, nullptr, nullptr, nullptr, nullptr, nullptr, nullptr, nullptr,
        red + 2, N);
    gemm_mma<0, 64, 2><<<gemmGrid, 512, SMBYTES>>>(
        nullptr, nullptr, xh, xl,
        nullptr, nullptr, imgh + 5 * 16384, imgl + 5 * 16384,
        nullptr, tmp, nullptr, (uint32_t*)tmph, (uint32_t*)tmpl, tmp, h1,
        lnw2, lnb2, a2, red + 2, nullptr, N);
    // layer 3
    aggregate128_kernel<<<aggGrid, 256>>>(tmp, csr, cnt, (uint32_t*)aggh, (uint32_t*)aggl, N);
    gemm_mma<128, 128, 0><<<gemmGrid, 512, SMBYTES>>>(
        aggh, aggl, tmph, tmpl,
        imgh + 6 * 16384, imgl + 6 * 16384, imgh + 7 * 16384, imgl + 7 * 16384,
        b3, out,
        nullptr, nullptr, nullptr, nullptr, nullptr, nullptr, nullptr, nullptr, nullptr,
        red + 4, N);
    ln_prelu_kernel<<<(int)(((long)N * 32 + 255) / 256), 256>>>(out, red + 4,
                                                                lnw3, lnb3, a3, N);
}

// round 13
// speedup vs baseline: 1.6621x; 1.2067x over previous
#include <cuda_runtime.h>
#include <cuda_bf16.h>
#include <math.h>
#include <stdint.h>

#define MAXN 100000
#define CAP  128
#define LN_EPS 1e-5

typedef unsigned long long u64;

// ---------------- scratch (static device globals; no allocation) ----------------
__device__ float  g_h1 [(size_t)MAXN * 128];
__device__ float  g_tmp[(size_t)MAXN * 128];
__device__ int    g_cnt[MAXN];
__device__ double g_red[8];
__device__ int    g_csr[(size_t)MAXN * CAP];
__device__ __align__(16) __nv_bfloat16 g_wimgh[8 * 16384];
__device__ __align__(16) __nv_bfloat16 g_wimgl[8 * 16384];
__device__ __align__(16) __nv_bfloat16 g_xh[(size_t)MAXN * 64];
__device__ __align__(16) __nv_bfloat16 g_xl[(size_t)MAXN * 64];
__device__ __align__(16) __nv_bfloat16 g_aggh[(size_t)MAXN * 128];
__device__ __align__(16) __nv_bfloat16 g_aggl[(size_t)MAXN * 128];
__device__ __align__(16) __nv_bfloat16 g_tmph[(size_t)MAXN * 128];
__device__ __align__(16) __nv_bfloat16 g_tmpl[(size_t)MAXN * 128];

// ---------------- mma/ldmatrix/cp.async helpers (sm_80+ ISA) ----------------
__device__ __forceinline__ uint32_t smem_to_u32(const void* p) {
    uint32_t a;
    asm("{ .reg .u64 t; cvta.to.shared.u64 t, %1; cvt.u32.u64 %0, t; }" : "=r"(a) : "l"(p));
    return a;
}
__device__ __forceinline__ void ldsm_x4(uint32_t (&r)[4], uint32_t addr) {
    asm volatile("ldmatrix.sync.aligned.m8n8.x4.shared.b16 {%0,%1,%2,%3}, [%4];"
                 : "=r"(r[0]), "=r"(r[1]), "=r"(r[2]), "=r"(r[3]) : "r"(addr));
}
__device__ __forceinline__ void ldsm_x2(uint32_t (&r)[2], uint32_t addr) {
    asm volatile("ldmatrix.sync.aligned.m8n8.x2.shared.b16 {%0,%1}, [%2];"
                 : "=r"(r[0]), "=r"(r[1]) : "r"(addr));
}
__device__ __forceinline__ void mma_bf16(float (&c)[4], const uint32_t (&a)[4],
                                         const uint32_t (&b)[2]) {
    asm volatile(
        "mma.sync.aligned.m16n8k16.row.col.f32.bf16.bf16.f32 "
        "{%0,%1,%2,%3}, {%4,%5,%6,%7}, {%8,%9}, {%0,%1,%2,%3};"
        : "+f"(c[0]), "+f"(c[1]), "+f"(c[2]), "+f"(c[3])
        : "r"(a[0]), "r"(a[1]), "r"(a[2]), "r"(a[3]), "r"(b[0]), "r"(b[1]));
}
__device__ __forceinline__ void cpa16(uint32_t dst, const void* src, uint32_t srcsize) {
    asm volatile("cp.async.cg.shared.global [%0], [%1], 16, %2;"
                 :: "r"(dst), "l"(src), "r"(srcsize));
}
__device__ __forceinline__ void cp_commit() {
    asm volatile("cp.async.commit_group;" ::: "memory");
}
template<int NW>
__device__ __forceinline__ void cp_wait() {
    asm volatile("cp.async.wait_group %0;" :: "n"(NW) : "memory");
}
// split two fp32 into packed bf16 hi-pair and lo-pair (low 16 bits = first elem)
__device__ __forceinline__ void split2(float v0, float v1, uint32_t& h, uint32_t& l) {
    __nv_bfloat16 h0 = __float2bfloat16(v0);
    __nv_bfloat16 h1 = __float2bfloat16(v1);
    __nv_bfloat16 l0 = __float2bfloat16(v0 - __bfloat162float(h0));
    __nv_bfloat16 l1 = __float2bfloat16(v1 - __bfloat162float(h1));
    h = (uint32_t)__bfloat16_as_ushort(h0) | ((uint32_t)__bfloat16_as_ushort(h1) << 16);
    l = (uint32_t)__bfloat16_as_ushort(l0) | ((uint32_t)__bfloat16_as_ushort(l1) << 16);
}

// ---------------- merged setup kernel ----------------
__global__ void setup_kernel(const float* __restrict__ x,
                             const float* Wl1, const float* Wr1, const float* Ws1,
                             const float* Wl2, const float* Wr2, const float* Ws2,
                             const float* Wl3, const float* Wr3,
                             int* __restrict__ cnt, double* __restrict__ red,
                             uint32_t* __restrict__ xh, uint32_t* __restrict__ xl,
                             __nv_bfloat16* __restrict__ imgh,
                             __nv_bfloat16* __restrict__ imgl, int N) {
    int zeroB = (N + 255) >> 8;
    int xB = (N * 32 + 255) >> 8;
    int bid = blockIdx.x;
    int tid = threadIdx.x;
    if (bid < zeroB) {
        int i = bid * 256 + tid;
        if (i < N) cnt[i] = 0;
        if (i < 8) red[i] = 0.0;
    } else if (bid < zeroB + xB) {
        int t = (bid - zeroB) * 256 + tid;
        int row = t >> 5;
        int c2 = t & 31;
        if (row < N) {
            int col = c2 * 2;
            float v0 = (col < 50) ? x[(size_t)row * 50 + col] : 0.0f;
            float v1 = (col + 1 < 50) ? x[(size_t)row * 50 + col + 1] : 0.0f;
            uint32_t h, l;
            split2(v0, v1, h, l);
            xh[(size_t)row * 32 + c2] = h;
            xl[(size_t)row * 32 + c2] = l;
        }
    } else {
        int b2 = bid - zeroB - xB;
        int slot = b2 >> 6;
        int idx = (b2 & 63) * 256 + tid;
        const float* W; int K;
        switch (slot) {
            case 0: W = Wl1; K = 50;  break;
            case 1: W = Wr1; K = 50;  break;
            case 2: W = Ws1; K = 50;  break;
            case 3: W = Wl2; K = 128; break;
            case 4: W = Wr2; K = 128; break;
            case 5: W = Ws2; K = 50;  break;
            case 6: W = Wl3; K = 128; break;
            default: W = Wr3; K = 128; break;
        }
        int n = idx >> 7;
        int k = idx & 127;
        float v = (k < K) ? W[(size_t)k * 128 + n] : 0.0f;
        __nv_bfloat16 hb = __float2bfloat16(v);
        __nv_bfloat16 lb = __float2bfloat16(v - __bfloat162float(hb));
        imgh[slot * 16384 + idx] = hb;
        imgl[slot * 16384 + idx] = lb;
    }
}

__global__ void fill_kernel(const int* __restrict__ src, const int* __restrict__ dst,
                            int E, int* __restrict__ cnt, int* __restrict__ csr) {
    int e = blockIdx.x * blockDim.x + threadIdx.x;
    if (e >= E) return;
    int d = dst[e];
    int slot = atomicAdd(&cnt[d], 1);
    if (slot < CAP) csr[(size_t)d * CAP + slot] = src[e];
}

// ---------------- CSR mean-aggregation -> bf16 hi/lo split images ----------------
__global__ void aggregate128_kernel(const float* __restrict__ feat,
                                    const int* __restrict__ csr,
                                    const int* __restrict__ cnt,
                                    uint32_t* __restrict__ mh,
                                    uint32_t* __restrict__ ml, int N) {
    int warp = (blockIdx.x * blockDim.x + threadIdx.x) >> 5;
    int lane = threadIdx.x & 31;
    if (warp >= N) return;
    int deg = cnt[warp];
    int n = deg < CAP ? deg : CAP;
    const int* row = csr + (size_t)warp * CAP;
    float4 a[8];
    #pragma unroll
    for (int j = 0; j < 8; j++) a[j] = make_float4(0.f, 0.f, 0.f, 0.f);
    int e = 0;
    for (; e + 8 <= n; e += 8) {
        int s[8];
        #pragma unroll
        for (int j = 0; j < 8; j++) s[j] = __ldg(&row[e + j]);
        #pragma unroll
        for (int j = 0; j < 8; j++) {
            float4 v = *(const float4*)(feat + (size_t)s[j] * 128 + lane * 4);
            a[j].x += v.x; a[j].y += v.y; a[j].z += v.z; a[j].w += v.w;
        }
    }
    for (; e < n; e++) {
        int s = __ldg(&row[e]);
        float4 v = *(const float4*)(feat + (size_t)s * 128 + lane * 4);
        a[0].x += v.x; a[0].y += v.y; a[0].z += v.z; a[0].w += v.w;
    }
    #pragma unroll
    for (int j = 1; j < 8; j++) {
        a[0].x += a[j].x; a[0].y += a[j].y; a[0].z += a[j].z; a[0].w += a[j].w;
    }
    float s = 1.0f / (float)(deg > 1 ? deg : 1);
    uint32_t h0, l0, h1, l1;
    split2(a[0].x * s, a[0].y * s, h0, l0);
    split2(a[0].z * s, a[0].w * s, h1, l1);
    *(uint2*)&mh[(size_t)warp * 64 + lane * 2] = make_uint2(h0, h1);
    *(uint2*)&ml[(size_t)warp * 64 + lane * 2] = make_uint2(l0, l1);
}

// D=50 variant: writes padded [N][64] split images (zeros cols 50..63)
__global__ void aggregate50_kernel(const float* __restrict__ feat,
                                   const int* __restrict__ csr,
                                   const int* __restrict__ cnt,
                                   uint32_t* __restrict__ mh,
                                   uint32_t* __restrict__ ml, int N) {
    int warp = (blockIdx.x * blockDim.x + threadIdx.x) >> 5;
    int lane = threadIdx.x & 31;
    if (warp >= N) return;
    int deg = cnt[warp];
    float2 r = make_float2(0.f, 0.f);
    if (lane < 25) {
        int n = deg < CAP ? deg : CAP;
        const int* row = csr + (size_t)warp * CAP;
        float2 a[8];
        #pragma unroll
        for (int j = 0; j < 8; j++) a[j] = make_float2(0.f, 0.f);
        int e = 0;
        for (; e + 8 <= n; e += 8) {
            int s[8];
            #pragma unroll
            for (int j = 0; j < 8; j++) s[j] = __ldg(&row[e + j]);
            #pragma unroll
            for (int j = 0; j < 8; j++) {
                float2 v = *(const float2*)(feat + (size_t)s[j] * 50 + lane * 2);
                a[j].x += v.x; a[j].y += v.y;
            }
        }
        for (; e < n; e++) {
            int s = __ldg(&row[e]);
            float2 v = *(const float2*)(feat + (size_t)s * 50 + lane * 2);
            a[0].x += v.x; a[0].y += v.y;
        }
        #pragma unroll
        for (int j = 1; j < 8; j++) { a[0].x += a[j].x; a[0].y += a[j].y; }
        float s = 1.0f / (float)(deg > 1 ? deg : 1);
        r.x = a[0].x * s; r.y = a[0].y * s;
    }
    uint32_t h, l;
    split2(r.x, r.y, h, l);
    mh[(size_t)warp * 32 + lane] = h;
    ml[(size_t)warp * 32 + lane] = l;
}

// ---------------- cp.async-pipelined mma.sync GEMM (pre-split operands) ----------
#define TILE_B 10240
#define SM_AH(b) ((b) * TILE_B)
#define SM_AL(b) (20480 + (b) * TILE_B)
#define SM_BH(b) (40960 + (b) * TILE_B)
#define SM_BL(b) (61440 + (b) * TILE_B)
#define SREDO 81920
#define SMBYTES (81920 + 256)

// EPI 0: + bias, store raw to out, accumulate (sum,sumsq) into redOut
// EPI 1: v = prelu(ln(rawbuf)); out2 = v; out = v + acc; split(out)->outsh/outsl
// EPI 2: v = prelu(ln(rawbuf)); out  = v + addend + acc; split(out)->outsh/outsl
template<int KP1, int KP2, int EPI>
__global__ __launch_bounds__(512, 2)
void gemm_mma(const __nv_bfloat16* __restrict__ A1h, const __nv_bfloat16* __restrict__ A1l,
              const __nv_bfloat16* __restrict__ A2h, const __nv_bfloat16* __restrict__ A2l,
              const __nv_bfloat16* __restrict__ B1h, const __nv_bfloat16* __restrict__ B1l,
              const __nv_bfloat16* __restrict__ B2h, const __nv_bfloat16* __restrict__ B2l,
              const float* __restrict__ bias,
              float* __restrict__ out, float* __restrict__ out2,
              uint32_t* __restrict__ outsh, uint32_t* __restrict__ outsl,
              const float* __restrict__ rawbuf, const float* __restrict__ addend,
              const float* __restrict__ lnw, const float* __restrict__ lnb,
              const float* __restrict__ alpha,
              const double* __restrict__ redIn, double* __restrict__ redOut,
              int N) {
    extern __shared__ __align__(16) unsigned char sm[];
    uint32_t sb = smem_to_u32(sm);
    int tid = threadIdx.x;
    int lane = tid & 31;
    int warp = tid >> 5;
    int wm = warp >> 2;
    int wn = warp & 3;
    int blockRow = blockIdx.x * 128;

    constexpr int CH1 = KP1 / 32;
    constexpr int CH2 = KP2 / 32;
    constexpr int CH = CH1 + CH2;

    const int prow = tid >> 2;        // 0..127
    const int pseg = tid & 3;         // 16B segment
    const int grow = blockRow + prow;
    const uint32_t asz = (grow < N) ? 16u : 0u;

    auto prefetch = [&](int cc, int buf) {
        const __nv_bfloat16 *ah, *al, *bh, *bl;
        int kp, c;
        if (cc < CH1) { ah = A1h; al = A1l; bh = B1h; bl = B1l; kp = KP1; c = cc; }
        else          { ah = A2h; al = A2l; bh = B2h; bl = B2l; kp = KP2; c = cc - CH1; }
        size_t aoff = ((size_t)grow * kp + c * 32) * 2 + pseg * 16;
        size_t boff = ((size_t)prow * 128 + c * 32) * 2 + pseg * 16;
        uint32_t d = prow * 80 + pseg * 16;
        cpa16(sb + SM_AH(buf) + d, (const unsigned char*)ah + aoff, asz);
        cpa16(sb + SM_AL(buf) + d, (const unsigned char*)al + aoff, asz);
        cpa16(sb + SM_BH(buf) + d, (const unsigned char*)bh + boff, 16u);
        cpa16(sb + SM_BL(buf) + d, (const unsigned char*)bl + boff, 16u);
    };

    float acc[2][4][4];
    #pragma unroll
    for (int i = 0; i < 2; i++)
        #pragma unroll
        for (int j = 0; j < 4; j++)
            #pragma unroll
            for (int r = 0; r < 4; r++) acc[i][j][r] = 0.0f;

    prefetch(0, 0);
    cp_commit();
    for (int cc = 0; cc < CH; cc++) {
        int buf = cc & 1;
        if (cc + 1 < CH) {
            prefetch(cc + 1, buf ^ 1);
            cp_commit();
            cp_wait<1>();
        } else {
            cp_wait<0>();
        }
        __syncthreads();
        uint32_t ahb = sb + SM_AH(buf), alb = sb + SM_AL(buf);
        uint32_t bhb = sb + SM_BH(buf), blb = sb + SM_BL(buf);
        #pragma unroll
        for (int ks = 0; ks < 32; ks += 16) {
            // A fragments hoisted per mi; B fragments reloaded per ni (low live range)
            #pragma unroll
            for (int mi = 0; mi < 2; mi++) {
                int arow = wm * 32 + mi * 16 + (lane & 15);
                int akoff = ks + (lane >> 4) * 8;
                uint32_t ah[4], al[4];
                ldsm_x4(ah, ahb + arow * 80 + akoff * 2);
                ldsm_x4(al, alb + arow * 80 + akoff * 2);
                #pragma unroll
                for (int ni = 0; ni < 4; ni++) {
                    int nrow = wn * 32 + ni * 8 + (lane & 7);
                    int bkoff = ks + ((lane >> 3) & 1) * 8;
                    uint32_t bh[2], bl[2];
                    ldsm_x2(bh, bhb + nrow * 80 + bkoff * 2);
                    ldsm_x2(bl, blb + nrow * 80 + bkoff * 2);
                    mma_bf16(acc[mi][ni], ah, bh);
                    mma_bf16(acc[mi][ni], ah, bl);
                    mma_bf16(acc[mi][ni], al, bh);
                }
            }
        }
        __syncthreads();
    }

    // ---- epilogue ----
    double ls = 0.0, lq = 0.0;
    float mu = 0.f, scale = 0.f, aslope = 0.f;
    if constexpr (EPI != 0) {
        double M = (double)N * 128.0;
        double mean = redIn[0] / M;
        double var = redIn[1] / M - mean * mean;
        if (var < 0.0) var = 0.0;
        scale = (float)(1.0 / (sqrt(var) + LN_EPS));
        mu = (float)mean;
        aslope = alpha[0];
    }
    #pragma unroll
    for (int mi = 0; mi < 2; mi++) {
        int rbase = blockRow + wm * 32 + mi * 16 + (lane >> 2);
        #pragma unroll
        for (int ni = 0; ni < 4; ni++) {
            int col = wn * 32 + ni * 8 + (lane & 3) * 2;
            #pragma unroll
            for (int half = 0; half < 2; half++) {
                int r = rbase + half * 8;
                if (r >= N) continue;
                float d0 = acc[mi][ni][half * 2];
                float d1 = acc[mi][ni][half * 2 + 1];
                size_t off = (size_t)r * 128 + col;
                if constexpr (EPI == 0) {
                    float o0 = d0 + bias[col];
                    float o1 = d1 + bias[col + 1];
                    *(float2*)&out[off] = make_float2(o0, o1);
                    ls += (double)o0 + (double)o1;
                    lq += (double)o0 * o0 + (double)o1 * o1;
                } else {
                    float2 rv = *(const float2*)&rawbuf[off];
                    float v0 = (rv.x - mu) * scale * lnw[col] + lnb[col];
                    float v1 = (rv.y - mu) * scale * lnw[col + 1] + lnb[col + 1];
                    v0 = v0 >= 0.f ? v0 : aslope * v0;
                    v1 = v1 >= 0.f ? v1 : aslope * v1;
                    float o0, o1;
                    if constexpr (EPI == 1) {
                        *(float2*)&out2[off] = make_float2(v0, v1);
                        o0 = v0 + d0; o1 = v1 + d1;
                    } else {
                        float2 ad = *(const float2*)&addend[off];
                        o0 = v0 + ad.x + d0; o1 = v1 + ad.y + d1;
                    }
                    *(float2*)&out[off] = make_float2(o0, o1);
                    uint32_t h, l;
                    split2(o0, o1, h, l);
                    outsh[(size_t)r * 64 + (col >> 1)] = h;
                    outsl[(size_t)r * 64 + (col >> 1)] = l;
                }
            }
        }
    }

    if constexpr (EPI == 0) {
        #pragma unroll
        for (int off = 16; off > 0; off >>= 1) {
            ls += __shfl_down_sync(0xffffffffu, ls, off);
            lq += __shfl_down_sync(0xffffffffu, lq, off);
        }
        double* sRed = (double*)(sm + SREDO);
        if (lane == 0) { sRed[warp * 2] = ls; sRed[warp * 2 + 1] = lq; }
        __syncthreads();
        if (tid == 0) {
            double S = 0.0, Q = 0.0;
            #pragma unroll
            for (int w = 0; w < 16; w++) { S += sRed[w * 2]; Q += sRed[w * 2 + 1]; }
            atomicAdd(&redOut[0], S);
            atomicAdd(&redOut[1], Q);
        }
    }
}

// final LN + PReLU on the output buffer
__global__ void ln_prelu_kernel(float* __restrict__ buf, const double* __restrict__ red,
                                const float* __restrict__ lnw, const float* __restrict__ lnb,
                                const float* __restrict__ alpha, int N) {
    long idx = (long)blockIdx.x * blockDim.x + threadIdx.x;
    long total = (long)N * 32;
    if (idx >= total) return;
    double M = (double)N * 128.0;
    double mean = red[0] / M;
    double var = red[1] / M - mean * mean;
    if (var < 0.0) var = 0.0;
    float sc = (float)(1.0 / (sqrt(var) + LN_EPS));
    float mu = (float)mean;
    float a = alpha[0];
    int c4 = ((int)(idx & 31)) * 4;
    float4 v = ((float4*)buf)[idx];
    float w0 = lnw[c4], w1 = lnw[c4 + 1], w2 = lnw[c4 + 2], w3 = lnw[c4 + 3];
    float b0 = lnb[c4], b1 = lnb[c4 + 1], b2 = lnb[c4 + 2], b3 = lnb[c4 + 3];
    float o0 = (v.x - mu) * sc * w0 + b0; o0 = o0 >= 0.f ? o0 : a * o0;
    float o1 = (v.y - mu) * sc * w1 + b1; o1 = o1 >= 0.f ? o1 : a * o1;
    float o2 = (v.z - mu) * sc * w2 + b2; o2 = o2 >= 0.f ? o2 : a * o2;
    float o3 = (v.w - mu) * sc * w3 + b3; o3 = o3 >= 0.f ? o3 : a * o3;
    ((float4*)buf)[idx] = make_float4(o0, o1, o2, o3);
}

// ---------------- launch ----------------
extern "C" void kernel_launch(void* const* d_in, const int* in_sizes, int n_in,
                              void* d_out, int out_size) {
    const float* x    = (const float*)d_in[0];
    const int*   srcp = (const int*)d_in[1];
    const int*   dstp = (const int*)d_in[2];
    const float* Wl1  = (const float*)d_in[3];
    const float* Wr1  = (const float*)d_in[4];
    const float* b1   = (const float*)d_in[5];
    const float* Wl2  = (const float*)d_in[6];
    const float* Wr2  = (const float*)d_in[7];
    const float* b2   = (const float*)d_in[8];
    const float* Wl3  = (const float*)d_in[9];
    const float* Wr3  = (const float*)d_in[10];
    const float* b3   = (const float*)d_in[11];
    const float* Ws1  = (const float*)d_in[12];
    const float* Ws2  = (const float*)d_in[13];
    const float* lnw1 = (const float*)d_in[14];
    const float* lnb1 = (const float*)d_in[15];
    const float* lnw2 = (const float*)d_in[16];
    const float* lnb2 = (const float*)d_in[17];
    const float* lnw3 = (const float*)d_in[18];
    const float* lnb3 = (const float*)d_in[19];
    const float* a1   = (const float*)d_in[20];
    const float* a2   = (const float*)d_in[21];
    const float* a3   = (const float*)d_in[22];

    int E = in_sizes[1];
    int N = in_sizes[0] / 50;

    float *h1, *tmp;
    double* red;
    int *cnt, *csr;
    __nv_bfloat16 *imgh, *imgl, *xh, *xl, *aggh, *aggl, *tmph, *tmpl;
    cudaGetSymbolAddress((void**)&h1,   g_h1);
    cudaGetSymbolAddress((void**)&tmp,  g_tmp);
    cudaGetSymbolAddress((void**)&red,  g_red);
    cudaGetSymbolAddress((void**)&cnt,  g_cnt);
    cudaGetSymbolAddress((void**)&csr,  g_csr);
    cudaGetSymbolAddress((void**)&imgh, g_wimgh);
    cudaGetSymbolAddress((void**)&imgl, g_wimgl);
    cudaGetSymbolAddress((void**)&xh,   g_xh);
    cudaGetSymbolAddress((void**)&xl,   g_xl);
    cudaGetSymbolAddress((void**)&aggh, g_aggh);
    cudaGetSymbolAddress((void**)&aggl, g_aggl);
    cudaGetSymbolAddress((void**)&tmph, g_tmph);
    cudaGetSymbolAddress((void**)&tmpl, g_tmpl);

    float* out = (float*)d_out;

    int gemmGrid = (N + 127) / 128;
    int aggGrid = (N + 7) / 8;
    int zeroB = (N + 255) / 256;
    int xB = (N * 32 + 255) / 256;
    int setupGrid = zeroB + xB + 512;

    cudaFuncSetAttribute(gemm_mma<64, 64, 0>,   cudaFuncAttributeMaxDynamicSharedMemorySize, SMBYTES);
    cudaFuncSetAttribute(gemm_mma<0, 64, 1>,    cudaFuncAttributeMaxDynamicSharedMemorySize, SMBYTES);
    cudaFuncSetAttribute(gemm_mma<128, 128, 0>, cudaFuncAttributeMaxDynamicSharedMemorySize, SMBYTES);
    cudaFuncSetAttribute(gemm_mma<0, 64, 2>,    cudaFuncAttributeMaxDynamicSharedMemorySize, SMBYTES);

    // launch 0: merged setup
    setup_kernel<<<setupGrid, 256>>>(x, Wl1, Wr1, Ws1, Wl2, Wr2, Ws2, Wl3, Wr3,
                                     cnt, red, (uint32_t*)xh, (uint32_t*)xl,
                                     imgh, imgl, N);
    // launch 1: CSR fill
    fill_kernel<<<(E + 255) / 256, 256>>>(srcp, dstp, E, cnt, csr);
    // launch 2: layer-1 aggregation (splits to aggh/aggl)
    aggregate50_kernel<<<aggGrid, 256>>>(x, csr, cnt, (uint32_t*)aggh, (uint32_t*)aggl, N);
    // launch 3 (ncu target): layer-1 GEMM  h1raw = mean@Wl1 + x@Wr1 + b1
    gemm_mma<64, 64, 0><<<gemmGrid, 512, SMBYTES>>>(
        aggh, aggl, xh, xl,
        imgh + 0 * 16384, imgl + 0 * 16384, imgh + 1 * 16384, imgl + 1 * 16384,
        b1, h1,
        nullptr, nullptr, nullptr, nullptr, nullptr, nullptr, nullptr, nullptr, nullptr,
        red + 0, N);
    // launch 4: h1 := prelu(ln(h1raw)); tmp := h1n + x@Ws1 (+ split images)
    gemm_mma<0, 64, 1><<<gemmGrid, 512, SMBYTES>>>(
        nullptr, nullptr, xh, xl,
        nullptr, nullptr, imgh + 2 * 16384, imgl + 2 * 16384,
        nullptr, tmp, h1, (uint32_t*)tmph, (uint32_t*)tmpl, h1, nullptr,
        lnw1, lnb1, a1, red + 0, nullptr, N);
    // layer 2
    aggregate128_kernel<<<aggGrid, 256>>>(tmp, csr, cnt, (uint32_t*)aggh, (uint32_t*)aggl, N);
    gemm_mma<128, 128, 0><<<gemmGrid, 512, SMBYTES>>>(
        aggh, aggl, tmph, tmpl,
        imgh + 3 * 16384, imgl + 3 * 16384, imgh + 4 * 16384, imgl + 4 * 16384,
        b2, tmp,
        nullptr, nullptr, nullptr, nullptr, nullptr, nullptr, nullptr, nullptr, nullptr,
        red + 2, N);
    gemm_mma<0, 64, 2><<<gemmGrid, 512, SMBYTES>>>(
        nullptr, nullptr, xh, xl,
        nullptr, nullptr, imgh + 5 * 16384, imgl + 5 * 16384,
        nullptr, tmp, nullptr, (uint32_t*)tmph, (uint32_t*)tmpl, tmp, h1,
        lnw2, lnb2, a2, red + 2, nullptr, N);
    // layer 3
    aggregate128_kernel<<<aggGrid, 256>>>(tmp, csr, cnt, (uint32_t*)aggh, (uint32_t*)aggl, N);
    gemm_mma<128, 128, 0><<<gemmGrid, 512, SMBYTES>>>(
        aggh, aggl, tmph, tmpl,
        imgh + 6 * 16384, imgl + 6 * 16384, imgh + 7 * 16384, imgl + 7 * 16384,
        b3, out,
        nullptr, nullptr, nullptr, nullptr, nullptr, nullptr, nullptr, nullptr, nullptr,
        red + 4, N);
    ln_prelu_kernel<<<(int)(((long)N * 32 + 255) / 256), 256>>>(out, red + 4,
                                                                lnw3, lnb3, a3, N);
}

// round 14
// speedup vs baseline: 2.1572x; 1.2979x over previous
#include <cuda_runtime.h>
#include <cuda_bf16.h>
#include <math.h>
#include <stdint.h>

#define MAXN 100000
#define NPAD 100128            // MAXN rounded up past a 128-row tile
#define PLANEB (NPAD * 128)    // bytes per 64-col (128B-row) plane
#define CAP  128
#define LN_EPS 1e-5

typedef unsigned long long u64;

// ---------------- scratch (static device globals; no allocation) ----------------
__device__ float  g_h1 [(size_t)MAXN * 128];
__device__ float  g_tmp[(size_t)MAXN * 128];
__device__ int    g_cnt[MAXN];
__device__ double g_red[8];
__device__ int    g_csr[(size_t)MAXN * CAP];
// pre-swizzled bf16 images (chunk-major planes of 128B rows)
__device__ __align__(16) unsigned char g_wimgh[8 * 32768];
__device__ __align__(16) unsigned char g_wimgl[8 * 32768];
__device__ __align__(16) unsigned char g_xh[PLANEB];
__device__ __align__(16) unsigned char g_xl[PLANEB];
__device__ __align__(16) unsigned char g_aggh[2 * (size_t)PLANEB];
__device__ __align__(16) unsigned char g_aggl[2 * (size_t)PLANEB];
__device__ __align__(16) unsigned char g_tmph[2 * (size_t)PLANEB];
__device__ __align__(16) unsigned char g_tmpl[2 * (size_t)PLANEB];

// swizzled byte offset within a plane: row r, byte-in-row w (16B-unit XOR)
__device__ __forceinline__ size_t swzoff(int r, int w) {
    return (size_t)r * 128 + (w ^ ((r & 7) << 4));
}

// ---------------- mma/ldmatrix/cp.async helpers (sm_80+ ISA) ----------------
__device__ __forceinline__ uint32_t smem_to_u32(const void* p) {
    uint32_t a;
    asm("{ .reg .u64 t; cvta.to.shared.u64 t, %1; cvt.u32.u64 %0, t; }" : "=r"(a) : "l"(p));
    return a;
}
__device__ __forceinline__ void ldsm_x4(uint32_t (&r)[4], uint32_t addr) {
    asm volatile("ldmatrix.sync.aligned.m8n8.x4.shared.b16 {%0,%1,%2,%3}, [%4];"
                 : "=r"(r[0]), "=r"(r[1]), "=r"(r[2]), "=r"(r[3]) : "r"(addr));
}
__device__ __forceinline__ void ldsm_x2(uint32_t (&r)[2], uint32_t addr) {
    asm volatile("ldmatrix.sync.aligned.m8n8.x2.shared.b16 {%0,%1}, [%2];"
                 : "=r"(r[0]), "=r"(r[1]) : "r"(addr));
}
__device__ __forceinline__ void mma_bf16(float (&c)[4], const uint32_t (&a)[4],
                                         const uint32_t (&b)[2]) {
    asm volatile(
        "mma.sync.aligned.m16n8k16.row.col.f32.bf16.bf16.f32 "
        "{%0,%1,%2,%3}, {%4,%5,%6,%7}, {%8,%9}, {%0,%1,%2,%3};"
        : "+f"(c[0]), "+f"(c[1]), "+f"(c[2]), "+f"(c[3])
        : "r"(a[0]), "r"(a[1]), "r"(a[2]), "r"(a[3]), "r"(b[0]), "r"(b[1]));
}
__device__ __forceinline__ void cpa16(uint32_t dst, const void* src) {
    asm volatile("cp.async.cg.shared.global [%0], [%1], 16;"
                 :: "r"(dst), "l"(src));
}
__device__ __forceinline__ void cp_commit() {
    asm volatile("cp.async.commit_group;" ::: "memory");
}
template<int NW>
__device__ __forceinline__ void cp_wait() {
    asm volatile("cp.async.wait_group %0;" :: "n"(NW) : "memory");
}
// split two fp32 into packed bf16 hi-pair and lo-pair (low 16 bits = first elem)
__device__ __forceinline__ void split2(float v0, float v1, uint32_t& h, uint32_t& l) {
    __nv_bfloat16 h0 = __float2bfloat16(v0);
    __nv_bfloat16 h1 = __float2bfloat16(v1);
    __nv_bfloat16 l0 = __float2bfloat16(v0 - __bfloat162float(h0));
    __nv_bfloat16 l1 = __float2bfloat16(v1 - __bfloat162float(h1));
    h = (uint32_t)__bfloat16_as_ushort(h0) | ((uint32_t)__bfloat16_as_ushort(h1) << 16);
    l = (uint32_t)__bfloat16_as_ushort(l0) | ((uint32_t)__bfloat16_as_ushort(l1) << 16);
}

// ---------------- merged setup kernel ----------------
__global__ void setup_kernel(const float* __restrict__ x,
                             const float* Wl1, const float* Wr1, const float* Ws1,
                             const float* Wl2, const float* Wr2, const float* Ws2,
                             const float* Wl3, const float* Wr3,
                             int* __restrict__ cnt, double* __restrict__ red,
                             unsigned char* __restrict__ xh, unsigned char* __restrict__ xl,
                             unsigned char* __restrict__ imgh,
                             unsigned char* __restrict__ imgl, int N) {
    int zeroB = (N + 255) >> 8;
    int xB = (N * 32 + 255) >> 8;
    int bid = blockIdx.x;
    int tid = threadIdx.x;
    if (bid < zeroB) {
        int i = bid * 256 + tid;
        if (i < N) cnt[i] = 0;
        if (i < 8) red[i] = 0.0;
    } else if (bid < zeroB + xB) {
        int t = (bid - zeroB) * 256 + tid;
        int row = t >> 5;
        int c2 = t & 31;
        if (row < N) {
            int col = c2 * 2;
            float v0 = (col < 50) ? x[(size_t)row * 50 + col] : 0.0f;
            float v1 = (col + 1 < 50) ? x[(size_t)row * 50 + col + 1] : 0.0f;
            uint32_t h, l;
            split2(v0, v1, h, l);
            size_t off = swzoff(row, c2 * 4);
            *(uint32_t*)(xh + off) = h;
            *(uint32_t*)(xl + off) = l;
        }
    } else {
        int b2 = bid - zeroB - xB;
        int slot = b2 >> 6;
        int idx = (b2 & 63) * 256 + tid;
        const float* W; int K;
        switch (slot) {
            case 0: W = Wl1; K = 50;  break;
            case 1: W = Wr1; K = 50;  break;
            case 2: W = Ws1; K = 50;  break;
            case 3: W = Wl2; K = 128; break;
            case 4: W = Wr2; K = 128; break;
            case 5: W = Ws2; K = 50;  break;
            case 6: W = Wl3; K = 128; break;
            default: W = Wr3; K = 128; break;
        }
        int n = idx >> 7;          // output col 0..127
        int k = idx & 127;         // k 0..127
        float v = (k < K) ? W[(size_t)k * 128 + n] : 0.0f;
        __nv_bfloat16 hb = __float2bfloat16(v);
        __nv_bfloat16 lb = __float2bfloat16(v - __bfloat162float(hb));
        int c = k >> 6, kk = k & 63;
        size_t off = (size_t)slot * 32768 + (size_t)c * 16384 + swzoff(n, kk * 2);
        *(__nv_bfloat16*)(imgh + off) = hb;
        *(__nv_bfloat16*)(imgl + off) = lb;
    }
}

__global__ void fill_kernel(const int* __restrict__ src, const int* __restrict__ dst,
                            int E, int* __restrict__ cnt, int* __restrict__ csr) {
    int e = blockIdx.x * blockDim.x + threadIdx.x;
    if (e >= E) return;
    int d = dst[e];
    int slot = atomicAdd(&cnt[d], 1);
    if (slot < CAP) csr[(size_t)d * CAP + slot] = src[e];
}

// ---------------- CSR mean-aggregation -> swizzled bf16 hi/lo planes ----------------
__global__ void aggregate128_kernel(const float* __restrict__ feat,
                                    const int* __restrict__ csr,
                                    const int* __restrict__ cnt,
                                    unsigned char* __restrict__ mh,
                                    unsigned char* __restrict__ ml, int N) {
    int warp = (blockIdx.x * blockDim.x + threadIdx.x) >> 5;
    int lane = threadIdx.x & 31;
    if (warp >= N) return;
    int deg = cnt[warp];
    int n = deg < CAP ? deg : CAP;
    const int* row = csr + (size_t)warp * CAP;
    float4 a[8];
    #pragma unroll
    for (int j = 0; j < 8; j++) a[j] = make_float4(0.f, 0.f, 0.f, 0.f);
    int e = 0;
    for (; e + 8 <= n; e += 8) {
        int s[8];
        #pragma unroll
        for (int j = 0; j < 8; j++) s[j] = __ldg(&row[e + j]);
        #pragma unroll
        for (int j = 0; j < 8; j++) {
            float4 v = *(const float4*)(feat + (size_t)s[j] * 128 + lane * 4);
            a[j].x += v.x; a[j].y += v.y; a[j].z += v.z; a[j].w += v.w;
        }
    }
    for (; e < n; e++) {
        int s = __ldg(&row[e]);
        float4 v = *(const float4*)(feat + (size_t)s * 128 + lane * 4);
        a[0].x += v.x; a[0].y += v.y; a[0].z += v.z; a[0].w += v.w;
    }
    #pragma unroll
    for (int j = 1; j < 8; j++) {
        a[0].x += a[j].x; a[0].y += a[j].y; a[0].z += a[j].z; a[0].w += a[j].w;
    }
    float s = 1.0f / (float)(deg > 1 ? deg : 1);
    uint32_t h0, l0, h1, l1;
    split2(a[0].x * s, a[0].y * s, h0, l0);
    split2(a[0].z * s, a[0].w * s, h1, l1);
    int plane = lane >> 4;                     // cols lane*4 : plane = (lane*4)>>6
    int w = (lane & 15) * 8;                   // byte offset within row
    size_t off = (size_t)plane * PLANEB + swzoff(warp, w);
    *(uint2*)(mh + off) = make_uint2(h0, h1);
    *(uint2*)(ml + off) = make_uint2(l0, l1);
}

// D=50 variant: single plane [N][64 cols], zeros for cols 50..63
__global__ void aggregate50_kernel(const float* __restrict__ feat,
                                   const int* __restrict__ csr,
                                   const int* __restrict__ cnt,
                                   unsigned char* __restrict__ mh,
                                   unsigned char* __restrict__ ml, int N) {
    int warp = (blockIdx.x * blockDim.x + threadIdx.x) >> 5;
    int lane = threadIdx.x & 31;
    if (warp >= N) return;
    int deg = cnt[warp];
    float2 r = make_float2(0.f, 0.f);
    if (lane < 25) {
        int n = deg < CAP ? deg : CAP;
        const int* row = csr + (size_t)warp * CAP;
        float2 a[8];
        #pragma unroll
        for (int j = 0; j < 8; j++) a[j] = make_float2(0.f, 0.f);
        int e = 0;
        for (; e + 8 <= n; e += 8) {
            int s[8];
            #pragma unroll
            for (int j = 0; j < 8; j++) s[j] = __ldg(&row[e + j]);
            #pragma unroll
            for (int j = 0; j < 8; j++) {
                float2 v = *(const float2*)(feat + (size_t)s[j] * 50 + lane * 2);
                a[j].x += v.x; a[j].y += v.y;
            }
        }
        for (; e < n; e++) {
            int s = __ldg(&row[e]);
            float2 v = *(const float2*)(feat + (size_t)s * 50 + lane * 2);
            a[0].x += v.x; a[0].y += v.y;
        }
        #pragma unroll
        for (int j = 1; j < 8; j++) { a[0].x += a[j].x; a[0].y += a[j].y; }
        float s = 1.0f / (float)(deg > 1 ? deg : 1);
        r.x = a[0].x * s; r.y = a[0].y * s;
    }
    uint32_t h, l;
    split2(r.x, r.y, h, l);
    size_t off = swzoff(warp, lane * 4);
    *(uint32_t*)(mh + off) = h;
    *(uint32_t*)(ml + off) = l;
}

// ---------------- cp.async-pipelined mma.sync GEMM (KC=64, pre-swizzled) ----------
// smem: Ah0 Al0 Ah1 Al1 (16KB each, double-buffered A) + Bh Bl (16KB, single) + red
#define SM_AH(b) ((b) * 32768)
#define SM_AL(b) ((b) * 32768 + 16384)
#define SM_BH 65536
#define SM_BL 81920
#define SREDO 98304
#define SMBYTES (98304 + 256)

// EPI 0: + bias, store raw to out, accumulate (sum,sumsq) into redOut
// EPI 1: v = prelu(ln(rawbuf)); out2 = v; out = v + acc; split(out)->outsh/outsl
// EPI 2: v = prelu(ln(rawbuf)); out  = v + addend + acc; split(out)->outsh/outsl
template<int CH1, int CH2, int EPI>
__global__ __launch_bounds__(512, 2)
void gemm_mma(const unsigned char* __restrict__ A1h, const unsigned char* __restrict__ A1l,
              const unsigned char* __restrict__ A2h, const unsigned char* __restrict__ A2l,
              const unsigned char* __restrict__ B1h, const unsigned char* __restrict__ B1l,
              const unsigned char* __restrict__ B2h, const unsigned char* __restrict__ B2l,
              const float* __restrict__ bias,
              float* __restrict__ out, float* __restrict__ out2,
              unsigned char* __restrict__ outsh, unsigned char* __restrict__ outsl,
              const float* __restrict__ rawbuf, const float* __restrict__ addend,
              const float* __restrict__ lnw, const float* __restrict__ lnb,
              const float* __restrict__ alpha,
              const double* __restrict__ redIn, double* __restrict__ redOut,
              int N) {
    extern __shared__ __align__(16) unsigned char sm[];
    uint32_t sb = smem_to_u32(sm);
    int tid = threadIdx.x;
    int lane = tid & 31;
    int warp = tid >> 5;
    int wm = warp >> 2;
    int wn = warp & 3;
    int blockRow = blockIdx.x * 128;

    constexpr int CH = CH1 + CH2;
    size_t arowoff = (size_t)blockRow * 128;

    auto prefetch_A = [&](int cc, int buf) {
        const unsigned char *ph, *pl;
        if (cc < CH1) { ph = A1h + (size_t)cc * PLANEB; pl = A1l + (size_t)cc * PLANEB; }
        else          { ph = A2h + (size_t)(cc - CH1) * PLANEB; pl = A2l + (size_t)(cc - CH1) * PLANEB; }
        ph += arowoff; pl += arowoff;
        #pragma unroll
        for (int t = 0; t < 2; t++) {
            int u = (tid + t * 512) * 16;
            cpa16(sb + SM_AH(buf) + u, ph + u);
            cpa16(sb + SM_AL(buf) + u, pl + u);
        }
    };
    auto prefetch_B = [&](int cc) {
        const unsigned char *ph, *pl;
        if (cc < CH1) { ph = B1h + (size_t)cc * 16384; pl = B1l + (size_t)cc * 16384; }
        else          { ph = B2h + (size_t)(cc - CH1) * 16384; pl = B2l + (size_t)(cc - CH1) * 16384; }
        #pragma unroll
        for (int t = 0; t < 2; t++) {
            int u = (tid + t * 512) * 16;
            cpa16(sb + SM_BH + u, ph + u);
            cpa16(sb + SM_BL + u, pl + u);
        }
    };

    float acc[2][4][4];
    #pragma unroll
    for (int i = 0; i < 2; i++)
        #pragma unroll
        for (int j = 0; j < 4; j++)
            #pragma unroll
            for (int r = 0; r < 4; r++) acc[i][j][r] = 0.0f;

    prefetch_A(0, 0);
    prefetch_B(0);
    cp_commit();
    for (int cc = 0; cc < CH; cc++) {
        int buf = cc & 1;
        if (cc + 1 < CH) {
            prefetch_A(cc + 1, buf ^ 1);
            cp_commit();
            cp_wait<1>();
        } else {
            cp_wait<0>();
        }
        __syncthreads();
        uint32_t ahb = sb + SM_AH(buf), alb = sb + SM_AL(buf);
        uint32_t bhb = sb + SM_BH, blb = sb + SM_BL;
        #pragma unroll
        for (int ks = 0; ks < 64; ks += 16) {
            #pragma unroll
            for (int mi = 0; mi < 2; mi++) {
                int arow = wm * 32 + mi * 16 + (lane & 15);
                int akoff = (ks + (lane >> 4) * 8) * 2;
                uint32_t aoff = arow * 128 + (akoff ^ ((arow & 7) << 4));
                uint32_t ah[4], al[4];
                ldsm_x4(ah, ahb + aoff);
                ldsm_x4(al, alb + aoff);
                #pragma unroll
                for (int ni = 0; ni < 4; ni++) {
                    int nrow = wn * 32 + ni * 8 + (lane & 7);
                    int bkoff = (ks + ((lane >> 3) & 1) * 8) * 2;
                    uint32_t boff = nrow * 128 + (bkoff ^ ((nrow & 7) << 4));
                    uint32_t bh[2], bl[2];
                    ldsm_x2(bh, bhb + boff);
                    ldsm_x2(bl, blb + boff);
                    mma_bf16(acc[mi][ni], ah, bh);
                    mma_bf16(acc[mi][ni], ah, bl);
                    mma_bf16(acc[mi][ni], al, bh);
                }
            }
        }
        __syncthreads();
        if (cc + 1 < CH) {
            prefetch_B(cc + 1);
            cp_commit();
        }
    }

    // ---- epilogue ----
    float ls = 0.0f, lq = 0.0f;
    float mu = 0.f, scale = 0.f, aslope = 0.f;
    if constexpr (EPI != 0) {
        double M = (double)N * 128.0;
        double mean = redIn[0] / M;
        double var = redIn[1] / M - mean * mean;
        if (var < 0.0) var = 0.0;
        scale = (float)(1.0 / (sqrt(var) + LN_EPS));
        mu = (float)mean;
        aslope = alpha[0];
    }
    #pragma unroll
    for (int mi = 0; mi < 2; mi++) {
        int rbase = blockRow + wm * 32 + mi * 16 + (lane >> 2);
        #pragma unroll
        for (int ni = 0; ni < 4; ni++) {
            int col = wn * 32 + ni * 8 + (lane & 3) * 2;
            #pragma unroll
            for (int half = 0; half < 2; half++) {
                int r = rbase + half * 8;
                if (r >= N) continue;
                float d0 = acc[mi][ni][half * 2];
                float d1 = acc[mi][ni][half * 2 + 1];
                size_t off = (size_t)r * 128 + col;
                if constexpr (EPI == 0) {
                    float o0 = d0 + bias[col];
                    float o1 = d1 + bias[col + 1];
                    *(float2*)&out[off] = make_float2(o0, o1);
                    ls += o0 + o1;
                    lq += o0 * o0 + o1 * o1;
                } else {
                    float2 rv = *(const float2*)&rawbuf[off];
                    float v0 = (rv.x - mu) * scale * lnw[col] + lnb[col];
                    float v1 = (rv.y - mu) * scale * lnw[col + 1] + lnb[col + 1];
                    v0 = v0 >= 0.f ? v0 : aslope * v0;
                    v1 = v1 >= 0.f ? v1 : aslope * v1;
                    float o0, o1;
                    if constexpr (EPI == 1) {
                        *(float2*)&out2[off] = make_float2(v0, v1);
                        o0 = v0 + d0; o1 = v1 + d1;
                    } else {
                        float2 ad = *(const float2*)&addend[off];
                        o0 = v0 + ad.x + d0; o1 = v1 + ad.y + d1;
                    }
                    *(float2*)&out[off] = make_float2(o0, o1);
                    uint32_t h, l;
                    split2(o0, o1, h, l);
                    int plane = col >> 6;
                    size_t soff = (size_t)plane * PLANEB + swzoff(r, (col & 63) * 2);
                    *(uint32_t*)(outsh + soff) = h;
                    *(uint32_t*)(outsl + soff) = l;
                }
            }
        }
    }

    if constexpr (EPI == 0) {
        #pragma unroll
        for (int off = 16; off > 0; off >>= 1) {
            ls += __shfl_down_sync(0xffffffffu, ls, off);
            lq += __shfl_down_sync(0xffffffffu, lq, off);
        }
        float* sRed = (float*)(sm + SREDO);
        if (lane == 0) { sRed[warp * 2] = ls; sRed[warp * 2 + 1] = lq; }
        __syncthreads();
        if (tid == 0) {
            float S = 0.0f, Q = 0.0f;
            #pragma unroll
            for (int w = 0; w < 16; w++) { S += sRed[w * 2]; Q += sRed[w * 2 + 1]; }
            atomicAdd(&redOut[0], (double)S);
            atomicAdd(&redOut[1], (double)Q);
        }
    }
}

// final LN + PReLU on the output buffer
__global__ void ln_prelu_kernel(float* __restrict__ buf, const double* __restrict__ red,
                                const float* __restrict__ lnw, const float* __restrict__ lnb,
                                const float* __restrict__ alpha, int N) {
    long idx = (long)blockIdx.x * blockDim.x + threadIdx.x;
    long total = (long)N * 32;
    if (idx >= total) return;
    double M = (double)N * 128.0;
    double mean = red[0] / M;
    double var = red[1] / M - mean * mean;
    if (var < 0.0) var = 0.0;
    float sc = (float)(1.0 / (sqrt(var) + LN_EPS));
    float mu = (float)mean;
    float a = alpha[0];
    int c4 = ((int)(idx & 31)) * 4;
    float4 v = ((float4*)buf)[idx];
    float w0 = lnw[c4], w1 = lnw[c4 + 1], w2 = lnw[c4 + 2], w3 = lnw[c4 + 3];
    float b0 = lnb[c4], b1 = lnb[c4 + 1], b2 = lnb[c4 + 2], b3 = lnb[c4 + 3];
    float o0 = (v.x - mu) * sc * w0 + b0; o0 = o0 >= 0.f ? o0 : a * o0;
    float o1 = (v.y - mu) * sc * w1 + b1; o1 = o1 >= 0.f ? o1 : a * o1;
    float o2 = (v.z - mu) * sc * w2 + b2; o2 = o2 >= 0.f ? o2 : a * o2;
    float o3 = (v.w - mu) * sc * w3 + b3; o3 = o3 >= 0.f ? o3 : a * o3;
    ((float4*)buf)[idx] = make_float4(o0, o1, o2, o3);
}

// ---------------- launch ----------------
extern "C" void kernel_launch(void* const* d_in, const int* in_sizes, int n_in,
                              void* d_out, int out_size) {
    const float* x    = (const float*)d_in[0];
    const int*   srcp = (const int*)d_in[1];
    const int*   dstp = (const int*)d_in[2];
    const float* Wl1  = (const float*)d_in[3];
    const float* Wr1  = (const float*)d_in[4];
    const float* b1   = (const float*)d_in[5];
    const float* Wl2  = (const float*)d_in[6];
    const float* Wr2  = (const float*)d_in[7];
    const float* b2   = (const float*)d_in[8];
    const float* Wl3  = (const float*)d_in[9];
    const float* Wr3  = (const float*)d_in[10];
    const float* b3   = (const float*)d_in[11];
    const float* Ws1  = (const float*)d_in[12];
    const float* Ws2  = (const float*)d_in[13];
    const float* lnw1 = (const float*)d_in[14];
    const float* lnb1 = (const float*)d_in[15];
    const float* lnw2 = (const float*)d_in[16];
    const float* lnb2 = (const float*)d_in[17];
    const float* lnw3 = (const float*)d_in[18];
    const float* lnb3 = (const float*)d_in[19];
    const float* a1   = (const float*)d_in[20];
    const float* a2   = (const float*)d_in[21];
    const float* a3   = (const float*)d_in[22];

    int E = in_sizes[1];
    int N = in_sizes[0] / 50;

    float *h1, *tmp;
    double* red;
    int *cnt, *csr;
    unsigned char *imgh, *imgl, *xh, *xl, *aggh, *aggl, *tmph, *tmpl;
    cudaGetSymbolAddress((void**)&h1,   g_h1);
    cudaGetSymbolAddress((void**)&tmp,  g_tmp);
    cudaGetSymbolAddress((void**)&red,  g_red);
    cudaGetSymbolAddress((void**)&cnt,  g_cnt);
    cudaGetSymbolAddress((void**)&csr,  g_csr);
    cudaGetSymbolAddress((void**)&imgh, g_wimgh);
    cudaGetSymbolAddress((void**)&imgl, g_wimgl);
    cudaGetSymbolAddress((void**)&xh,   g_xh);
    cudaGetSymbolAddress((void**)&xl,   g_xl);
    cudaGetSymbolAddress((void**)&aggh, g_aggh);
    cudaGetSymbolAddress((void**)&aggl, g_aggl);
    cudaGetSymbolAddress((void**)&tmph, g_tmph);
    cudaGetSymbolAddress((void**)&tmpl, g_tmpl);

    float* out = (float*)d_out;

    int gemmGrid = (N + 127) / 128;
    int aggGrid = (N + 7) / 8;
    int zeroB = (N + 255) / 256;
    int xB = (N * 32 + 255) / 256;
    int setupGrid = zeroB + xB + 512;

    cudaFuncSetAttribute(gemm_mma<1, 1, 0>, cudaFuncAttributeMaxDynamicSharedMemorySize, SMBYTES);
    cudaFuncSetAttribute(gemm_mma<0, 1, 1>, cudaFuncAttributeMaxDynamicSharedMemorySize, SMBYTES);
    cudaFuncSetAttribute(gemm_mma<2, 2, 0>, cudaFuncAttributeMaxDynamicSharedMemorySize, SMBYTES);
    cudaFuncSetAttribute(gemm_mma<0, 1, 2>, cudaFuncAttributeMaxDynamicSharedMemorySize, SMBYTES);

    // launch 0: merged setup (zero + x-split + weight images)
    setup_kernel<<<setupGrid, 256>>>(x, Wl1, Wr1, Ws1, Wl2, Wr2, Ws2, Wl3, Wr3,
                                     cnt, red, xh, xl, imgh, imgl, N);
    // launch 1: CSR fill
    fill_kernel<<<(E + 255) / 256, 256>>>(srcp, dstp, E, cnt, csr);
    // launch 2: layer-1 aggregation
    aggregate50_kernel<<<aggGrid, 256>>>(x, csr, cnt, aggh, aggl, N);
    // launch 3 (ncu target): layer-1 GEMM  h1raw = mean@Wl1 + x@Wr1 + b1
    gemm_mma<1, 1, 0><<<gemmGrid, 512, SMBYTES>>>(
        aggh, aggl, xh, xl,
        imgh + 0 * 32768, imgl + 0 * 32768, imgh + 1 * 32768, imgl + 1 * 32768,
        b1, h1,
        nullptr, nullptr, nullptr, nullptr, nullptr, nullptr, nullptr, nullptr, nullptr,
        red + 0, N);
    // launch 4: h1 := prelu(ln(h1raw)); tmp := h1n + x@Ws1 (+ split planes)
    gemm_mma<0, 1, 1><<<gemmGrid, 512, SMBYTES>>>(
        nullptr, nullptr, xh, xl,
        nullptr, nullptr, imgh + 2 * 32768, imgl + 2 * 32768,
        nullptr, tmp, h1, tmph, tmpl, h1, nullptr,
        lnw1, lnb1, a1, red + 0, nullptr, N);
    // layer 2
    aggregate128_kernel<<<aggGrid, 256>>>(tmp, csr, cnt, aggh, aggl, N);
    gemm_mma<2, 2, 0><<<gemmGrid, 512, SMBYTES>>>(
        aggh, aggl, tmph, tmpl,
        imgh + 3 * 32768, imgl + 3 * 32768, imgh + 4 * 32768, imgl + 4 * 32768,
        b2, tmp,
        nullptr, nullptr, nullptr, nullptr, nullptr, nullptr, nullptr, nullptr, nullptr,
        red + 2, N);
    gemm_mma<0, 1, 2><<<gemmGrid, 512, SMBYTES>>>(
        nullptr, nullptr, xh, xl,
        nullptr, nullptr, imgh + 5 * 32768, imgl + 5 * 32768,
        nullptr, tmp, nullptr, tmph, tmpl, tmp, h1,
        lnw2, lnb2, a2, red + 2, nullptr, N);
    // layer 3
    aggregate128_kernel<<<aggGrid, 256>>>(tmp, csr, cnt, aggh, aggl, N);
    gemm_mma<2, 2, 0><<<gemmGrid, 512, SMBYTES>>>(
        aggh, aggl, tmph, tmpl,
        imgh + 6 * 32768, imgl + 6 * 32768, imgh + 7 * 32768, imgl + 7 * 32768,
        b3, out,
        nullptr, nullptr, nullptr, nullptr, nullptr, nullptr, nullptr, nullptr, nullptr,
        red + 4, N);
    ln_prelu_kernel<<<(int)(((long)N * 32 + 255) / 256), 256>>>(out, red + 4,
                                                                lnw3, lnb3, a3, N);
}

// round 15
// speedup vs baseline: 2.1695x; 1.0057x over previous
#include <cuda_runtime.h>
#include <cuda_bf16.h>
#include <math.h>
#include <stdint.h>

#define MAXN 100000
#define NPAD 100128            // MAXN rounded up past a 128-row tile
#define PLANEB (NPAD * 128)    // bytes per 64-col (128B-row) plane
#define CAP  128
#define LN_EPS 1e-5

typedef unsigned long long u64;

// ---------------- scratch (static device globals; no allocation) ----------------
__device__ float  g_h1 [(size_t)MAXN * 128];
__device__ float  g_tmp[(size_t)MAXN * 128];
__device__ int    g_cnt[MAXN];
__device__ double g_red[8];
__device__ int    g_csr[(size_t)MAXN * CAP];
// pre-swizzled bf16 images (chunk-major planes of 128B rows)
__device__ __align__(16) unsigned char g_wimgh[8 * 32768];
__device__ __align__(16) unsigned char g_wimgl[8 * 32768];
__device__ __align__(16) unsigned char g_xh[PLANEB];
__device__ __align__(16) unsigned char g_xl[PLANEB];
__device__ __align__(16) unsigned char g_aggh[2 * (size_t)PLANEB];
__device__ __align__(16) unsigned char g_aggl[2 * (size_t)PLANEB];
__device__ __align__(16) unsigned char g_tmph[2 * (size_t)PLANEB];
__device__ __align__(16) unsigned char g_tmpl[2 * (size_t)PLANEB];

// swizzled byte offset within a plane: row r, byte-in-row w (16B-unit XOR)
__device__ __forceinline__ size_t swzoff(int r, int w) {
    return (size_t)r * 128 + (w ^ ((r & 7) << 4));
}

// ---------------- mma/ldmatrix/cp.async helpers (sm_80+ ISA) ----------------
__device__ __forceinline__ uint32_t smem_to_u32(const void* p) {
    uint32_t a;
    asm("{ .reg .u64 t; cvta.to.shared.u64 t, %1; cvt.u32.u64 %0, t; }" : "=r"(a) : "l"(p));
    return a;
}
__device__ __forceinline__ void ldsm_x4(uint32_t (&r)[4], uint32_t addr) {
    asm volatile("ldmatrix.sync.aligned.m8n8.x4.shared.b16 {%0,%1,%2,%3}, [%4];"
                 : "=r"(r[0]), "=r"(r[1]), "=r"(r[2]), "=r"(r[3]) : "r"(addr));
}
__device__ __forceinline__ void ldsm_x2(uint32_t (&r)[2], uint32_t addr) {
    asm volatile("ldmatrix.sync.aligned.m8n8.x2.shared.b16 {%0,%1}, [%2];"
                 : "=r"(r[0]), "=r"(r[1]) : "r"(addr));
}
__device__ __forceinline__ void mma_bf16(float (&c)[4], const uint32_t (&a)[4],
                                         const uint32_t (&b)[2]) {
    asm volatile(
        "mma.sync.aligned.m16n8k16.row.col.f32.bf16.bf16.f32 "
        "{%0,%1,%2,%3}, {%4,%5,%6,%7}, {%8,%9}, {%0,%1,%2,%3};"
        : "+f"(c[0]), "+f"(c[1]), "+f"(c[2]), "+f"(c[3])
        : "r"(a[0]), "r"(a[1]), "r"(a[2]), "r"(a[3]), "r"(b[0]), "r"(b[1]));
}
__device__ __forceinline__ void cpa16(uint32_t dst, const void* src) {
    asm volatile("cp.async.cg.shared.global [%0], [%1], 16;"
                 :: "r"(dst), "l"(src));
}
__device__ __forceinline__ void cp_commit() {
    asm volatile("cp.async.commit_group;" ::: "memory");
}
template<int NW>
__device__ __forceinline__ void cp_wait() {
    asm volatile("cp.async.wait_group %0;" :: "n"(NW) : "memory");
}
// split two fp32 into packed bf16 hi-pair and lo-pair (low 16 bits = first elem)
__device__ __forceinline__ void split2(float v0, float v1, uint32_t& h, uint32_t& l) {
    __nv_bfloat16 h0 = __float2bfloat16(v0);
    __nv_bfloat16 h1 = __float2bfloat16(v1);
    __nv_bfloat16 l0 = __float2bfloat16(v0 - __bfloat162float(h0));
    __nv_bfloat16 l1 = __float2bfloat16(v1 - __bfloat162float(h1));
    h = (uint32_t)__bfloat16_as_ushort(h0) | ((uint32_t)__bfloat16_as_ushort(h1) << 16);
    l = (uint32_t)__bfloat16_as_ushort(l0) | ((uint32_t)__bfloat16_as_ushort(l1) << 16);
}

// ---------------- merged setup kernel ----------------
__global__ void setup_kernel(const float* __restrict__ x,
                             const float* Wl1, const float* Wr1, const float* Ws1,
                             const float* Wl2, const float* Wr2, const float* Ws2,
                             const float* Wl3, const float* Wr3,
                             int* __restrict__ cnt, double* __restrict__ red,
                             unsigned char* __restrict__ xh, unsigned char* __restrict__ xl,
                             unsigned char* __restrict__ imgh,
                             unsigned char* __restrict__ imgl, int N) {
    int zeroB = (N + 255) >> 8;
    int xB = (N * 32 + 255) >> 8;
    int bid = blockIdx.x;
    int tid = threadIdx.x;
    if (bid < zeroB) {
        int i = bid * 256 + tid;
        if (i < N) cnt[i] = 0;
        if (i < 8) red[i] = 0.0;
    } else if (bid < zeroB + xB) {
        int t = (bid - zeroB) * 256 + tid;
        int row = t >> 5;
        int c2 = t & 31;
        if (row < N) {
            int col = c2 * 2;
            float v0 = (col < 50) ? x[(size_t)row * 50 + col] : 0.0f;
            float v1 = (col + 1 < 50) ? x[(size_t)row * 50 + col + 1] : 0.0f;
            uint32_t h, l;
            split2(v0, v1, h, l);
            size_t off = swzoff(row, c2 * 4);
            *(uint32_t*)(xh + off) = h;
            *(uint32_t*)(xl + off) = l;
        }
    } else {
        int b2 = bid - zeroB - xB;
        int slot = b2 >> 6;
        int idx = (b2 & 63) * 256 + tid;
        const float* W; int K;
        switch (slot) {
            case 0: W = Wl1; K = 50;  break;
            case 1: W = Wr1; K = 50;  break;
            case 2: W = Ws1; K = 50;  break;
            case 3: W = Wl2; K = 128; break;
            case 4: W = Wr2; K = 128; break;
            case 5: W = Ws2; K = 50;  break;
            case 6: W = Wl3; K = 128; break;
            default: W = Wr3; K = 128; break;
        }
        int n = idx >> 7;          // output col 0..127
        int k = idx & 127;         // k 0..127
        float v = (k < K) ? W[(size_t)k * 128 + n] : 0.0f;
        __nv_bfloat16 hb = __float2bfloat16(v);
        __nv_bfloat16 lb = __float2bfloat16(v - __bfloat162float(hb));
        int c = k >> 6, kk = k & 63;
        size_t off = (size_t)slot * 32768 + (size_t)c * 16384 + swzoff(n, kk * 2);
        *(__nv_bfloat16*)(imgh + off) = hb;
        *(__nv_bfloat16*)(imgl + off) = lb;
    }
}

__global__ void fill_kernel(const int* __restrict__ src, const int* __restrict__ dst,
                            int E, int* __restrict__ cnt, int* __restrict__ csr) {
    int e = blockIdx.x * blockDim.x + threadIdx.x;
    if (e >= E) return;
    int d = dst[e];
    int slot = atomicAdd(&cnt[d], 1);
    if (slot < CAP) csr[(size_t)d * CAP + slot] = src[e];
}

// ---------------- CSR mean-aggregation -> swizzled bf16 hi/lo planes ----------------
__global__ void aggregate128_kernel(const float* __restrict__ feat,
                                    const int* __restrict__ csr,
                                    const int* __restrict__ cnt,
                                    unsigned char* __restrict__ mh,
                                    unsigned char* __restrict__ ml, int N) {
    int warp = (blockIdx.x * blockDim.x + threadIdx.x) >> 5;
    int lane = threadIdx.x & 31;
    if (warp >= N) return;
    int deg = cnt[warp];
    int n = deg < CAP ? deg : CAP;
    const int* row = csr + (size_t)warp * CAP;
    float4 a[8];
    #pragma unroll
    for (int j = 0; j < 8; j++) a[j] = make_float4(0.f, 0.f, 0.f, 0.f);
    int e = 0;
    for (; e + 8 <= n; e += 8) {
        int s[8];
        #pragma unroll
        for (int j = 0; j < 8; j++) s[j] = __ldg(&row[e + j]);
        #pragma unroll
        for (int j = 0; j < 8; j++) {
            float4 v = *(const float4*)(feat + (size_t)s[j] * 128 + lane * 4);
            a[j].x += v.x; a[j].y += v.y; a[j].z += v.z; a[j].w += v.w;
        }
    }
    for (; e < n; e++) {
        int s = __ldg(&row[e]);
        float4 v = *(const float4*)(feat + (size_t)s * 128 + lane * 4);
        a[0].x += v.x; a[0].y += v.y; a[0].z += v.z; a[0].w += v.w;
    }
    #pragma unroll
    for (int j = 1; j < 8; j++) {
        a[0].x += a[j].x; a[0].y += a[j].y; a[0].z += a[j].z; a[0].w += a[j].w;
    }
    float s = 1.0f / (float)(deg > 1 ? deg : 1);
    uint32_t h0, l0, h1, l1;
    split2(a[0].x * s, a[0].y * s, h0, l0);
    split2(a[0].z * s, a[0].w * s, h1, l1);
    int plane = lane >> 4;
    int w = (lane & 15) * 8;
    size_t off = (size_t)plane * PLANEB + swzoff(warp, w);
    *(uint2*)(mh + off) = make_uint2(h0, h1);
    *(uint2*)(ml + off) = make_uint2(l0, l1);
}

// D=50 variant: single plane [N][64 cols], zeros for cols 50..63
__global__ void aggregate50_kernel(const float* __restrict__ feat,
                                   const int* __restrict__ csr,
                                   const int* __restrict__ cnt,
                                   unsigned char* __restrict__ mh,
                                   unsigned char* __restrict__ ml, int N) {
    int warp = (blockIdx.x * blockDim.x + threadIdx.x) >> 5;
    int lane = threadIdx.x & 31;
    if (warp >= N) return;
    int deg = cnt[warp];
    float2 r = make_float2(0.f, 0.f);
    if (lane < 25) {
        int n = deg < CAP ? deg : CAP;
        const int* row = csr + (size_t)warp * CAP;
        float2 a[8];
        #pragma unroll
        for (int j = 0; j < 8; j++) a[j] = make_float2(0.f, 0.f);
        int e = 0;
        for (; e + 8 <= n; e += 8) {
            int s[8];
            #pragma unroll
            for (int j = 0; j < 8; j++) s[j] = __ldg(&row[e + j]);
            #pragma unroll
            for (int j = 0; j < 8; j++) {
                float2 v = *(const float2*)(feat + (size_t)s[j] * 50 + lane * 2);
                a[j].x += v.x; a[j].y += v.y;
            }
        }
        for (; e < n; e++) {
            int s = __ldg(&row[e]);
            float2 v = *(const float2*)(feat + (size_t)s * 50 + lane * 2);
            a[0].x += v.x; a[0].y += v.y;
        }
        #pragma unroll
        for (int j = 1; j < 8; j++) { a[0].x += a[j].x; a[0].y += a[j].y; }
        float s = 1.0f / (float)(deg > 1 ? deg : 1);
        r.x = a[0].x * s; r.y = a[0].y * s;
    }
    uint32_t h, l;
    split2(r.x, r.y, h, l);
    size_t off = swzoff(warp, lane * 4);
    *(uint32_t*)(mh + off) = h;
    *(uint32_t*)(ml + off) = l;
}

// ---------------- cp.async-pipelined mma.sync GEMM (KC=64, pre-swizzled) ----------
// smem: Ah0 Al0 Ah1 Al1 (16KB each, double-buffered A) + Bh Bl (16KB, single) + red
#define SM_AH(b) ((b) * 32768)
#define SM_AL(b) ((b) * 32768 + 16384)
#define SM_BH 65536
#define SM_BL 81920
#define SREDO 98304
#define SMBYTES (98304 + 256)

// EPI 0: + bias, store raw to out, accumulate (sum,sumsq) into redOut
// EPI 1: v = prelu(ln(rawbuf)); out2 = v; out = v + acc; split(out)->outsh/outsl
// EPI 2: v = prelu(ln(rawbuf)); out  = v + addend + acc; split(out)->outsh/outsl
template<int CH1, int CH2, int EPI>
__global__ __launch_bounds__(512, 2)
void gemm_mma(const unsigned char* __restrict__ A1h, const unsigned char* __restrict__ A1l,
              const unsigned char* __restrict__ A2h, const unsigned char* __restrict__ A2l,
              const unsigned char* __restrict__ B1h, const unsigned char* __restrict__ B1l,
              const unsigned char* __restrict__ B2h, const unsigned char* __restrict__ B2l,
              const float* __restrict__ bias,
              float* __restrict__ out, float* __restrict__ out2,
              unsigned char* __restrict__ outsh, unsigned char* __restrict__ outsl,
              const float* __restrict__ rawbuf, const float* __restrict__ addend,
              const float* __restrict__ lnw, const float* __restrict__ lnb,
              const float* __restrict__ alpha,
              const double* __restrict__ redIn, double* __restrict__ redOut,
              int N) {
    extern __shared__ __align__(16) unsigned char sm[];
    uint32_t sb = smem_to_u32(sm);
    int tid = threadIdx.x;
    int lane = tid & 31;
    int warp = tid >> 5;
    int wm = warp >> 2;
    int wn = warp & 3;
    int blockRow = blockIdx.x * 128;

    constexpr int CH = CH1 + CH2;
    size_t arowoff = (size_t)blockRow * 128;

    auto prefetch_A = [&](int cc, int buf) {
        const unsigned char *ph, *pl;
        if (cc < CH1) { ph = A1h + (size_t)cc * PLANEB; pl = A1l + (size_t)cc * PLANEB; }
        else          { ph = A2h + (size_t)(cc - CH1) * PLANEB; pl = A2l + (size_t)(cc - CH1) * PLANEB; }
        ph += arowoff; pl += arowoff;
        #pragma unroll
        for (int t = 0; t < 2; t++) {
            int u = (tid + t * 512) * 16;
            cpa16(sb + SM_AH(buf) + u, ph + u);
            cpa16(sb + SM_AL(buf) + u, pl + u);
        }
    };
    auto prefetch_B = [&](int cc) {
        const unsigned char *ph, *pl;
        if (cc < CH1) { ph = B1h + (size_t)cc * 16384; pl = B1l + (size_t)cc * 16384; }
        else          { ph = B2h + (size_t)(cc - CH1) * 16384; pl = B2l + (size_t)(cc - CH1) * 16384; }
        #pragma unroll
        for (int t = 0; t < 2; t++) {
            int u = (tid + t * 512) * 16;
            cpa16(sb + SM_BH + u, ph + u);
            cpa16(sb + SM_BL + u, pl + u);
        }
    };

    float acc[2][4][4];
    #pragma unroll
    for (int i = 0; i < 2; i++)
        #pragma unroll
        for (int j = 0; j < 4; j++)
            #pragma unroll
            for (int r = 0; r < 4; r++) acc[i][j][r] = 0.0f;

    prefetch_A(0, 0);
    prefetch_B(0);
    cp_commit();
    for (int cc = 0; cc < CH; cc++) {
        int buf = cc & 1;
        if (cc + 1 < CH) {
            prefetch_A(cc + 1, buf ^ 1);
            cp_commit();
            cp_wait<1>();
        } else {
            cp_wait<0>();
        }
        __syncthreads();
        uint32_t ahb = sb + SM_AH(buf), alb = sb + SM_AL(buf);
        uint32_t bhb = sb + SM_BH, blb = sb + SM_BL;
        #pragma unroll
        for (int ks = 0; ks < 64; ks += 16) {
            // B fragments hoisted per k-step (loaded once, used by both mi)
            uint32_t bh[4][2], bl[4][2];
            #pragma unroll
            for (int ni = 0; ni < 4; ni++) {
                int nrow = wn * 32 + ni * 8 + (lane & 7);
                int bkoff = (ks + ((lane >> 3) & 1) * 8) * 2;
                uint32_t boff = nrow * 128 + (bkoff ^ ((nrow & 7) << 4));
                ldsm_x2(bh[ni], bhb + boff);
                ldsm_x2(bl[ni], blb + boff);
            }
            #pragma unroll
            for (int mi = 0; mi < 2; mi++) {
                int arow = wm * 32 + mi * 16 + (lane & 15);
                int akoff = (ks + (lane >> 4) * 8) * 2;
                uint32_t aoff = arow * 128 + (akoff ^ ((arow & 7) << 4));
                uint32_t ah[4], al[4];
                ldsm_x4(ah, ahb + aoff);
                ldsm_x4(al, alb + aoff);
                #pragma unroll
                for (int ni = 0; ni < 4; ni++) {
                    mma_bf16(acc[mi][ni], ah, bh[ni]);
                    mma_bf16(acc[mi][ni], ah, bl[ni]);
                    mma_bf16(acc[mi][ni], al, bh[ni]);
                }
            }
        }
        __syncthreads();
        if (cc + 1 < CH) {
            prefetch_B(cc + 1);
            cp_commit();
        }
    }

    // ---- epilogue ----
    float ls = 0.0f, lq = 0.0f;
    float mu = 0.f, scale = 0.f, aslope = 0.f;
    if constexpr (EPI != 0) {
        double M = (double)N * 128.0;
        double mean = redIn[0] / M;
        double var = redIn[1] / M - mean * mean;
        if (var < 0.0) var = 0.0;
        scale = (float)(1.0 / (sqrt(var) + LN_EPS));
        mu = (float)mean;
        aslope = alpha[0];
    }
    #pragma unroll
    for (int mi = 0; mi < 2; mi++) {
        int rbase = blockRow + wm * 32 + mi * 16 + (lane >> 2);
        #pragma unroll
        for (int ni = 0; ni < 4; ni++) {
            int col = wn * 32 + ni * 8 + (lane & 3) * 2;
            #pragma unroll
            for (int half = 0; half < 2; half++) {
                int r = rbase + half * 8;
                if (r >= N) continue;
                float d0 = acc[mi][ni][half * 2];
                float d1 = acc[mi][ni][half * 2 + 1];
                size_t off = (size_t)r * 128 + col;
                if constexpr (EPI == 0) {
                    float o0 = d0 + bias[col];
                    float o1 = d1 + bias[col + 1];
                    *(float2*)&out[off] = make_float2(o0, o1);
                    ls += o0 + o1;
                    lq += o0 * o0 + o1 * o1;
                } else {
                    float2 rv = *(const float2*)&rawbuf[off];
                    float v0 = (rv.x - mu) * scale * lnw[col] + lnb[col];
                    float v1 = (rv.y - mu) * scale * lnw[col + 1] + lnb[col + 1];
                    v0 = v0 >= 0.f ? v0 : aslope * v0;
                    v1 = v1 >= 0.f ? v1 : aslope * v1;
                    float o0, o1;
                    if constexpr (EPI == 1) {
                        *(float2*)&out2[off] = make_float2(v0, v1);
                        o0 = v0 + d0; o1 = v1 + d1;
                    } else {
                        float2 ad = *(const float2*)&addend[off];
                        o0 = v0 + ad.x + d0; o1 = v1 + ad.y + d1;
                    }
                    *(float2*)&out[off] = make_float2(o0, o1);
                    uint32_t h, l;
                    split2(o0, o1, h, l);
                    int plane = col >> 6;
                    size_t soff = (size_t)plane * PLANEB + swzoff(r, (col & 63) * 2);
                    *(uint32_t*)(outsh + soff) = h;
                    *(uint32_t*)(outsl + soff) = l;
                }
            }
        }
    }

    if constexpr (EPI == 0) {
        #pragma unroll
        for (int off = 16; off > 0; off >>= 1) {
            ls += __shfl_down_sync(0xffffffffu, ls, off);
            lq += __shfl_down_sync(0xffffffffu, lq, off);
        }
        float* sRed = (float*)(sm + SREDO);
        if (lane == 0) { sRed[warp * 2] = ls; sRed[warp * 2 + 1] = lq; }
        __syncthreads();
        if (tid == 0) {
            float S = 0.0f, Q = 0.0f;
            #pragma unroll
            for (int w = 0; w < 16; w++) { S += sRed[w * 2]; Q += sRed[w * 2 + 1]; }
            atomicAdd(&redOut[0], (double)S);
            atomicAdd(&redOut[1], (double)Q);
        }
    }
}

// final LN + PReLU on the output buffer
__global__ void ln_prelu_kernel(float* __restrict__ buf, const double* __restrict__ red,
                                const float* __restrict__ lnw, const float* __restrict__ lnb,
                                const float* __restrict__ alpha, int N) {
    long idx = (long)blockIdx.x * blockDim.x + threadIdx.x;
    long total = (long)N * 32;
    if (idx >= total) return;
    double M = (double)N * 128.0;
    double mean = red[0] / M;
    double var = red[1] / M - mean * mean;
    if (var < 0.0) var = 0.0;
    float sc = (float)(1.0 / (sqrt(var) + LN_EPS));
    float mu = (float)mean;
    float a = alpha[0];
    int c4 = ((int)(idx & 31)) * 4;
    float4 v = ((float4*)buf)[idx];
    float w0 = lnw[c4], w1 = lnw[c4 + 1], w2 = lnw[c4 + 2], w3 = lnw[c4 + 3];
    float b0 = lnb[c4], b1 = lnb[c4 + 1], b2 = lnb[c4 + 2], b3 = lnb[c4 + 3];
    float o0 = (v.x - mu) * sc * w0 + b0; o0 = o0 >= 0.f ? o0 : a * o0;
    float o1 = (v.y - mu) * sc * w1 + b1; o1 = o1 >= 0.f ? o1 : a * o1;
    float o2 = (v.z - mu) * sc * w2 + b2; o2 = o2 >= 0.f ? o2 : a * o2;
    float o3 = (v.w - mu) * sc * w3 + b3; o3 = o3 >= 0.f ? o3 : a * o3;
    ((float4*)buf)[idx] = make_float4(o0, o1, o2, o3);
}

// ---------------- launch ----------------
extern "C" void kernel_launch(void* const* d_in, const int* in_sizes, int n_in,
                              void* d_out, int out_size) {
    const float* x    = (const float*)d_in[0];
    const int*   srcp = (const int*)d_in[1];
    const int*   dstp = (const int*)d_in[2];
    const float* Wl1  = (const float*)d_in[3];
    const float* Wr1  = (const float*)d_in[4];
    const float* b1   = (const float*)d_in[5];
    const float* Wl2  = (const float*)d_in[6];
    const float* Wr2  = (const float*)d_in[7];
    const float* b2   = (const float*)d_in[8];
    const float* Wl3  = (const float*)d_in[9];
    const float* Wr3  = (const float*)d_in[10];
    const float* b3   = (const float*)d_in[11];
    const float* Ws1  = (const float*)d_in[12];
    const float* Ws2  = (const float*)d_in[13];
    const float* lnw1 = (const float*)d_in[14];
    const float* lnb1 = (const float*)d_in[15];
    const float* lnw2 = (const float*)d_in[16];
    const float* lnb2 = (const float*)d_in[17];
    const float* lnw3 = (const float*)d_in[18];
    const float* lnb3 = (const float*)d_in[19];
    const float* a1   = (const float*)d_in[20];
    const float* a2   = (const float*)d_in[21];
    const float* a3   = (const float*)d_in[22];

    int E = in_sizes[1];
    int N = in_sizes[0] / 50;

    float *h1, *tmp;
    double* red;
    int *cnt, *csr;
    unsigned char *imgh, *imgl, *xh, *xl, *aggh, *aggl, *tmph, *tmpl;
    cudaGetSymbolAddress((void**)&h1,   g_h1);
    cudaGetSymbolAddress((void**)&tmp,  g_tmp);
    cudaGetSymbolAddress((void**)&red,  g_red);
    cudaGetSymbolAddress((void**)&cnt,  g_cnt);
    cudaGetSymbolAddress((void**)&csr,  g_csr);
    cudaGetSymbolAddress((void**)&imgh, g_wimgh);
    cudaGetSymbolAddress((void**)&imgl, g_wimgl);
    cudaGetSymbolAddress((void**)&xh,   g_xh);
    cudaGetSymbolAddress((void**)&xl,   g_xl);
    cudaGetSymbolAddress((void**)&aggh, g_aggh);
    cudaGetSymbolAddress((void**)&aggl, g_aggl);
    cudaGetSymbolAddress((void**)&tmph, g_tmph);
    cudaGetSymbolAddress((void**)&tmpl, g_tmpl);

    float* out = (float*)d_out;

    int gemmGrid = (N + 127) / 128;
    int aggGrid = (N + 7) / 8;
    int zeroB = (N + 255) / 256;
    int xB = (N * 32 + 255) / 256;
    int setupGrid = zeroB + xB + 512;

    cudaFuncSetAttribute(gemm_mma<1, 1, 0>, cudaFuncAttributeMaxDynamicSharedMemorySize, SMBYTES);
    cudaFuncSetAttribute(gemm_mma<0, 1, 1>, cudaFuncAttributeMaxDynamicSharedMemorySize, SMBYTES);
    cudaFuncSetAttribute(gemm_mma<2, 2, 0>, cudaFuncAttributeMaxDynamicSharedMemorySize, SMBYTES);
    cudaFuncSetAttribute(gemm_mma<0, 1, 2>, cudaFuncAttributeMaxDynamicSharedMemorySize, SMBYTES);

    // launch 0: merged setup (zero + x-split + weight images)
    setup_kernel<<<setupGrid, 256>>>(x, Wl1, Wr1, Ws1, Wl2, Wr2, Ws2, Wl3, Wr3,
                                     cnt, red, xh, xl, imgh, imgl, N);
    // launch 1: CSR fill
    fill_kernel<<<(E + 255) / 256, 256>>>(srcp, dstp, E, cnt, csr);
    // launch 2: layer-1 aggregation
    aggregate50_kernel<<<aggGrid, 256>>>(x, csr, cnt, aggh, aggl, N);
    // launch 3 (ncu target): layer-1 GEMM  h1raw = mean@Wl1 + x@Wr1 + b1
    gemm_mma<1, 1, 0><<<gemmGrid, 512, SMBYTES>>>(
        aggh, aggl, xh, xl,
        imgh + 0 * 32768, imgl + 0 * 32768, imgh + 1 * 32768, imgl + 1 * 32768,
        b1, h1,
        nullptr, nullptr, nullptr, nullptr, nullptr, nullptr, nullptr, nullptr, nullptr,
        red + 0, N);
    // launch 4: h1 := prelu(ln(h1raw)); tmp := h1n + x@Ws1 (+ split planes)
    gemm_mma<0, 1, 1><<<gemmGrid, 512, SMBYTES>>>(
        nullptr, nullptr, xh, xl,
        nullptr, nullptr, imgh + 2 * 32768, imgl + 2 * 32768,
        nullptr, tmp, h1, tmph, tmpl, h1, nullptr,
        lnw1, lnb1, a1, red + 0, nullptr, N);
    // layer 2
    aggregate128_kernel<<<aggGrid, 256>>>(tmp, csr, cnt, aggh, aggl, N);
    gemm_mma<2, 2, 0><<<gemmGrid, 512, SMBYTES>>>(
        aggh, aggl, tmph, tmpl,
        imgh + 3 * 32768, imgl + 3 * 32768, imgh + 4 * 32768, imgl + 4 * 32768,
        b2, tmp,
        nullptr, nullptr, nullptr, nullptr, nullptr, nullptr, nullptr, nullptr, nullptr,
        red + 2, N);
    gemm_mma<0, 1, 2><<<gemmGrid, 512, SMBYTES>>>(
        nullptr, nullptr, xh, xl,
        nullptr, nullptr, imgh + 5 * 32768, imgl + 5 * 32768,
        nullptr, tmp, nullptr, tmph, tmpl, tmp, h1,
        lnw2, lnb2, a2, red + 2, nullptr, N);
    // layer 3
    aggregate128_kernel<<<aggGrid, 256>>>(tmp, csr, cnt, aggh, aggl, N);
    gemm_mma<2, 2, 0><<<gemmGrid, 512, SMBYTES>>>(
        aggh, aggl, tmph, tmpl,
        imgh + 6 * 32768, imgl + 6 * 32768, imgh + 7 * 32768, imgl + 7 * 32768,
        b3, out,
        nullptr, nullptr, nullptr, nullptr, nullptr, nullptr, nullptr, nullptr, nullptr,
        red + 4, N);
    ln_prelu_kernel<<<(int)(((long)N * 32 + 255) / 256), 256>>>(out, red + 4,
                                                                lnw3, lnb3, a3, N);
}

// round 16
// speedup vs baseline: 2.1804x; 1.0050x over previous
#include <cuda_runtime.h>
#include <cuda_bf16.h>
#include <math.h>
#include <stdint.h>

#define MAXN 100000
#define NPAD 100128            // MAXN rounded up past a 128-row tile
#define PLANEB (NPAD * 128)    // bytes per 64-col (128B-row) plane
#define CAP  128
#define LN_EPS 1e-5

typedef unsigned long long u64;

// ---------------- scratch (static device globals; no allocation) ----------------
__device__ float  g_h1 [(size_t)MAXN * 128];
__device__ float  g_tmp[(size_t)MAXN * 128];
__device__ int    g_cnt[MAXN];
__device__ double g_red[8];
__device__ int    g_csr[(size_t)MAXN * CAP];
// pre-swizzled bf16 images (chunk-major planes of 128B rows)
__device__ __align__(16) unsigned char g_wimgh[8 * 32768];
__device__ __align__(16) unsigned char g_wimgl[8 * 32768];
__device__ __align__(16) unsigned char g_xh[PLANEB];
__device__ __align__(16) unsigned char g_xl[PLANEB];
__device__ __align__(16) unsigned char g_aggh[2 * (size_t)PLANEB];
__device__ __align__(16) unsigned char g_aggl[2 * (size_t)PLANEB];
__device__ __align__(16) unsigned char g_tmph[2 * (size_t)PLANEB];
__device__ __align__(16) unsigned char g_tmpl[2 * (size_t)PLANEB];

// swizzled byte offset within a plane: row r, byte-in-row w (16B-unit XOR)
__device__ __forceinline__ size_t swzoff(int r, int w) {
    return (size_t)r * 128 + (w ^ ((r & 7) << 4));
}

// ---------------- mma/ldmatrix/cp.async helpers (sm_80+ ISA) ----------------
__device__ __forceinline__ uint32_t smem_to_u32(const void* p) {
    uint32_t a;
    asm("{ .reg .u64 t; cvta.to.shared.u64 t, %1; cvt.u32.u64 %0, t; }" : "=r"(a) : "l"(p));
    return a;
}
__device__ __forceinline__ void ldsm_x4(uint32_t (&r)[4], uint32_t addr) {
    asm volatile("ldmatrix.sync.aligned.m8n8.x4.shared.b16 {%0,%1,%2,%3}, [%4];"
                 : "=r"(r[0]), "=r"(r[1]), "=r"(r[2]), "=r"(r[3]) : "r"(addr));
}
__device__ __forceinline__ void ldsm_x2(uint32_t (&r)[2], uint32_t addr) {
    asm volatile("ldmatrix.sync.aligned.m8n8.x2.shared.b16 {%0,%1}, [%2];"
                 : "=r"(r[0]), "=r"(r[1]) : "r"(addr));
}
__device__ __forceinline__ void mma_bf16(float (&c)[4], const uint32_t (&a)[4],
                                         const uint32_t (&b)[2]) {
    asm volatile(
        "mma.sync.aligned.m16n8k16.row.col.f32.bf16.bf16.f32 "
        "{%0,%1,%2,%3}, {%4,%5,%6,%7}, {%8,%9}, {%0,%1,%2,%3};"
        : "+f"(c[0]), "+f"(c[1]), "+f"(c[2]), "+f"(c[3])
        : "r"(a[0]), "r"(a[1]), "r"(a[2]), "r"(a[3]), "r"(b[0]), "r"(b[1]));
}
__device__ __forceinline__ void cpa16(uint32_t dst, const void* src) {
    asm volatile("cp.async.cg.shared.global [%0], [%1], 16;"
                 :: "r"(dst), "l"(src));
}
__device__ __forceinline__ void cp_commit() {
    asm volatile("cp.async.commit_group;" ::: "memory");
}
template<int NW>
__device__ __forceinline__ void cp_wait() {
    asm volatile("cp.async.wait_group %0;" :: "n"(NW) : "memory");
}
// split two fp32 into packed bf16 hi-pair and lo-pair (low 16 bits = first elem)
__device__ __forceinline__ void split2(float v0, float v1, uint32_t& h, uint32_t& l) {
    __nv_bfloat16 h0 = __float2bfloat16(v0);
    __nv_bfloat16 h1 = __float2bfloat16(v1);
    __nv_bfloat16 l0 = __float2bfloat16(v0 - __bfloat162float(h0));
    __nv_bfloat16 l1 = __float2bfloat16(v1 - __bfloat162float(h1));
    h = (uint32_t)__bfloat16_as_ushort(h0) | ((uint32_t)__bfloat16_as_ushort(h1) << 16);
    l = (uint32_t)__bfloat16_as_ushort(l0) | ((uint32_t)__bfloat16_as_ushort(l1) << 16);
}

// ---------------- merged setup kernel ----------------
__global__ void setup_kernel(const float* __restrict__ x,
                             const float* Wl1, const float* Wr1, const float* Ws1,
                             const float* Wl2, const float* Wr2, const float* Ws2,
                             const float* Wl3, const float* Wr3,
                             int* __restrict__ cnt, double* __restrict__ red,
                             unsigned char* __restrict__ xh, unsigned char* __restrict__ xl,
                             unsigned char* __restrict__ imgh,
                             unsigned char* __restrict__ imgl, int N) {
    int zeroB = (N + 255) >> 8;
    int xB = (N * 32 + 255) >> 8;
    int bid = blockIdx.x;
    int tid = threadIdx.x;
    if (bid < zeroB) {
        int i = bid * 256 + tid;
        if (i < N) cnt[i] = 0;
        if (i < 8) red[i] = 0.0;
    } else if (bid < zeroB + xB) {
        int t = (bid - zeroB) * 256 + tid;
        int row = t >> 5;
        int c2 = t & 31;
        if (row < N) {
            int col = c2 * 2;
            float v0 = (col < 50) ? x[(size_t)row * 50 + col] : 0.0f;
            float v1 = (col + 1 < 50) ? x[(size_t)row * 50 + col + 1] : 0.0f;
            uint32_t h, l;
            split2(v0, v1, h, l);
            size_t off = swzoff(row, c2 * 4);
            *(uint32_t*)(xh + off) = h;
            *(uint32_t*)(xl + off) = l;
        }
    } else {
        int b2 = bid - zeroB - xB;
        int slot = b2 >> 6;
        int idx = (b2 & 63) * 256 + tid;
        const float* W; int K;
        switch (slot) {
            case 0: W = Wl1; K = 50;  break;
            case 1: W = Wr1; K = 50;  break;
            case 2: W = Ws1; K = 50;  break;
            case 3: W = Wl2; K = 128; break;
            case 4: W = Wr2; K = 128; break;
            case 5: W = Ws2; K = 50;  break;
            case 6: W = Wl3; K = 128; break;
            default: W = Wr3; K = 128; break;
        }
        int n = idx >> 7;          // output col 0..127
        int k = idx & 127;         // k 0..127
        float v = (k < K) ? W[(size_t)k * 128 + n] : 0.0f;
        __nv_bfloat16 hb = __float2bfloat16(v);
        __nv_bfloat16 lb = __float2bfloat16(v - __bfloat162float(hb));
        int c = k >> 6, kk = k & 63;
        size_t off = (size_t)slot * 32768 + (size_t)c * 16384 + swzoff(n, kk * 2);
        *(__nv_bfloat16*)(imgh + off) = hb;
        *(__nv_bfloat16*)(imgl + off) = lb;
    }
}

__global__ void fill_kernel(const int* __restrict__ src, const int* __restrict__ dst,
                            int E, int* __restrict__ cnt, int* __restrict__ csr) {
    int e = blockIdx.x * blockDim.x + threadIdx.x;
    if (e >= E) return;
    int d = dst[e];
    int slot = atomicAdd(&cnt[d], 1);
    if (slot < CAP) csr[(size_t)d * CAP + slot] = src[e];
}

// ---------------- CSR mean-aggregation -> swizzled bf16 hi/lo planes ----------------
// warp = (node, column-half): each warp gathers 256B/edge and owns one output plane
__global__ void aggregate128_kernel(const float* __restrict__ feat,
                                    const int* __restrict__ csr,
                                    const int* __restrict__ cnt,
                                    unsigned char* __restrict__ mh,
                                    unsigned char* __restrict__ ml, int N) {
    int gw = (blockIdx.x * blockDim.x + threadIdx.x) >> 5;
    int lane = threadIdx.x & 31;
    int node = gw >> 1;
    int half = gw & 1;
    if (node >= N) return;
    int deg = cnt[node];
    int n = deg < CAP ? deg : CAP;
    const int* row = csr + (size_t)node * CAP;
    const float* fb = feat + half * 64 + lane * 2;

    float2 a[8];
    #pragma unroll
    for (int j = 0; j < 8; j++) a[j] = make_float2(0.f, 0.f);
    int e = 0;
    for (; e + 8 <= n; e += 8) {
        int s[8];
        #pragma unroll
        for (int j = 0; j < 8; j++) s[j] = __ldg(&row[e + j]);
        #pragma unroll
        for (int j = 0; j < 8; j++) {
            float2 v = *(const float2*)(fb + (size_t)s[j] * 128);
            a[j].x += v.x; a[j].y += v.y;
        }
    }
    for (; e < n; e++) {
        int s = __ldg(&row[e]);
        float2 v = *(const float2*)(fb + (size_t)s * 128);
        a[0].x += v.x; a[0].y += v.y;
    }
    #pragma unroll
    for (int j = 1; j < 8; j++) { a[0].x += a[j].x; a[0].y += a[j].y; }
    float s = 1.0f / (float)(deg > 1 ? deg : 1);
    uint32_t h, l;
    split2(a[0].x * s, a[0].y * s, h, l);
    size_t off = (size_t)half * PLANEB + swzoff(node, lane * 4);
    *(uint32_t*)(mh + off) = h;
    *(uint32_t*)(ml + off) = l;
}

// D=50 variant: single plane [N][64 cols], zeros for cols 50..63
__global__ void aggregate50_kernel(const float* __restrict__ feat,
                                   const int* __restrict__ csr,
                                   const int* __restrict__ cnt,
                                   unsigned char* __restrict__ mh,
                                   unsigned char* __restrict__ ml, int N) {
    int warp = (blockIdx.x * blockDim.x + threadIdx.x) >> 5;
    int lane = threadIdx.x & 31;
    if (warp >= N) return;
    int deg = cnt[warp];
    float2 r = make_float2(0.f, 0.f);
    if (lane < 25) {
        int n = deg < CAP ? deg : CAP;
        const int* row = csr + (size_t)warp * CAP;
        float2 a[8];
        #pragma unroll
        for (int j = 0; j < 8; j++) a[j] = make_float2(0.f, 0.f);
        int e = 0;
        for (; e + 8 <= n; e += 8) {
            int s[8];
            #pragma unroll
            for (int j = 0; j < 8; j++) s[j] = __ldg(&row[e + j]);
            #pragma unroll
            for (int j = 0; j < 8; j++) {
                float2 v = *(const float2*)(feat + (size_t)s[j] * 50 + lane * 2);
                a[j].x += v.x; a[j].y += v.y;
            }
        }
        for (; e < n; e++) {
            int s = __ldg(&row[e]);
            float2 v = *(const float2*)(feat + (size_t)s * 50 + lane * 2);
            a[0].x += v.x; a[0].y += v.y;
        }
        #pragma unroll
        for (int j = 1; j < 8; j++) { a[0].x += a[j].x; a[0].y += a[j].y; }
        float s = 1.0f / (float)(deg > 1 ? deg : 1);
        r.x = a[0].x * s; r.y = a[0].y * s;
    }
    uint32_t h, l;
    split2(r.x, r.y, h, l);
    size_t off = swzoff(warp, lane * 4);
    *(uint32_t*)(mh + off) = h;
    *(uint32_t*)(ml + off) = l;
}

// ---------------- cp.async-pipelined mma.sync GEMM (KC=64, pre-swizzled) ----------
// smem: Ah0 Al0 Ah1 Al1 (16KB each, double-buffered A) + Bh Bl (16KB, single) + red
#define SM_AH(b) ((b) * 32768)
#define SM_AL(b) ((b) * 32768 + 16384)
#define SM_BH 65536
#define SM_BL 81920
#define SREDO 98304
#define SMBYTES (98304 + 256)

// EPI 0: + bias, store raw to out, accumulate (sum,sumsq) into redOut
// EPI 1: v = prelu(ln(rawbuf)); out2 = v; out = v + acc; split(out)->outsh/outsl
// EPI 2: v = prelu(ln(rawbuf)); out  = v + addend + acc; split(out)->outsh/outsl
template<int CH1, int CH2, int EPI>
__global__ __launch_bounds__(512, 2)
void gemm_mma(const unsigned char* __restrict__ A1h, const unsigned char* __restrict__ A1l,
              const unsigned char* __restrict__ A2h, const unsigned char* __restrict__ A2l,
              const unsigned char* __restrict__ B1h, const unsigned char* __restrict__ B1l,
              const unsigned char* __restrict__ B2h, const unsigned char* __restrict__ B2l,
              const float* __restrict__ bias,
              float* __restrict__ out, float* __restrict__ out2,
              unsigned char* __restrict__ outsh, unsigned char* __restrict__ outsl,
              const float* __restrict__ rawbuf, const float* __restrict__ addend,
              const float* __restrict__ lnw, const float* __restrict__ lnb,
              const float* __restrict__ alpha,
              const double* __restrict__ redIn, double* __restrict__ redOut,
              int N) {
    extern __shared__ __align__(16) unsigned char sm[];
    uint32_t sb = smem_to_u32(sm);
    int tid = threadIdx.x;
    int lane = tid & 31;
    int warp = tid >> 5;
    int wm = warp >> 2;
    int wn = warp & 3;
    int blockRow = blockIdx.x * 128;

    constexpr int CH = CH1 + CH2;
    size_t arowoff = (size_t)blockRow * 128;

    auto prefetch_A = [&](int cc, int buf) {
        const unsigned char *ph, *pl;
        if (cc < CH1) { ph = A1h + (size_t)cc * PLANEB; pl = A1l + (size_t)cc * PLANEB; }
        else          { ph = A2h + (size_t)(cc - CH1) * PLANEB; pl = A2l + (size_t)(cc - CH1) * PLANEB; }
        ph += arowoff; pl += arowoff;
        #pragma unroll
        for (int t = 0; t < 2; t++) {
            int u = (tid + t * 512) * 16;
            cpa16(sb + SM_AH(buf) + u, ph + u);
            cpa16(sb + SM_AL(buf) + u, pl + u);
        }
    };
    auto prefetch_B = [&](int cc) {
        const unsigned char *ph, *pl;
        if (cc < CH1) { ph = B1h + (size_t)cc * 16384; pl = B1l + (size_t)cc * 16384; }
        else          { ph = B2h + (size_t)(cc - CH1) * 16384; pl = B2l + (size_t)(cc - CH1) * 16384; }
        #pragma unroll
        for (int t = 0; t < 2; t++) {
            int u = (tid + t * 512) * 16;
            cpa16(sb + SM_BH + u, ph + u);
            cpa16(sb + SM_BL + u, pl + u);
        }
    };

    float acc[2][4][4];
    #pragma unroll
    for (int i = 0; i < 2; i++)
        #pragma unroll
        for (int j = 0; j < 4; j++)
            #pragma unroll
            for (int r = 0; r < 4; r++) acc[i][j][r] = 0.0f;

    prefetch_A(0, 0);
    prefetch_B(0);
    cp_commit();
    for (int cc = 0; cc < CH; cc++) {
        int buf = cc & 1;
        if (cc + 1 < CH) {
            prefetch_A(cc + 1, buf ^ 1);
            cp_commit();
            cp_wait<1>();
        } else {
            cp_wait<0>();
        }
        __syncthreads();
        uint32_t ahb = sb + SM_AH(buf), alb = sb + SM_AL(buf);
        uint32_t bhb = sb + SM_BH, blb = sb + SM_BL;
        #pragma unroll
        for (int ks = 0; ks < 64; ks += 16) {
            uint32_t bh[4][2], bl[4][2];
            #pragma unroll
            for (int ni = 0; ni < 4; ni++) {
                int nrow = wn * 32 + ni * 8 + (lane & 7);
                int bkoff = (ks + ((lane >> 3) & 1) * 8) * 2;
                uint32_t boff = nrow * 128 + (bkoff ^ ((nrow & 7) << 4));
                ldsm_x2(bh[ni], bhb + boff);
                ldsm_x2(bl[ni], blb + boff);
            }
            #pragma unroll
            for (int mi = 0; mi < 2; mi++) {
                int arow = wm * 32 + mi * 16 + (lane & 15);
                int akoff = (ks + (lane >> 4) * 8) * 2;
                uint32_t aoff = arow * 128 + (akoff ^ ((arow & 7) << 4));
                uint32_t ah[4], al[4];
                ldsm_x4(ah, ahb + aoff);
                ldsm_x4(al, alb + aoff);
                #pragma unroll
                for (int ni = 0; ni < 4; ni++) {
                    mma_bf16(acc[mi][ni], ah, bh[ni]);
                    mma_bf16(acc[mi][ni], ah, bl[ni]);
                    mma_bf16(acc[mi][ni], al, bh[ni]);
                }
            }
        }
        __syncthreads();
        if (cc + 1 < CH) {
            prefetch_B(cc + 1);
            cp_commit();
        }
    }

    // ---- epilogue ----
    float ls = 0.0f, lq = 0.0f;
    float mu = 0.f, scale = 0.f, aslope = 0.f;
    if constexpr (EPI != 0) {
        double M = (double)N * 128.0;
        double mean = redIn[0] / M;
        double var = redIn[1] / M - mean * mean;
        if (var < 0.0) var = 0.0;
        scale = (float)(1.0 / (sqrt(var) + LN_EPS));
        mu = (float)mean;
        aslope = alpha[0];
    }
    #pragma unroll
    for (int mi = 0; mi < 2; mi++) {
        int rbase = blockRow + wm * 32 + mi * 16 + (lane >> 2);
        #pragma unroll
        for (int ni = 0; ni < 4; ni++) {
            int col = wn * 32 + ni * 8 + (lane & 3) * 2;
            #pragma unroll
            for (int half = 0; half < 2; half++) {
                int r = rbase + half * 8;
                if (r >= N) continue;
                float d0 = acc[mi][ni][half * 2];
                float d1 = acc[mi][ni][half * 2 + 1];
                size_t off = (size_t)r * 128 + col;
                if constexpr (EPI == 0) {
                    float o0 = d0 + bias[col];
                    float o1 = d1 + bias[col + 1];
                    *(float2*)&out[off] = make_float2(o0, o1);
                    ls += o0 + o1;
                    lq += o0 * o0 + o1 * o1;
                } else {
                    float2 rv = *(const float2*)&rawbuf[off];
                    float v0 = (rv.x - mu) * scale * lnw[col] + lnb[col];
                    float v1 = (rv.y - mu) * scale * lnw[col + 1] + lnb[col + 1];
                    v0 = v0 >= 0.f ? v0 : aslope * v0;
                    v1 = v1 >= 0.f ? v1 : aslope * v1;
                    float o0, o1;
                    if constexpr (EPI == 1) {
                        *(float2*)&out2[off] = make_float2(v0, v1);
                        o0 = v0 + d0; o1 = v1 + d1;
                    } else {
                        float2 ad = *(const float2*)&addend[off];
                        o0 = v0 + ad.x + d0; o1 = v1 + ad.y + d1;
                    }
                    *(float2*)&out[off] = make_float2(o0, o1);
                    uint32_t h, l;
                    split2(o0, o1, h, l);
                    int plane = col >> 6;
                    size_t soff = (size_t)plane * PLANEB + swzoff(r, (col & 63) * 2);
                    *(uint32_t*)(outsh + soff) = h;
                    *(uint32_t*)(outsl + soff) = l;
                }
            }
        }
    }

    if constexpr (EPI == 0) {
        #pragma unroll
        for (int off = 16; off > 0; off >>= 1) {
            ls += __shfl_down_sync(0xffffffffu, ls, off);
            lq += __shfl_down_sync(0xffffffffu, lq, off);
        }
        float* sRed = (float*)(sm + SREDO);
        if (lane == 0) { sRed[warp * 2] = ls; sRed[warp * 2 + 1] = lq; }
        __syncthreads();
        if (tid == 0) {
            float S = 0.0f, Q = 0.0f;
            #pragma unroll
            for (int w = 0; w < 16; w++) { S += sRed[w * 2]; Q += sRed[w * 2 + 1]; }
            atomicAdd(&redOut[0], (double)S);
            atomicAdd(&redOut[1], (double)Q);
        }
    }
}

// final LN + PReLU on the output buffer
__global__ void ln_prelu_kernel(float* __restrict__ buf, const double* __restrict__ red,
                                const float* __restrict__ lnw, const float* __restrict__ lnb,
                                const float* __restrict__ alpha, int N) {
    long idx = (long)blockIdx.x * blockDim.x + threadIdx.x;
    long total = (long)N * 32;
    if (idx >= total) return;
    double M = (double)N * 128.0;
    double mean = red[0] / M;
    double var = red[1] / M - mean * mean;
    if (var < 0.0) var = 0.0;
    float sc = (float)(1.0 / (sqrt(var) + LN_EPS));
    float mu = (float)mean;
    float a = alpha[0];
    int c4 = ((int)(idx & 31)) * 4;
    float4 v = ((float4*)buf)[idx];
    float w0 = lnw[c4], w1 = lnw[c4 + 1], w2 = lnw[c4 + 2], w3 = lnw[c4 + 3];
    float b0 = lnb[c4], b1 = lnb[c4 + 1], b2 = lnb[c4 + 2], b3 = lnb[c4 + 3];
    float o0 = (v.x - mu) * sc * w0 + b0; o0 = o0 >= 0.f ? o0 : a * o0;
    float o1 = (v.y - mu) * sc * w1 + b1; o1 = o1 >= 0.f ? o1 : a * o1;
    float o2 = (v.z - mu) * sc * w2 + b2; o2 = o2 >= 0.f ? o2 : a * o2;
    float o3 = (v.w - mu) * sc * w3 + b3; o3 = o3 >= 0.f ? o3 : a * o3;
    ((float4*)buf)[idx] = make_float4(o0, o1, o2, o3);
}

// ---------------- launch ----------------
extern "C" void kernel_launch(void* const* d_in, const int* in_sizes, int n_in,
                              void* d_out, int out_size) {
    const float* x    = (const float*)d_in[0];
    const int*   srcp = (const int*)d_in[1];
    const int*   dstp = (const int*)d_in[2];
    const float* Wl1  = (const float*)d_in[3];
    const float* Wr1  = (const float*)d_in[4];
    const float* b1   = (const float*)d_in[5];
    const float* Wl2  = (const float*)d_in[6];
    const float* Wr2  = (const float*)d_in[7];
    const float* b2   = (const float*)d_in[8];
    const float* Wl3  = (const float*)d_in[9];
    const float* Wr3  = (const float*)d_in[10];
    const float* b3   = (const float*)d_in[11];
    const float* Ws1  = (const float*)d_in[12];
    const float* Ws2  = (const float*)d_in[13];
    const float* lnw1 = (const float*)d_in[14];
    const float* lnb1 = (const float*)d_in[15];
    const float* lnw2 = (const float*)d_in[16];
    const float* lnb2 = (const float*)d_in[17];
    const float* lnw3 = (const float*)d_in[18];
    const float* lnb3 = (const float*)d_in[19];
    const float* a1   = (const float*)d_in[20];
    const float* a2   = (const float*)d_in[21];
    const float* a3   = (const float*)d_in[22];

    int E = in_sizes[1];
    int N = in_sizes[0] / 50;

    float *h1, *tmp;
    double* red;
    int *cnt, *csr;
    unsigned char *imgh, *imgl, *xh, *xl, *aggh, *aggl, *tmph, *tmpl;
    cudaGetSymbolAddress((void**)&h1,   g_h1);
    cudaGetSymbolAddress((void**)&tmp,  g_tmp);
    cudaGetSymbolAddress((void**)&red,  g_red);
    cudaGetSymbolAddress((void**)&cnt,  g_cnt);
    cudaGetSymbolAddress((void**)&csr,  g_csr);
    cudaGetSymbolAddress((void**)&imgh, g_wimgh);
    cudaGetSymbolAddress((void**)&imgl, g_wimgl);
    cudaGetSymbolAddress((void**)&xh,   g_xh);
    cudaGetSymbolAddress((void**)&xl,   g_xl);
    cudaGetSymbolAddress((void**)&aggh, g_aggh);
    cudaGetSymbolAddress((void**)&aggl, g_aggl);
    cudaGetSymbolAddress((void**)&tmph, g_tmph);
    cudaGetSymbolAddress((void**)&tmpl, g_tmpl);

    float* out = (float*)d_out;

    int gemmGrid = (N + 127) / 128;
    int aggGrid = (N + 7) / 8;
    int agg2Grid = (2 * N + 7) / 8;       // two warps per node
    int zeroB = (N + 255) / 256;
    int xB = (N * 32 + 255) / 256;
    int setupGrid = zeroB + xB + 512;

    cudaFuncSetAttribute(gemm_mma<1, 1, 0>, cudaFuncAttributeMaxDynamicSharedMemorySize, SMBYTES);
    cudaFuncSetAttribute(gemm_mma<0, 1, 1>, cudaFuncAttributeMaxDynamicSharedMemorySize, SMBYTES);
    cudaFuncSetAttribute(gemm_mma<2, 2, 0>, cudaFuncAttributeMaxDynamicSharedMemorySize, SMBYTES);
    cudaFuncSetAttribute(gemm_mma<0, 1, 2>, cudaFuncAttributeMaxDynamicSharedMemorySize, SMBYTES);

    // launch 0: merged setup (zero + x-split + weight images)
    setup_kernel<<<setupGrid, 256>>>(x, Wl1, Wr1, Ws1, Wl2, Wr2, Ws2, Wl3, Wr3,
                                     cnt, red, xh, xl, imgh, imgl, N);
    // launch 1: CSR fill
    fill_kernel<<<(E + 255) / 256, 256>>>(srcp, dstp, E, cnt, csr);
    // launch 2: layer-1 aggregation
    aggregate50_kernel<<<aggGrid, 256>>>(x, csr, cnt, aggh, aggl, N);
    // launch 3 (ncu target): layer-1 GEMM  h1raw = mean@Wl1 + x@Wr1 + b1
    gemm_mma<1, 1, 0><<<gemmGrid, 512, SMBYTES>>>(
        aggh, aggl, xh, xl,
        imgh + 0 * 32768, imgl + 0 * 32768, imgh + 1 * 32768, imgl + 1 * 32768,
        b1, h1,
        nullptr, nullptr, nullptr, nullptr, nullptr, nullptr, nullptr, nullptr, nullptr,
        red + 0, N);
    // launch 4: h1 := prelu(ln(h1raw)); tmp := h1n + x@Ws1 (+ split planes)
    gemm_mma<0, 1, 1><<<gemmGrid, 512, SMBYTES>>>(
        nullptr, nullptr, xh, xl,
        nullptr, nullptr, imgh + 2 * 32768, imgl + 2 * 32768,
        nullptr, tmp, h1, tmph, tmpl, h1, nullptr,
        lnw1, lnb1, a1, red + 0, nullptr, N);
    // layer 2
    aggregate128_kernel<<<agg2Grid, 256>>>(tmp, csr, cnt, aggh, aggl, N);
    gemm_mma<2, 2, 0><<<gemmGrid, 512, SMBYTES>>>(
        aggh, aggl, tmph, tmpl,
        imgh + 3 * 32768, imgl + 3 * 32768, imgh + 4 * 32768, imgl + 4 * 32768,
        b2, tmp,
        nullptr, nullptr, nullptr, nullptr, nullptr, nullptr, nullptr, nullptr, nullptr,
        red + 2, N);
    gemm_mma<0, 1, 2><<<gemmGrid, 512, SMBYTES>>>(
        nullptr, nullptr, xh, xl,
        nullptr, nullptr, imgh + 5 * 32768, imgl + 5 * 32768,
        nullptr, tmp, nullptr, tmph, tmpl, tmp, h1,
        lnw2, lnb2, a2, red + 2, nullptr, N);
    // layer 3
    aggregate128_kernel<<<agg2Grid, 256>>>(tmp, csr, cnt, aggh, aggl, N);
    gemm_mma<2, 2, 0><<<gemmGrid, 512, SMBYTES>>>(
        aggh, aggl, tmph, tmpl,
        imgh + 6 * 32768, imgl + 6 * 32768, imgh + 7 * 32768, imgl + 7 * 32768,
        b3, out,
        nullptr, nullptr, nullptr, nullptr, nullptr, nullptr, nullptr, nullptr, nullptr,
        red + 4, N);
    ln_prelu_kernel<<<(int)(((long)N * 32 + 255) / 256), 256>>>(out, red + 4,
                                                                lnw3, lnb3, a3, N);
}